// round 3
// baseline (speedup 1.0000x reference)
#include <cuda_runtime.h>
#include <math.h>
#include <stdint.h>

#define BB   4
#define NN   2048
#define KCC  2048
#define DD   1024
#define HH   16
#define HD   64
#define SCALE_F 0.125f
#define EPS_F   1e-6f

// ---------------- scratch ----------------
__device__ float g_ctxn[BB * KCC * DD];
__device__ float g_q   [BB * NN  * DD];
__device__ float g_k   [BB * KCC * DD];
__device__ float g_v   [BB * KCC * DD];
__device__ float g_ao  [BB * NN  * DD];

// ---------------- tf32 helpers ----------------
__device__ __forceinline__ uint32_t f2tf(float f) {
    uint32_t u;
    asm("cvt.rna.tf32.f32 %0, %1;" : "=r"(u) : "f"(f));
    return u;
}
__device__ __forceinline__ void mma8(float* c, const uint32_t* a, const uint32_t* b) {
    asm volatile(
        "mma.sync.aligned.m16n8k8.row.col.f32.tf32.tf32.f32 "
        "{%0,%1,%2,%3}, {%4,%5,%6,%7}, {%8,%9}, {%0,%1,%2,%3};"
        : "+f"(c[0]), "+f"(c[1]), "+f"(c[2]), "+f"(c[3])
        : "r"(a[0]), "r"(a[1]), "r"(a[2]), "r"(a[3]), "r"(b[0]), "r"(b[1]));
}

// exp(clip(s,-10,10) - 10) on FMA/ALU pipes (no MUFU).
__device__ __forceinline__ float fexp10(float s) {
    float sc = fminf(fmaxf(s, -10.0f), 10.0f);
    float y = fmaf(sc, 1.4426950409f, -14.4269504089f);   // [-28.86, 0]
    float magic = y + 12582912.0f;                        // 1.5*2^23
    int n = __float_as_int(magic) - 0x4B400000;           // n = round(y)
    float f = y - (magic - 12582912.0f);                  // f in [-0.5,0.5]
    float p = 1.8775767e-3f;
    p = fmaf(p, f, 8.9893397e-3f);
    p = fmaf(p, f, 5.5804010e-2f);
    p = fmaf(p, f, 2.4022650e-1f);
    p = fmaf(p, f, 6.9314718e-1f);
    p = fmaf(p, f, 1.0f);                                 // 2^f
    return __int_as_float(__float_as_int(p) + (n << 23)); // * 2^n
}

// ---------------- rms norm ----------------
__global__ void rmsnorm_k(const float* __restrict__ ctx, float* __restrict__ o) {
    int row = blockIdx.x;
    const float4* p = reinterpret_cast<const float4*>(ctx + (size_t)row * DD);
    float4 v = p[threadIdx.x];
    float ss = v.x * v.x + v.y * v.y + v.z * v.z + v.w * v.w;
    __shared__ float red[8];
    #pragma unroll
    for (int off = 16; off; off >>= 1) ss += __shfl_xor_sync(0xffffffffu, ss, off);
    if ((threadIdx.x & 31) == 0) red[threadIdx.x >> 5] = ss;
    __syncthreads();
    if (threadIdx.x < 32) {
        float t = (threadIdx.x < 8) ? red[threadIdx.x] : 0.0f;
        #pragma unroll
        for (int off = 4; off; off >>= 1) t += __shfl_xor_sync(0xffffffffu, t, off);
        if (threadIdx.x == 0) red[0] = t;
    }
    __syncthreads();
    float r = 1.0f / sqrtf(red[0] * (1.0f / DD) + EPS_F);
    float4* q = reinterpret_cast<float4*>(o + (size_t)row * DD);
    float4 w; w.x = v.x * r; w.y = v.y * r; w.z = v.z * r; w.w = v.w * r;
    q[threadIdx.x] = w;
}

// ---------------- tf32 tensor-core GEMM ----------------
#define GAP 36
#define GBP 264
#define GASZ (128 * GAP)
#define GBSZ (32 * GBP)
#define GEMM_SMEM ((2 * GASZ + 2 * GBSZ) * 4)

template <int MODE>
__global__ void __launch_bounds__(256)
gemm_tc(const float* __restrict__ A, const float* __restrict__ W,
        const float* __restrict__ bias, float* __restrict__ C,
        int M2, int N2, int K2,
        float* __restrict__ outK, float* __restrict__ outV) {
    extern __shared__ uint32_t smu[];
    uint32_t* As = smu;
    uint32_t* Bs = smu + 2 * GASZ;

    int tid = threadIdx.x;
    int lane = tid & 31;
    int wid = tid >> 5;
    int gid = lane >> 2, tig = lane & 3;
    int warpm = wid & 1, warpn = wid >> 1;
    int rowBase = blockIdx.y * 128, colBase = blockIdx.x * 256;

    int am = tid >> 3, ak = (tid & 7) << 2;
    int bn = (tid & 63) << 2, bk = tid >> 6;

    const float* Ap = A + (size_t)rowBase * K2;
    const float* Wp = W + colBase + bn;

    float4 ar[4], br[8];
    #pragma unroll
    for (int i = 0; i < 4; ++i)
        ar[i] = *(const float4*)(Ap + (size_t)(am + 32 * i) * K2 + ak);
    #pragma unroll
    for (int i = 0; i < 8; ++i)
        br[i] = *(const float4*)(Wp + (size_t)(bk + 4 * i) * N2);

    #pragma unroll
    for (int i = 0; i < 4; ++i) {
        uint32_t* p = &As[(am + 32 * i) * GAP + ak];
        p[0] = f2tf(ar[i].x); p[1] = f2tf(ar[i].y);
        p[2] = f2tf(ar[i].z); p[3] = f2tf(ar[i].w);
    }
    #pragma unroll
    for (int i = 0; i < 8; ++i) {
        uint32_t* p = &Bs[(bk + 4 * i) * GBP + bn];
        p[0] = f2tf(br[i].x); p[1] = f2tf(br[i].y);
        p[2] = f2tf(br[i].z); p[3] = f2tf(br[i].w);
    }
    __syncthreads();

    float acc[4][8][4];
    #pragma unroll
    for (int mt = 0; mt < 4; ++mt)
        #pragma unroll
        for (int nt = 0; nt < 8; ++nt)
            #pragma unroll
            for (int r = 0; r < 4; ++r) acc[mt][nt][r] = 0.0f;

    int nT = K2 >> 5;
    int cur = 0;
    for (int t = 0; t < nT; ++t) {
        if (t + 1 < nT) {
            const float* Ap2 = Ap + (t + 1) * 32;
            #pragma unroll
            for (int i = 0; i < 4; ++i)
                ar[i] = *(const float4*)(Ap2 + (size_t)(am + 32 * i) * K2 + ak);
            const float* Wp2 = Wp + (size_t)(t + 1) * 32 * N2;
            #pragma unroll
            for (int i = 0; i < 8; ++i)
                br[i] = *(const float4*)(Wp2 + (size_t)(bk + 4 * i) * N2);
        }
        const uint32_t* Ab = &As[cur * GASZ];
        const uint32_t* Bb = &Bs[cur * GBSZ];
        #pragma unroll
        for (int ks = 0; ks < 4; ++ks) {
            int tk = ks << 3;
            uint32_t af[4][4], bf[8][2];
            #pragma unroll
            for (int mt = 0; mt < 4; ++mt) {
                int m0 = warpm * 64 + mt * 16 + gid;
                af[mt][0] = Ab[m0 * GAP + tk + tig];
                af[mt][1] = Ab[(m0 + 8) * GAP + tk + tig];
                af[mt][2] = Ab[m0 * GAP + tk + tig + 4];
                af[mt][3] = Ab[(m0 + 8) * GAP + tk + tig + 4];
            }
            #pragma unroll
            for (int nt = 0; nt < 8; ++nt) {
                int n0 = warpn * 64 + nt * 8 + gid;
                bf[nt][0] = Bb[(tk + tig) * GBP + n0];
                bf[nt][1] = Bb[(tk + tig + 4) * GBP + n0];
            }
            #pragma unroll
            for (int mt = 0; mt < 4; ++mt)
                #pragma unroll
                for (int nt = 0; nt < 8; ++nt)
                    mma8(acc[mt][nt], af[mt], bf[nt]);
        }
        if (t + 1 < nT) {
            int nb = cur ^ 1;
            #pragma unroll
            for (int i = 0; i < 4; ++i) {
                uint32_t* p = &As[nb * GASZ + (am + 32 * i) * GAP + ak];
                p[0] = f2tf(ar[i].x); p[1] = f2tf(ar[i].y);
                p[2] = f2tf(ar[i].z); p[3] = f2tf(ar[i].w);
            }
            #pragma unroll
            for (int i = 0; i < 8; ++i) {
                uint32_t* p = &Bs[nb * GBSZ + (bk + 4 * i) * GBP + bn];
                p[0] = f2tf(br[i].x); p[1] = f2tf(br[i].y);
                p[2] = f2tf(br[i].z); p[3] = f2tf(br[i].w);
            }
        }
        __syncthreads();
        cur ^= 1;
    }

    #pragma unroll
    for (int mt = 0; mt < 4; ++mt) {
        int r0 = rowBase + warpm * 64 + mt * 16 + gid;
        #pragma unroll
        for (int nt = 0; nt < 8; ++nt) {
            int col = colBase + warpn * 64 + nt * 8 + tig * 2;
            float2 bb = *(const float2*)(bias + col);
            float2 v0, v1;
            v0.x = acc[mt][nt][0] + bb.x; v0.y = acc[mt][nt][1] + bb.y;
            v1.x = acc[mt][nt][2] + bb.x; v1.y = acc[mt][nt][3] + bb.y;
            if (MODE == 0) {
                v0.x *= SCALE_F; v0.y *= SCALE_F; v1.x *= SCALE_F; v1.y *= SCALE_F;
                *(float2*)(&C[(size_t)r0 * N2 + col]) = v0;
                *(float2*)(&C[(size_t)(r0 + 8) * N2 + col]) = v1;
            } else if (MODE == 2) {
                *(float2*)(&C[(size_t)r0 * N2 + col]) = v0;
                *(float2*)(&C[(size_t)(r0 + 8) * N2 + col]) = v1;
            } else {
                if (col < DD) {
                    *(float2*)(&outK[(size_t)r0 * DD + col]) = v0;
                    *(float2*)(&outK[(size_t)(r0 + 8) * DD + col]) = v1;
                } else {
                    *(float2*)(&outV[(size_t)r0 * DD + col - DD]) = v0;
                    *(float2*)(&outV[(size_t)(r0 + 8) * DD + col - DD]) = v1;
                }
            }
        }
    }
}

// ---------------- fused attention (tf32 mma, 512 threads, poly exp) -------
#define QSP 72
#define PSP 136
#define ATTN_SMEM ((3 * 128 * QSP + 128 * PSP + 128) * 4)

__global__ void __launch_bounds__(512)
attn_k(const float* __restrict__ q, const float* __restrict__ kk,
       const float* __restrict__ vv, float* __restrict__ o) {
    extern __shared__ uint32_t smu[];
    uint32_t* Qs = smu;
    uint32_t* Ks = smu + 128 * QSP;
    uint32_t* Vs = smu + 2 * 128 * QSP;
    uint32_t* Ps = smu + 3 * 128 * QSP;
    float*    RS = (float*)(smu + 3 * 128 * QSP + 128 * PSP);

    int tid = threadIdx.x;
    int lane = tid & 31;
    int wid = tid >> 5;
    int gid = lane >> 2, tig = lane & 3;
    int warpm = wid & 3;     // q 32-block (both phases)
    int warpn = wid >> 2;    // S: k 32-block; PV: dv 16-block

    int bh = blockIdx.y;
    int b = bh >> 4;
    int h = bh & 15;
    int n0blk = blockIdx.x * 128;

    const float* qbase = q + ((size_t)(b * NN + n0blk)) * DD + h * HD;
    const float* kbase = kk + (size_t)b * KCC * DD + h * HD;
    const float* vbase = vv + (size_t)b * KCC * DD + h * HD;

    #pragma unroll
    for (int i = 0; i < 4; ++i) {
        int idx = tid + 512 * i;
        int row = idx >> 4;
        int d4 = (idx & 15) << 2;
        float4 t = *(const float4*)(qbase + (size_t)row * DD + d4);
        uint32_t* p = &Qs[row * QSP + d4];
        p[0] = f2tf(t.x); p[1] = f2tf(t.y); p[2] = f2tf(t.z); p[3] = f2tf(t.w);
    }
    if (tid < 128) RS[tid] = 0.0f;

    float oAcc[2][2][4];
    #pragma unroll
    for (int mt = 0; mt < 2; ++mt)
        #pragma unroll
        for (int nt = 0; nt < 2; ++nt)
            #pragma unroll
            for (int r = 0; r < 4; ++r) oAcc[mt][nt][r] = 0.0f;
    float rs[4];
    #pragma unroll
    for (int i = 0; i < 4; ++i) rs[i] = 0.0f;

    for (int kc0 = 0; kc0 < KCC; kc0 += 128) {
        __syncthreads();   // all warps done with Ks/Vs/Ps (and Qs stores visible, 1st iter)
        #pragma unroll
        for (int i = 0; i < 4; ++i) {
            int idx = tid + 512 * i;
            int key = idx >> 4;
            int d4 = (idx & 15) << 2;
            float4 kt = *(const float4*)(kbase + (size_t)(kc0 + key) * DD + d4);
            float4 vt = *(const float4*)(vbase + (size_t)(kc0 + key) * DD + d4);
            uint32_t* pk = &Ks[key * QSP + d4];
            pk[0] = f2tf(kt.x); pk[1] = f2tf(kt.y);
            pk[2] = f2tf(kt.z); pk[3] = f2tf(kt.w);
            uint32_t* pv = &Vs[key * QSP + d4];
            pv[0] = f2tf(vt.x); pv[1] = f2tf(vt.y);
            pv[2] = f2tf(vt.z); pv[3] = f2tf(vt.w);
        }
        __syncthreads();

        // ---- S = Q @ K^T : 32q x 32k per warp ----
        float sAcc[2][4][4];
        #pragma unroll
        for (int mt = 0; mt < 2; ++mt)
            #pragma unroll
            for (int nt = 0; nt < 4; ++nt)
                #pragma unroll
                for (int r = 0; r < 4; ++r) sAcc[mt][nt][r] = 0.0f;

        #pragma unroll
        for (int ks = 0; ks < 8; ++ks) {
            int tk = ks << 3;
            uint32_t af[2][4], bf[4][2];
            #pragma unroll
            for (int mt = 0; mt < 2; ++mt) {
                int m0 = warpm * 32 + mt * 16 + gid;
                af[mt][0] = Qs[m0 * QSP + tk + tig];
                af[mt][1] = Qs[(m0 + 8) * QSP + tk + tig];
                af[mt][2] = Qs[m0 * QSP + tk + tig + 4];
                af[mt][3] = Qs[(m0 + 8) * QSP + tk + tig + 4];
            }
            #pragma unroll
            for (int nt = 0; nt < 4; ++nt) {
                int n0 = warpn * 32 + nt * 8 + gid;
                bf[nt][0] = Ks[n0 * QSP + tk + tig];
                bf[nt][1] = Ks[n0 * QSP + tk + tig + 4];
            }
            #pragma unroll
            for (int mt = 0; mt < 2; ++mt)
                #pragma unroll
                for (int nt = 0; nt < 4; ++nt)
                    mma8(sAcc[mt][nt], af[mt], bf[nt]);
        }

        // ---- epilogue: poly exp, rowsum, P -> smem (tf32) ----
        #pragma unroll
        for (int mt = 0; mt < 2; ++mt) {
            int r0 = warpm * 32 + mt * 16 + gid;
            #pragma unroll
            for (int nt = 0; nt < 4; ++nt) {
                int col = warpn * 32 + nt * 8 + tig * 2;
                uint32_t u0 = f2tf(fexp10(sAcc[mt][nt][0]));
                uint32_t u1 = f2tf(fexp10(sAcc[mt][nt][1]));
                uint32_t u2 = f2tf(fexp10(sAcc[mt][nt][2]));
                uint32_t u3 = f2tf(fexp10(sAcc[mt][nt][3]));
                rs[mt * 2 + 0] += __uint_as_float(u0) + __uint_as_float(u1);
                rs[mt * 2 + 1] += __uint_as_float(u2) + __uint_as_float(u3);
                uint2 w0; w0.x = u0; w0.y = u1;
                uint2 w1; w1.x = u2; w1.y = u3;
                *(uint2*)(&Ps[r0 * PSP + col]) = w0;
                *(uint2*)(&Ps[(r0 + 8) * PSP + col]) = w1;
            }
        }
        __syncthreads();

        // ---- O += P @ V : 32q x 16dv per warp ----
        #pragma unroll
        for (int ks = 0; ks < 16; ++ks) {
            int tk = ks << 3;
            uint32_t af[2][4], bf[2][2];
            #pragma unroll
            for (int mt = 0; mt < 2; ++mt) {
                int m0 = warpm * 32 + mt * 16 + gid;
                af[mt][0] = Ps[m0 * PSP + tk + tig];
                af[mt][1] = Ps[(m0 + 8) * PSP + tk + tig];
                af[mt][2] = Ps[m0 * PSP + tk + tig + 4];
                af[mt][3] = Ps[(m0 + 8) * PSP + tk + tig + 4];
            }
            #pragma unroll
            for (int nt = 0; nt < 2; ++nt) {
                int n0 = warpn * 16 + nt * 8 + gid;
                bf[nt][0] = Vs[(tk + tig) * QSP + n0];
                bf[nt][1] = Vs[(tk + tig + 4) * QSP + n0];
            }
            #pragma unroll
            for (int mt = 0; mt < 2; ++mt)
                #pragma unroll
                for (int nt = 0; nt < 2; ++nt)
                    mma8(oAcc[mt][nt], af[mt], bf[nt]);
        }
    }

    // ---- rowsum reduce: quad shuffle + shared atomic over 4 warpn warps ----
    #pragma unroll
    for (int mt = 0; mt < 2; ++mt)
        #pragma unroll
        for (int rr = 0; rr < 2; ++rr) {
            float v = rs[mt * 2 + rr];
            v += __shfl_xor_sync(0xffffffffu, v, 1);
            v += __shfl_xor_sync(0xffffffffu, v, 2);
            if (tig == 0)
                atomicAdd(&RS[warpm * 32 + mt * 16 + rr * 8 + gid], v);
        }
    __syncthreads();

    // ---- normalize + write ----
    #pragma unroll
    for (int mt = 0; mt < 2; ++mt) {
        int r0 = warpm * 32 + mt * 16 + gid;
        float inv0 = 1.0f / RS[r0];
        float inv1 = 1.0f / RS[r0 + 8];
        #pragma unroll
        for (int nt = 0; nt < 2; ++nt) {
            int dv = warpn * 16 + nt * 8 + tig * 2;
            float2 w0, w1;
            w0.x = oAcc[mt][nt][0] * inv0; w0.y = oAcc[mt][nt][1] * inv0;
            w1.x = oAcc[mt][nt][2] * inv1; w1.y = oAcc[mt][nt][3] * inv1;
            *(float2*)(&o[((size_t)(b * NN + n0blk + r0)) * DD + h * HD + dv]) = w0;
            *(float2*)(&o[((size_t)(b * NN + n0blk + r0 + 8)) * DD + h * HD + dv]) = w1;
        }
    }
}

// ---------------- tail ----------------
__global__ void tail_k(float* __restrict__ dst) {
    dst[0] = 1.0f / (float)KCC;
}

// ---------------- launch ----------------
extern "C" void kernel_launch(void* const* d_in, const int* in_sizes, int n_in,
                              void* d_out, int out_size) {
    const float* x      = (const float*)d_in[0];
    const float* ctx    = (const float*)d_in[1];
    const float* q_w    = (const float*)d_in[2];
    const float* q_b    = (const float*)d_in[3];
    const float* kv_w   = (const float*)d_in[4];
    const float* kv_b   = (const float*)d_in[5];
    const float* proj_w = (const float*)d_in[6];
    const float* proj_b = (const float*)d_in[7];
    float* out = (float*)d_out;

    float *ctxn, *qg, *kg, *vg, *ao;
    cudaGetSymbolAddress((void**)&ctxn, g_ctxn);
    cudaGetSymbolAddress((void**)&qg,   g_q);
    cudaGetSymbolAddress((void**)&kg,   g_k);
    cudaGetSymbolAddress((void**)&vg,   g_v);
    cudaGetSymbolAddress((void**)&ao,   g_ao);

    cudaFuncSetAttribute(gemm_tc<0>, cudaFuncAttributeMaxDynamicSharedMemorySize, GEMM_SMEM);
    cudaFuncSetAttribute(gemm_tc<1>, cudaFuncAttributeMaxDynamicSharedMemorySize, GEMM_SMEM);
    cudaFuncSetAttribute(gemm_tc<2>, cudaFuncAttributeMaxDynamicSharedMemorySize, GEMM_SMEM);
    cudaFuncSetAttribute(attn_k,     cudaFuncAttributeMaxDynamicSharedMemorySize, ATTN_SMEM);

    rmsnorm_k<<<BB * KCC, 256>>>(ctx, ctxn);

    dim3 gq(DD / 256, (BB * NN) / 128);
    gemm_tc<0><<<gq, 256, GEMM_SMEM>>>(x, q_w, q_b, qg, BB * NN, DD, DD, nullptr, nullptr);

    dim3 gkv((2 * DD) / 256, (BB * KCC) / 128);
    gemm_tc<1><<<gkv, 256, GEMM_SMEM>>>(ctxn, kv_w, kv_b, nullptr, BB * KCC, 2 * DD, DD, kg, vg);

    dim3 ga(NN / 128, BB * HH);
    attn_k<<<ga, 512, ATTN_SMEM>>>(qg, kg, vg, ao);

    dim3 gp(DD / 256, (BB * NN) / 128);
    gemm_tc<2><<<gp, 256, GEMM_SMEM>>>(ao, proj_w, proj_b, out, BB * NN, DD, DD, nullptr, nullptr);

    if (out_size > BB * NN * DD) {
        tail_k<<<1, 1>>>(out + (size_t)BB * NN * DD);
    }
}

// round 5
// speedup vs baseline: 1.3209x; 1.3209x over previous
#include <cuda_runtime.h>
#include <cuda_fp16.h>
#include <math.h>
#include <stdint.h>

#define BB   4
#define NN   2048
#define KCC  2048
#define DD   1024
#define HH   16
#define HD   64
#define SCALE_F 0.125f
#define EPS_F   1e-6f

// ---------------- scratch ----------------
__device__ float g_ctxn[BB * KCC * DD];
__device__ float g_q   [BB * NN  * DD];
__device__ float g_k   [BB * KCC * DD];
__device__ float g_v   [BB * KCC * DD];
__device__ float g_ao  [BB * NN  * DD];

// ---------------- helpers ----------------
__device__ __forceinline__ uint32_t f2tf(float f) {
    uint32_t u;
    asm("cvt.rna.tf32.f32 %0, %1;" : "=r"(u) : "f"(f));
    return u;
}
__device__ __forceinline__ unsigned short f2h(float f) {
    unsigned short r;
    asm("cvt.rn.f16.f32 %0, %1;" : "=h"(r) : "f"(f));
    return r;
}
__device__ __forceinline__ void mma8(float* c, const uint32_t* a, const uint32_t* b) {
    asm volatile(
        "mma.sync.aligned.m16n8k8.row.col.f32.tf32.tf32.f32 "
        "{%0,%1,%2,%3}, {%4,%5,%6,%7}, {%8,%9}, {%0,%1,%2,%3};"
        : "+f"(c[0]), "+f"(c[1]), "+f"(c[2]), "+f"(c[3])
        : "r"(a[0]), "r"(a[1]), "r"(a[2]), "r"(a[3]), "r"(b[0]), "r"(b[1]));
}
__device__ __forceinline__ void mma16h(float* c, const uint32_t* a, uint32_t b0, uint32_t b1) {
    asm volatile(
        "mma.sync.aligned.m16n8k16.row.col.f32.f16.f16.f32 "
        "{%0,%1,%2,%3}, {%4,%5,%6,%7}, {%8,%9}, {%0,%1,%2,%3};"
        : "+f"(c[0]), "+f"(c[1]), "+f"(c[2]), "+f"(c[3])
        : "r"(a[0]), "r"(a[1]), "r"(a[2]), "r"(a[3]), "r"(b0), "r"(b1));
}
__device__ __forceinline__ uint32_t packh2(float a, float b) {
    uint32_t r;
    asm("cvt.rn.f16x2.f32 %0, %2, %1;" : "=r"(r) : "f"(a), "f"(b));
    return r;
}
// p = exp(clip(s,-10,10) - 10) * 2^15   (FMA/ALU-pipe poly, fp16-normal range)
__device__ __forceinline__ float fexp15(float s) {
    float sc = fminf(fmaxf(s, -10.0f), 10.0f);
    float y = fmaf(sc, 1.4426950409f, 0.5730495911f);     // [-13.85, 15]
    float magic = y + 12582912.0f;
    int n = __float_as_int(magic) - 0x4B400000;
    float f = y - (magic - 12582912.0f);
    float p = 1.8775767e-3f;
    p = fmaf(p, f, 8.9893397e-3f);
    p = fmaf(p, f, 5.5804010e-2f);
    p = fmaf(p, f, 2.4022650e-1f);
    p = fmaf(p, f, 6.9314718e-1f);
    p = fmaf(p, f, 1.0f);
    return __int_as_float(__float_as_int(p) + (n << 23));
}

// ---------------- rms norm ----------------
__global__ void rmsnorm_k(const float* __restrict__ ctx, float* __restrict__ o) {
    int row = blockIdx.x;
    const float4* p = reinterpret_cast<const float4*>(ctx + (size_t)row * DD);
    float4 v = p[threadIdx.x];
    float ss = v.x * v.x + v.y * v.y + v.z * v.z + v.w * v.w;
    __shared__ float red[8];
    #pragma unroll
    for (int off = 16; off; off >>= 1) ss += __shfl_xor_sync(0xffffffffu, ss, off);
    if ((threadIdx.x & 31) == 0) red[threadIdx.x >> 5] = ss;
    __syncthreads();
    if (threadIdx.x < 32) {
        float t = (threadIdx.x < 8) ? red[threadIdx.x] : 0.0f;
        #pragma unroll
        for (int off = 4; off; off >>= 1) t += __shfl_xor_sync(0xffffffffu, t, off);
        if (threadIdx.x == 0) red[0] = t;
    }
    __syncthreads();
    float r = 1.0f / sqrtf(red[0] * (1.0f / DD) + EPS_F);
    float4* q = reinterpret_cast<float4*>(o + (size_t)row * DD);
    float4 w; w.x = v.x * r; w.y = v.y * r; w.z = v.z * r; w.w = v.w * r;
    q[threadIdx.x] = w;
}

// ---------------- tf32 tensor-core GEMM ----------------
#define GAP 36
#define GBP 264
#define GASZ (128 * GAP)
#define GBSZ (32 * GBP)
#define GEMM_SMEM ((2 * GASZ + 2 * GBSZ) * 4)

template <int MODE>
__global__ void __launch_bounds__(256)
gemm_tc(const float* __restrict__ A, const float* __restrict__ W,
        const float* __restrict__ bias, float* __restrict__ C,
        int M2, int N2, int K2,
        float* __restrict__ outK, float* __restrict__ outV) {
    extern __shared__ uint32_t smu[];
    uint32_t* As = smu;
    uint32_t* Bs = smu + 2 * GASZ;

    int tid = threadIdx.x;
    int lane = tid & 31;
    int wid = tid >> 5;
    int gid = lane >> 2, tig = lane & 3;
    int warpm = wid & 1, warpn = wid >> 1;
    int rowBase = blockIdx.y * 128, colBase = blockIdx.x * 256;

    int am = tid >> 3, ak = (tid & 7) << 2;
    int bn = (tid & 63) << 2, bk = tid >> 6;

    const float* Ap = A + (size_t)rowBase * K2;
    const float* Wp = W + colBase + bn;

    float4 ar[4], br[8];
    #pragma unroll
    for (int i = 0; i < 4; ++i)
        ar[i] = *(const float4*)(Ap + (size_t)(am + 32 * i) * K2 + ak);
    #pragma unroll
    for (int i = 0; i < 8; ++i)
        br[i] = *(const float4*)(Wp + (size_t)(bk + 4 * i) * N2);

    #pragma unroll
    for (int i = 0; i < 4; ++i) {
        uint32_t* p = &As[(am + 32 * i) * GAP + ak];
        p[0] = f2tf(ar[i].x); p[1] = f2tf(ar[i].y);
        p[2] = f2tf(ar[i].z); p[3] = f2tf(ar[i].w);
    }
    #pragma unroll
    for (int i = 0; i < 8; ++i) {
        uint32_t* p = &Bs[(bk + 4 * i) * GBP + bn];
        p[0] = f2tf(br[i].x); p[1] = f2tf(br[i].y);
        p[2] = f2tf(br[i].z); p[3] = f2tf(br[i].w);
    }
    __syncthreads();

    float acc[4][8][4];
    #pragma unroll
    for (int mt = 0; mt < 4; ++mt)
        #pragma unroll
        for (int nt = 0; nt < 8; ++nt)
            #pragma unroll
            for (int r = 0; r < 4; ++r) acc[mt][nt][r] = 0.0f;

    int nT = K2 >> 5;
    int cur = 0;
    for (int t = 0; t < nT; ++t) {
        if (t + 1 < nT) {
            const float* Ap2 = Ap + (t + 1) * 32;
            #pragma unroll
            for (int i = 0; i < 4; ++i)
                ar[i] = *(const float4*)(Ap2 + (size_t)(am + 32 * i) * K2 + ak);
            const float* Wp2 = Wp + (size_t)(t + 1) * 32 * N2;
            #pragma unroll
            for (int i = 0; i < 8; ++i)
                br[i] = *(const float4*)(Wp2 + (size_t)(bk + 4 * i) * N2);
        }
        const uint32_t* Ab = &As[cur * GASZ];
        const uint32_t* Bb = &Bs[cur * GBSZ];
        #pragma unroll
        for (int ks = 0; ks < 4; ++ks) {
            int tk = ks << 3;
            uint32_t af[4][4], bf[8][2];
            #pragma unroll
            for (int mt = 0; mt < 4; ++mt) {
                int m0 = warpm * 64 + mt * 16 + gid;
                af[mt][0] = Ab[m0 * GAP + tk + tig];
                af[mt][1] = Ab[(m0 + 8) * GAP + tk + tig];
                af[mt][2] = Ab[m0 * GAP + tk + tig + 4];
                af[mt][3] = Ab[(m0 + 8) * GAP + tk + tig + 4];
            }
            #pragma unroll
            for (int nt = 0; nt < 8; ++nt) {
                int n0 = warpn * 64 + nt * 8 + gid;
                bf[nt][0] = Bb[(tk + tig) * GBP + n0];
                bf[nt][1] = Bb[(tk + tig + 4) * GBP + n0];
            }
            #pragma unroll
            for (int mt = 0; mt < 4; ++mt)
                #pragma unroll
                for (int nt = 0; nt < 8; ++nt)
                    mma8(acc[mt][nt], af[mt], bf[nt]);
        }
        if (t + 1 < nT) {
            int nb = cur ^ 1;
            #pragma unroll
            for (int i = 0; i < 4; ++i) {
                uint32_t* p = &As[nb * GASZ + (am + 32 * i) * GAP + ak];
                p[0] = f2tf(ar[i].x); p[1] = f2tf(ar[i].y);
                p[2] = f2tf(ar[i].z); p[3] = f2tf(ar[i].w);
            }
            #pragma unroll
            for (int i = 0; i < 8; ++i) {
                uint32_t* p = &Bs[nb * GBSZ + (bk + 4 * i) * GBP + bn];
                p[0] = f2tf(br[i].x); p[1] = f2tf(br[i].y);
                p[2] = f2tf(br[i].z); p[3] = f2tf(br[i].w);
            }
        }
        __syncthreads();
        cur ^= 1;
    }

    #pragma unroll
    for (int mt = 0; mt < 4; ++mt) {
        int r0 = rowBase + warpm * 64 + mt * 16 + gid;
        #pragma unroll
        for (int nt = 0; nt < 8; ++nt) {
            int col = colBase + warpn * 64 + nt * 8 + tig * 2;
            float2 bb = *(const float2*)(bias + col);
            float2 v0, v1;
            v0.x = acc[mt][nt][0] + bb.x; v0.y = acc[mt][nt][1] + bb.y;
            v1.x = acc[mt][nt][2] + bb.x; v1.y = acc[mt][nt][3] + bb.y;
            if (MODE == 0) {
                v0.x *= SCALE_F; v0.y *= SCALE_F; v1.x *= SCALE_F; v1.y *= SCALE_F;
                *(float2*)(&C[(size_t)r0 * N2 + col]) = v0;
                *(float2*)(&C[(size_t)(r0 + 8) * N2 + col]) = v1;
            } else if (MODE == 2) {
                *(float2*)(&C[(size_t)r0 * N2 + col]) = v0;
                *(float2*)(&C[(size_t)(r0 + 8) * N2 + col]) = v1;
            } else {
                if (col < DD) {
                    *(float2*)(&outK[(size_t)r0 * DD + col]) = v0;
                    *(float2*)(&outK[(size_t)(r0 + 8) * DD + col]) = v1;
                } else {
                    *(float2*)(&outV[(size_t)r0 * DD + col - DD]) = v0;
                    *(float2*)(&outV[(size_t)(r0 + 8) * DD + col - DD]) = v1;
                }
            }
        }
    }
}

// ---------------- fused attention: register-resident P (FA2 trick) --------
// 256 threads, 8 warps. Warp w owns q rows [16w,16w+16) x ALL chunk keys.
// S tf32 mma -> exp poly -> pack f16x2 in regs -> fp16 m16n8k16 PV mma.
#define QSP 68              // tf32 Q/K pitch (uint32)
#define VTP 136             // fp16 Vt pitch (halves), Vt[dv][key]
#define ATTN_SMEM (2 * 128 * QSP * 4 + HD * VTP * 2)

__global__ void __launch_bounds__(256, 2)
attn_k(const float* __restrict__ q, const float* __restrict__ kk,
       const float* __restrict__ vv, float* __restrict__ o) {
    extern __shared__ uint32_t smu[];
    uint32_t* Qs = smu;                       // [128][QSP]
    uint32_t* Ks = smu + 128 * QSP;           // [128][QSP]
    unsigned short* Vt = (unsigned short*)(smu + 2 * 128 * QSP);  // [64][VTP]
    uint32_t* Vt32 = (uint32_t*)Vt;

    int tid = threadIdx.x;
    int lane = tid & 31;
    int wid = tid >> 5;
    int gid = lane >> 2, tig = lane & 3;

    int bh = blockIdx.y;
    int b = bh >> 4;
    int h = bh & 15;
    int n0blk = blockIdx.x * 128;

    const float* qbase = q + ((size_t)(b * NN + n0blk)) * DD + h * HD;
    const float* kbase = kk + (size_t)b * KCC * DD + h * HD;
    const float* vbase = vv + (size_t)b * KCC * DD + h * HD;

    // load Q once (tf32)
    #pragma unroll
    for (int i = 0; i < 8; ++i) {
        int idx = tid + 256 * i;
        int row = idx >> 4;
        int d4 = (idx & 15) << 2;
        float4 t = *(const float4*)(qbase + (size_t)row * DD + d4);
        uint32_t* p = &Qs[row * QSP + d4];
        p[0] = f2tf(t.x); p[1] = f2tf(t.y); p[2] = f2tf(t.z); p[3] = f2tf(t.w);
    }

    float oAcc[8][4];
    #pragma unroll
    for (int nt = 0; nt < 8; ++nt)
        #pragma unroll
        for (int r = 0; r < 4; ++r) oAcc[nt][r] = 0.0f;
    float rs0 = 0.0f, rs1 = 0.0f;

    int m0 = wid * 16 + gid;

    for (int kc0 = 0; kc0 < KCC; kc0 += 128) {
        __syncthreads();   // prior chunk done with Ks/Vt (and Qs visible on 1st)
        // K: tf32, row-major [key][d]
        #pragma unroll
        for (int i = 0; i < 8; ++i) {
            int idx = tid + 256 * i;
            int key = idx >> 4;
            int d4 = (idx & 15) << 2;
            float4 t = *(const float4*)(kbase + (size_t)(kc0 + key) * DD + d4);
            uint32_t* p = &Ks[key * QSP + d4];
            p[0] = f2tf(t.x); p[1] = f2tf(t.y); p[2] = f2tf(t.z); p[3] = f2tf(t.w);
        }
        // V: fp16 transposed Vt[dv][key] (key-fast lanes: conflict-free STS.16)
        #pragma unroll
        for (int i = 0; i < 8; ++i) {
            int idx = tid + 256 * i;
            int key = idx & 127;
            int dv = (idx >> 7) << 2;
            float4 t = *(const float4*)(vbase + (size_t)(kc0 + key) * DD + dv);
            Vt[(dv + 0) * VTP + key] = f2h(t.x);
            Vt[(dv + 1) * VTP + key] = f2h(t.y);
            Vt[(dv + 2) * VTP + key] = f2h(t.z);
            Vt[(dv + 3) * VTP + key] = f2h(t.w);
        }
        __syncthreads();

        // two 64-key halves to cap register pressure
        #pragma unroll
        for (int half = 0; half < 2; ++half) {
            // ---- S = Q K^T for keys [64*half, 64*half+64) ----
            float sAcc[8][4];
            #pragma unroll
            for (int nt = 0; nt < 8; ++nt)
                #pragma unroll
                for (int r = 0; r < 4; ++r) sAcc[nt][r] = 0.0f;

            #pragma unroll
            for (int ks = 0; ks < 8; ++ks) {
                int tk = ks << 3;
                uint32_t af[4];
                af[0] = Qs[m0 * QSP + tk + tig];
                af[1] = Qs[(m0 + 8) * QSP + tk + tig];
                af[2] = Qs[m0 * QSP + tk + tig + 4];
                af[3] = Qs[(m0 + 8) * QSP + tk + tig + 4];
                #pragma unroll
                for (int nt = 0; nt < 8; ++nt) {
                    int krow = half * 64 + nt * 8 + gid;
                    uint32_t bf[2];
                    bf[0] = Ks[krow * QSP + tk + tig];
                    bf[1] = Ks[krow * QSP + tk + tig + 4];
                    mma8(sAcc[nt], af, bf);
                }
            }

            // ---- exp poly + pack to fp16 A-fragments (P stays in regs) ----
            uint32_t pa[4][4];
            #pragma unroll
            for (int nt = 0; nt < 8; ++nt) {
                float p0 = fexp15(sAcc[nt][0]);
                float p1 = fexp15(sAcc[nt][1]);
                float p2 = fexp15(sAcc[nt][2]);
                float p3 = fexp15(sAcc[nt][3]);
                rs0 += p0 + p1;
                rs1 += p2 + p3;
                int kp = nt >> 1, hi = (nt & 1) << 1;
                pa[kp][hi + 0] = packh2(p0, p1);
                pa[kp][hi + 1] = packh2(p2, p3);
            }

            // ---- O += P V : fp16 m16n8k16, keys 16 per step ----
            #pragma unroll
            for (int kp = 0; kp < 4; ++kp) {
                int k0 = half * 64 + kp * 16;
                #pragma unroll
                for (int nt = 0; nt < 8; ++nt) {
                    int hidx = (nt * 8 + gid) * VTP + k0 + 2 * tig;
                    uint32_t b0 = Vt32[hidx >> 1];
                    uint32_t b1 = Vt32[(hidx + 8) >> 1];
                    mma16h(oAcc[nt], pa[kp], b0, b1);
                }
            }
        }
    }

    // rowsum: quad reduce (cols live in tig dimension)
    rs0 += __shfl_xor_sync(0xffffffffu, rs0, 1);
    rs0 += __shfl_xor_sync(0xffffffffu, rs0, 2);
    rs1 += __shfl_xor_sync(0xffffffffu, rs1, 1);
    rs1 += __shfl_xor_sync(0xffffffffu, rs1, 2);
    float inv0 = 1.0f / rs0;
    float inv1 = 1.0f / rs1;

    int row0 = n0blk + m0;
    #pragma unroll
    for (int nt = 0; nt < 8; ++nt) {
        int dv = nt * 8 + 2 * tig;
        float2 w0, w1;
        w0.x = oAcc[nt][0] * inv0; w0.y = oAcc[nt][1] * inv0;
        w1.x = oAcc[nt][2] * inv1; w1.y = oAcc[nt][3] * inv1;
        *(float2*)(&o[((size_t)(b * NN + row0)) * DD + h * HD + dv]) = w0;
        *(float2*)(&o[((size_t)(b * NN + row0 + 8)) * DD + h * HD + dv]) = w1;
    }
}

// ---------------- tail ----------------
__global__ void tail_k(float* __restrict__ dst) {
    dst[0] = 1.0f / (float)KCC;
}

// ---------------- launch ----------------
extern "C" void kernel_launch(void* const* d_in, const int* in_sizes, int n_in,
                              void* d_out, int out_size) {
    const float* x      = (const float*)d_in[0];
    const float* ctx    = (const float*)d_in[1];
    const float* q_w    = (const float*)d_in[2];
    const float* q_b    = (const float*)d_in[3];
    const float* kv_w   = (const float*)d_in[4];
    const float* kv_b   = (const float*)d_in[5];
    const float* proj_w = (const float*)d_in[6];
    const float* proj_b = (const float*)d_in[7];
    float* out = (float*)d_out;

    float *ctxn, *qg, *kg, *vg, *ao;
    cudaGetSymbolAddress((void**)&ctxn, g_ctxn);
    cudaGetSymbolAddress((void**)&qg,   g_q);
    cudaGetSymbolAddress((void**)&kg,   g_k);
    cudaGetSymbolAddress((void**)&vg,   g_v);
    cudaGetSymbolAddress((void**)&ao,   g_ao);

    cudaFuncSetAttribute(gemm_tc<0>, cudaFuncAttributeMaxDynamicSharedMemorySize, GEMM_SMEM);
    cudaFuncSetAttribute(gemm_tc<1>, cudaFuncAttributeMaxDynamicSharedMemorySize, GEMM_SMEM);
    cudaFuncSetAttribute(gemm_tc<2>, cudaFuncAttributeMaxDynamicSharedMemorySize, GEMM_SMEM);
    cudaFuncSetAttribute(attn_k,     cudaFuncAttributeMaxDynamicSharedMemorySize, ATTN_SMEM);

    rmsnorm_k<<<BB * KCC, 256>>>(ctx, ctxn);

    dim3 gq(DD / 256, (BB * NN) / 128);
    gemm_tc<0><<<gq, 256, GEMM_SMEM>>>(x, q_w, q_b, qg, BB * NN, DD, DD, nullptr, nullptr);

    dim3 gkv((2 * DD) / 256, (BB * KCC) / 128);
    gemm_tc<1><<<gkv, 256, GEMM_SMEM>>>(ctxn, kv_w, kv_b, nullptr, BB * KCC, 2 * DD, DD, kg, vg);

    dim3 ga(NN / 128, BB * HH);
    attn_k<<<ga, 256, ATTN_SMEM>>>(qg, kg, vg, ao);

    dim3 gp(DD / 256, (BB * NN) / 128);
    gemm_tc<2><<<gp, 256, GEMM_SMEM>>>(ao, proj_w, proj_b, out, BB * NN, DD, DD, nullptr, nullptr);

    if (out_size > BB * NN * DD) {
        tail_k<<<1, 1>>>(out + (size_t)BB * NN * DD);
    }
}

// round 7
// speedup vs baseline: 1.8265x; 1.3828x over previous
#include <cuda_runtime.h>
#include <cuda_fp16.h>
#include <math.h>
#include <stdint.h>

#define BB   4
#define NN   2048
#define KCC  2048
#define DD   1024
#define HH   16
#define HD   64
#define SCALE_F 0.125f
#define EPS_F   1e-6f

// ---------------- scratch ----------------
__device__ float g_ctxn[BB * KCC * DD];
__device__ float g_q   [BB * NN  * DD];
__device__ float g_k   [BB * KCC * DD];
__device__ float g_v   [BB * KCC * DD];
__device__ float g_ao  [BB * NN  * DD];

// ---------------- helpers ----------------
__device__ __forceinline__ unsigned short f2h(float f) {
    unsigned short r;
    asm("cvt.rn.f16.f32 %0, %1;" : "=h"(r) : "f"(f));
    return r;
}
__device__ __forceinline__ uint32_t packh2(float a, float b) {
    uint32_t r;
    asm("cvt.rn.f16x2.f32 %0, %2, %1;" : "=r"(r) : "f"(a), "f"(b));
    return r;
}
__device__ __forceinline__ void mma16h(float* c, const uint32_t* a, uint32_t b0, uint32_t b1) {
    asm volatile(
        "mma.sync.aligned.m16n8k16.row.col.f32.f16.f16.f32 "
        "{%0,%1,%2,%3}, {%4,%5,%6,%7}, {%8,%9}, {%0,%1,%2,%3};"
        : "+f"(c[0]), "+f"(c[1]), "+f"(c[2]), "+f"(c[3])
        : "r"(a[0]), "r"(a[1]), "r"(a[2]), "r"(a[3]), "r"(b0), "r"(b1));
}
// p = exp(clip(s,-10,10) - 10) * 2^15   (FMA/ALU-pipe poly, fp16-normal range)
__device__ __forceinline__ float fexp15(float s) {
    float sc = fminf(fmaxf(s, -10.0f), 10.0f);
    float y = fmaf(sc, 1.4426950409f, 0.5730495911f);
    float magic = y + 12582912.0f;
    int n = __float_as_int(magic) - 0x4B400000;
    float f = y - (magic - 12582912.0f);
    float p = 1.8775767e-3f;
    p = fmaf(p, f, 8.9893397e-3f);
    p = fmaf(p, f, 5.5804010e-2f);
    p = fmaf(p, f, 2.4022650e-1f);
    p = fmaf(p, f, 6.9314718e-1f);
    p = fmaf(p, f, 1.0f);
    return __int_as_float(__float_as_int(p) + (n << 23));
}

// ---------------- rms norm ----------------
__global__ void rmsnorm_k(const float* __restrict__ ctx, float* __restrict__ o) {
    int row = blockIdx.x;
    const float4* p = reinterpret_cast<const float4*>(ctx + (size_t)row * DD);
    float4 v = p[threadIdx.x];
    float ss = v.x * v.x + v.y * v.y + v.z * v.z + v.w * v.w;
    __shared__ float red[8];
    #pragma unroll
    for (int off = 16; off; off >>= 1) ss += __shfl_xor_sync(0xffffffffu, ss, off);
    if ((threadIdx.x & 31) == 0) red[threadIdx.x >> 5] = ss;
    __syncthreads();
    if (threadIdx.x < 32) {
        float t = (threadIdx.x < 8) ? red[threadIdx.x] : 0.0f;
        #pragma unroll
        for (int off = 4; off; off >>= 1) t += __shfl_xor_sync(0xffffffffu, t, off);
        if (threadIdx.x == 0) red[0] = t;
    }
    __syncthreads();
    float r = 1.0f / sqrtf(red[0] * (1.0f / DD) + EPS_F);
    float4* q = reinterpret_cast<float4*>(o + (size_t)row * DD);
    float4 w; w.x = v.x * r; w.y = v.y * r; w.z = v.z * r; w.w = v.w * r;
    q[threadIdx.x] = w;
}

// ---------------- fp16 tensor-core GEMM ----------------
// C[M,N2] = A[M,K2] @ W[K2,N2] + bias.  Block 128x256, BK=32, 8 warps @64x64.
// As32: k-pair packed f16x2, [128 rows][20 words] (16 k-pairs + 4 pad)
// Bs32: k-pair packed f16x2, [16 kp][264 words] (256 n + 8 pad)
#define GAPW 20
#define GBPW 264
#define GASZ (128 * GAPW)
#define GBSZ (16 * GBPW)
#define GEMM_SMEM ((2 * GASZ + 2 * GBSZ) * 4)

template <int MODE>
__global__ void __launch_bounds__(256)
gemm_tc(const float* __restrict__ A, const float* __restrict__ W,
        const float* __restrict__ bias, float* __restrict__ C,
        int M2, int N2, int K2,
        float* __restrict__ outK, float* __restrict__ outV) {
    extern __shared__ uint32_t smu[];
    uint32_t* As = smu;
    uint32_t* Bs = smu + 2 * GASZ;

    int tid = threadIdx.x;
    int lane = tid & 31;
    int wid = tid >> 5;
    int gid = lane >> 2, tig = lane & 3;
    int warpm = wid & 1, warpn = wid >> 1;
    int rowBase = blockIdx.y * 128, colBase = blockIdx.x * 256;

    int am = tid >> 3, ak = (tid & 7) << 2;       // A: rows am+32i, floats ak..ak+3
    int bn = (tid & 63) << 2, bkp = tid >> 6;     // B: n-group bn, k-pairs bkp+4i

    const float* Ap = A + (size_t)rowBase * K2;
    const float* Wp = W + colBase + bn;

    float4 ar[4];
    float4 br0[4], br1[4];
    #pragma unroll
    for (int i = 0; i < 4; ++i)
        ar[i] = *(const float4*)(Ap + (size_t)(am + 32 * i) * K2 + ak);
    #pragma unroll
    for (int i = 0; i < 4; ++i) {
        int kp = bkp + 4 * i;
        br0[i] = *(const float4*)(Wp + (size_t)(2 * kp) * N2);
        br1[i] = *(const float4*)(Wp + (size_t)(2 * kp + 1) * N2);
    }

    #pragma unroll
    for (int i = 0; i < 4; ++i) {
        uint32_t* p = &As[(am + 32 * i) * GAPW + (ak >> 1)];
        p[0] = packh2(ar[i].x, ar[i].y);
        p[1] = packh2(ar[i].z, ar[i].w);
    }
    #pragma unroll
    for (int i = 0; i < 4; ++i) {
        int kp = bkp + 4 * i;
        uint32_t* p = &Bs[kp * GBPW + bn];
        p[0] = packh2(br0[i].x, br1[i].x);
        p[1] = packh2(br0[i].y, br1[i].y);
        p[2] = packh2(br0[i].z, br1[i].z);
        p[3] = packh2(br0[i].w, br1[i].w);
    }
    __syncthreads();

    float acc[4][8][4];
    #pragma unroll
    for (int mt = 0; mt < 4; ++mt)
        #pragma unroll
        for (int nt = 0; nt < 8; ++nt)
            #pragma unroll
            for (int r = 0; r < 4; ++r) acc[mt][nt][r] = 0.0f;

    int nT = K2 >> 5;
    int cur = 0;
    for (int t = 0; t < nT; ++t) {
        if (t + 1 < nT) {
            const float* Ap2 = Ap + (t + 1) * 32;
            #pragma unroll
            for (int i = 0; i < 4; ++i)
                ar[i] = *(const float4*)(Ap2 + (size_t)(am + 32 * i) * K2 + ak);
            const float* Wp2 = Wp + (size_t)(t + 1) * 32 * N2;
            #pragma unroll
            for (int i = 0; i < 4; ++i) {
                int kp = bkp + 4 * i;
                br0[i] = *(const float4*)(Wp2 + (size_t)(2 * kp) * N2);
                br1[i] = *(const float4*)(Wp2 + (size_t)(2 * kp + 1) * N2);
            }
        }
        const uint32_t* Ab = &As[cur * GASZ];
        const uint32_t* Bb = &Bs[cur * GBSZ];
        #pragma unroll
        for (int ks = 0; ks < 2; ++ks) {       // two k16 steps per BK=32
            int kw = ks << 3;                  // k-pair word base
            uint32_t af[4][4], bf[8][2];
            #pragma unroll
            for (int mt = 0; mt < 4; ++mt) {
                int m0 = warpm * 64 + mt * 16 + gid;
                af[mt][0] = Ab[m0 * GAPW + kw + tig];
                af[mt][1] = Ab[(m0 + 8) * GAPW + kw + tig];
                af[mt][2] = Ab[m0 * GAPW + kw + tig + 4];
                af[mt][3] = Ab[(m0 + 8) * GAPW + kw + tig + 4];
            }
            #pragma unroll
            for (int nt = 0; nt < 8; ++nt) {
                int n0 = warpn * 64 + nt * 8 + gid;
                bf[nt][0] = Bb[(kw + tig) * GBPW + n0];
                bf[nt][1] = Bb[(kw + tig + 4) * GBPW + n0];
            }
            #pragma unroll
            for (int mt = 0; mt < 4; ++mt)
                #pragma unroll
                for (int nt = 0; nt < 8; ++nt)
                    mma16h(acc[mt][nt], af[mt], bf[nt][0], bf[nt][1]);
        }
        if (t + 1 < nT) {
            int nb = cur ^ 1;
            #pragma unroll
            for (int i = 0; i < 4; ++i) {
                uint32_t* p = &As[nb * GASZ + (am + 32 * i) * GAPW + (ak >> 1)];
                p[0] = packh2(ar[i].x, ar[i].y);
                p[1] = packh2(ar[i].z, ar[i].w);
            }
            #pragma unroll
            for (int i = 0; i < 4; ++i) {
                int kp = bkp + 4 * i;
                uint32_t* p = &Bs[nb * GBSZ + kp * GBPW + bn];
                p[0] = packh2(br0[i].x, br1[i].x);
                p[1] = packh2(br0[i].y, br1[i].y);
                p[2] = packh2(br0[i].z, br1[i].z);
                p[3] = packh2(br0[i].w, br1[i].w);
            }
        }
        __syncthreads();
        cur ^= 1;
    }

    #pragma unroll
    for (int mt = 0; mt < 4; ++mt) {
        int r0 = rowBase + warpm * 64 + mt * 16 + gid;
        #pragma unroll
        for (int nt = 0; nt < 8; ++nt) {
            int col = colBase + warpn * 64 + nt * 8 + tig * 2;
            float2 bb = *(const float2*)(bias + col);
            float2 v0, v1;
            v0.x = acc[mt][nt][0] + bb.x; v0.y = acc[mt][nt][1] + bb.y;
            v1.x = acc[mt][nt][2] + bb.x; v1.y = acc[mt][nt][3] + bb.y;
            if (MODE == 0) {
                v0.x *= SCALE_F; v0.y *= SCALE_F; v1.x *= SCALE_F; v1.y *= SCALE_F;
                *(float2*)(&C[(size_t)r0 * N2 + col]) = v0;
                *(float2*)(&C[(size_t)(r0 + 8) * N2 + col]) = v1;
            } else if (MODE == 2) {
                *(float2*)(&C[(size_t)r0 * N2 + col]) = v0;
                *(float2*)(&C[(size_t)(r0 + 8) * N2 + col]) = v1;
            } else {
                if (col < DD) {
                    *(float2*)(&outK[(size_t)r0 * DD + col]) = v0;
                    *(float2*)(&outK[(size_t)(r0 + 8) * DD + col]) = v1;
                } else {
                    *(float2*)(&outV[(size_t)r0 * DD + col - DD]) = v0;
                    *(float2*)(&outV[(size_t)(r0 + 8) * DD + col - DD]) = v1;
                }
            }
        }
    }
}

// ---------------- fused attention: all-fp16 mma, register-resident P -------
// Qs32/Ks32: k-pair packed f16x2 [128 rows][36 words] (32 kp + 4 pad)
// Vt: fp16 transposed [64 dv][136 halves]
#define QWP 36
#define VTP 136
#define ATTN_SMEM (2 * 128 * QWP * 4 + HD * VTP * 2)

__global__ void __launch_bounds__(256, 2)
attn_k(const float* __restrict__ q, const float* __restrict__ kk,
       const float* __restrict__ vv, float* __restrict__ o) {
    extern __shared__ uint32_t smu[];
    uint32_t* Qs = smu;                        // [128][QWP]
    uint32_t* Ks = smu + 128 * QWP;            // [128][QWP]
    unsigned short* Vt = (unsigned short*)(smu + 2 * 128 * QWP);  // [64][VTP]
    uint32_t* Vt32 = (uint32_t*)Vt;

    int tid = threadIdx.x;
    int lane = tid & 31;
    int wid = tid >> 5;
    int gid = lane >> 2, tig = lane & 3;

    int bh = blockIdx.y;
    int b = bh >> 4;
    int h = bh & 15;
    int n0blk = blockIdx.x * 128;

    const float* qbase = q + ((size_t)(b * NN + n0blk)) * DD + h * HD;
    const float* kbase = kk + (size_t)b * KCC * DD + h * HD;
    const float* vbase = vv + (size_t)b * KCC * DD + h * HD;

    // load Q once (fp16 k-pair packed)
    #pragma unroll
    for (int i = 0; i < 8; ++i) {
        int idx = tid + 256 * i;
        int row = idx >> 4;
        int d4 = (idx & 15) << 2;
        float4 t = *(const float4*)(qbase + (size_t)row * DD + d4);
        uint32_t* p = &Qs[row * QWP + (d4 >> 1)];
        p[0] = packh2(t.x, t.y);
        p[1] = packh2(t.z, t.w);
    }

    float oAcc[8][4];
    #pragma unroll
    for (int nt = 0; nt < 8; ++nt)
        #pragma unroll
        for (int r = 0; r < 4; ++r) oAcc[nt][r] = 0.0f;
    float rs0 = 0.0f, rs1 = 0.0f;

    int m0 = wid * 16 + gid;

    for (int kc0 = 0; kc0 < KCC; kc0 += 128) {
        __syncthreads();
        // K: fp16 k-pair packed [key][kp]
        #pragma unroll
        for (int i = 0; i < 8; ++i) {
            int idx = tid + 256 * i;
            int key = idx >> 4;
            int d4 = (idx & 15) << 2;
            float4 t = *(const float4*)(kbase + (size_t)(kc0 + key) * DD + d4);
            uint32_t* p = &Ks[key * QWP + (d4 >> 1)];
            p[0] = packh2(t.x, t.y);
            p[1] = packh2(t.z, t.w);
        }
        // V: fp16 transposed Vt[dv][key]
        #pragma unroll
        for (int i = 0; i < 8; ++i) {
            int idx = tid + 256 * i;
            int key = idx & 127;
            int dv = (idx >> 7) << 2;
            float4 t = *(const float4*)(vbase + (size_t)(kc0 + key) * DD + dv);
            Vt[(dv + 0) * VTP + key] = f2h(t.x);
            Vt[(dv + 1) * VTP + key] = f2h(t.y);
            Vt[(dv + 2) * VTP + key] = f2h(t.z);
            Vt[(dv + 3) * VTP + key] = f2h(t.w);
        }
        __syncthreads();

        // two 64-key halves to cap register pressure
        #pragma unroll
        for (int half = 0; half < 2; ++half) {
            // ---- S = Q K^T (fp16 m16n8k16, 4 k-steps over d=64) ----
            float sAcc[8][4];
            #pragma unroll
            for (int nt = 0; nt < 8; ++nt)
                #pragma unroll
                for (int r = 0; r < 4; ++r) sAcc[nt][r] = 0.0f;

            #pragma unroll
            for (int ks = 0; ks < 4; ++ks) {
                int kw = ks << 3;
                uint32_t af[4];
                af[0] = Qs[m0 * QWP + kw + tig];
                af[1] = Qs[(m0 + 8) * QWP + kw + tig];
                af[2] = Qs[m0 * QWP + kw + tig + 4];
                af[3] = Qs[(m0 + 8) * QWP + kw + tig + 4];
                #pragma unroll
                for (int nt = 0; nt < 8; ++nt) {
                    int krow = half * 64 + nt * 8 + gid;
                    uint32_t b0 = Ks[krow * QWP + kw + tig];
                    uint32_t b1 = Ks[krow * QWP + kw + tig + 4];
                    mma16h(sAcc[nt], af, b0, b1);
                }
            }

            // ---- exp poly + pack fp16 A-fragments (P stays in regs) ----
            uint32_t pa[4][4];
            #pragma unroll
            for (int nt = 0; nt < 8; ++nt) {
                float p0 = fexp15(sAcc[nt][0]);
                float p1 = fexp15(sAcc[nt][1]);
                float p2 = fexp15(sAcc[nt][2]);
                float p3 = fexp15(sAcc[nt][3]);
                rs0 += p0 + p1;
                rs1 += p2 + p3;
                int kp = nt >> 1, hi = (nt & 1) << 1;
                pa[kp][hi + 0] = packh2(p0, p1);
                pa[kp][hi + 1] = packh2(p2, p3);
            }

            // ---- O += P V : fp16 m16n8k16, 16 keys per step ----
            #pragma unroll
            for (int kp = 0; kp < 4; ++kp) {
                int k0 = half * 64 + kp * 16;
                #pragma unroll
                for (int nt = 0; nt < 8; ++nt) {
                    int hidx = (nt * 8 + gid) * VTP + k0 + 2 * tig;
                    uint32_t b0 = Vt32[hidx >> 1];
                    uint32_t b1 = Vt32[(hidx + 8) >> 1];
                    mma16h(oAcc[nt], pa[kp], b0, b1);
                }
            }
        }
    }

    // rowsum: quad reduce
    rs0 += __shfl_xor_sync(0xffffffffu, rs0, 1);
    rs0 += __shfl_xor_sync(0xffffffffu, rs0, 2);
    rs1 += __shfl_xor_sync(0xffffffffu, rs1, 1);
    rs1 += __shfl_xor_sync(0xffffffffu, rs1, 2);
    float inv0 = 1.0f / rs0;
    float inv1 = 1.0f / rs1;

    int row0 = n0blk + m0;
    #pragma unroll
    for (int nt = 0; nt < 8; ++nt) {
        int dv = nt * 8 + 2 * tig;
        float2 w0, w1;
        w0.x = oAcc[nt][0] * inv0; w0.y = oAcc[nt][1] * inv0;
        w1.x = oAcc[nt][2] * inv1; w1.y = oAcc[nt][3] * inv1;
        *(float2*)(&o[((size_t)(b * NN + row0)) * DD + h * HD + dv]) = w0;
        *(float2*)(&o[((size_t)(b * NN + row0 + 8)) * DD + h * HD + dv]) = w1;
    }
}

// ---------------- tail ----------------
__global__ void tail_k(float* __restrict__ dst) {
    dst[0] = 1.0f / (float)KCC;
}

// ---------------- launch ----------------
extern "C" void kernel_launch(void* const* d_in, const int* in_sizes, int n_in,
                              void* d_out, int out_size) {
    const float* x      = (const float*)d_in[0];
    const float* ctx    = (const float*)d_in[1];
    const float* q_w    = (const float*)d_in[2];
    const float* q_b    = (const float*)d_in[3];
    const float* kv_w   = (const float*)d_in[4];
    const float* kv_b   = (const float*)d_in[5];
    const float* proj_w = (const float*)d_in[6];
    const float* proj_b = (const float*)d_in[7];
    float* out = (float*)d_out;

    float *ctxn, *qg, *kg, *vg, *ao;
    cudaGetSymbolAddress((void**)&ctxn, g_ctxn);
    cudaGetSymbolAddress((void**)&qg,   g_q);
    cudaGetSymbolAddress((void**)&kg,   g_k);
    cudaGetSymbolAddress((void**)&vg,   g_v);
    cudaGetSymbolAddress((void**)&ao,   g_ao);

    cudaFuncSetAttribute(gemm_tc<0>, cudaFuncAttributeMaxDynamicSharedMemorySize, GEMM_SMEM);
    cudaFuncSetAttribute(gemm_tc<1>, cudaFuncAttributeMaxDynamicSharedMemorySize, GEMM_SMEM);
    cudaFuncSetAttribute(gemm_tc<2>, cudaFuncAttributeMaxDynamicSharedMemorySize, GEMM_SMEM);
    cudaFuncSetAttribute(attn_k,     cudaFuncAttributeMaxDynamicSharedMemorySize, ATTN_SMEM);

    rmsnorm_k<<<BB * KCC, 256>>>(ctx, ctxn);

    dim3 gq(DD / 256, (BB * NN) / 128);
    gemm_tc<0><<<gq, 256, GEMM_SMEM>>>(x, q_w, q_b, qg, BB * NN, DD, DD, nullptr, nullptr);

    dim3 gkv((2 * DD) / 256, (BB * KCC) / 128);
    gemm_tc<1><<<gkv, 256, GEMM_SMEM>>>(ctxn, kv_w, kv_b, nullptr, BB * KCC, 2 * DD, DD, kg, vg);

    dim3 ga(NN / 128, BB * HH);
    attn_k<<<ga, 256, ATTN_SMEM>>>(qg, kg, vg, ao);

    dim3 gp(DD / 256, (BB * NN) / 128);
    gemm_tc<2><<<gp, 256, GEMM_SMEM>>>(ao, proj_w, proj_b, out, BB * NN, DD, DD, nullptr, nullptr);

    if (out_size > BB * NN * DD) {
        tail_k<<<1, 1>>>(out + (size_t)BB * NN * DD);
    }
}

// round 10
// speedup vs baseline: 2.3386x; 1.2803x over previous
#include <cuda_runtime.h>
#include <cuda_fp16.h>
#include <math.h>
#include <stdint.h>

#define BB   4
#define NN   2048
#define KCC  2048
#define DD   1024
#define HH   16
#define HD   64
#define SCALE_F 0.125f
#define EPS_F   1e-6f

// ---------------- scratch ----------------
__device__ float  g_ctxn[BB * KCC * DD];
__device__ __half g_qh [BB * NN  * DD];
__device__ __half g_kh [BB * KCC * DD];
__device__ __half g_vh [BB * KCC * DD];
__device__ float  g_ao [BB * NN  * DD];

// ---------------- helpers ----------------
__device__ __forceinline__ uint32_t packh2(float a, float b) {
    uint32_t r;
    asm("cvt.rn.f16x2.f32 %0, %2, %1;" : "=r"(r) : "f"(a), "f"(b));
    return r;
}
__device__ __forceinline__ void mma16h(float* c, const uint32_t* a, uint32_t b0, uint32_t b1) {
    asm volatile(
        "mma.sync.aligned.m16n8k16.row.col.f32.f16.f16.f32 "
        "{%0,%1,%2,%3}, {%4,%5,%6,%7}, {%8,%9}, {%0,%1,%2,%3};"
        : "+f"(c[0]), "+f"(c[1]), "+f"(c[2]), "+f"(c[3])
        : "r"(a[0]), "r"(a[1]), "r"(a[2]), "r"(a[3]), "r"(b0), "r"(b1));
}
__device__ __forceinline__ uint32_t smem_u32(const void* p) {
    return (uint32_t)__cvta_generic_to_shared(p);
}
#define LDSM4(r0,r1,r2,r3,addr) \
    asm volatile("ldmatrix.sync.aligned.m8n8.x4.shared.b16 {%0,%1,%2,%3},[%4];" \
        : "=r"(r0),"=r"(r1),"=r"(r2),"=r"(r3) : "r"(addr))
#define LDSM4T(r0,r1,r2,r3,addr) \
    asm volatile("ldmatrix.sync.aligned.m8n8.x4.trans.shared.b16 {%0,%1,%2,%3},[%4];" \
        : "=r"(r0),"=r"(r1),"=r"(r2),"=r"(r3) : "r"(addr))
#define LDSM2T(r0,r1,addr) \
    asm volatile("ldmatrix.sync.aligned.m8n8.x2.trans.shared.b16 {%0,%1},[%2];" \
        : "=r"(r0),"=r"(r1) : "r"(addr))
#define CPA16(dst,src) \
    asm volatile("cp.async.cg.shared.global [%0],[%1],16;" :: "r"(dst),"l"(src))
#define CPCOMMIT() asm volatile("cp.async.commit_group;")
#define CPWAIT(n)  asm volatile("cp.async.wait_group %0;" :: "n"(n))

__device__ __forceinline__ uint32_t h2max(uint32_t a, uint32_t b) {
    uint32_t r; asm("max.f16x2 %0,%1,%2;" : "=r"(r) : "r"(a), "r"(b)); return r;
}
__device__ __forceinline__ uint32_t h2min(uint32_t a, uint32_t b) {
    uint32_t r; asm("min.f16x2 %0,%1,%2;" : "=r"(r) : "r"(a), "r"(b)); return r;
}
__device__ __forceinline__ uint32_t h2fma(uint32_t a, uint32_t b, uint32_t c) {
    uint32_t r; asm("fma.rn.f16x2 %0,%1,%2,%3;" : "=r"(r) : "r"(a), "r"(b), "r"(c)); return r;
}
__device__ __forceinline__ uint32_t h2ex2(uint32_t a) {
    uint32_t r; asm("ex2.approx.f16x2 %0,%1;" : "=r"(r) : "r"(a)); return r;
}

// ---------------- rms norm ----------------
__global__ void rmsnorm_k(const float* __restrict__ ctx, float* __restrict__ o) {
    int row = blockIdx.x;
    const float4* p = reinterpret_cast<const float4*>(ctx + (size_t)row * DD);
    float4 v = p[threadIdx.x];
    float ss = v.x * v.x + v.y * v.y + v.z * v.z + v.w * v.w;
    __shared__ float red[8];
    #pragma unroll
    for (int off = 16; off; off >>= 1) ss += __shfl_xor_sync(0xffffffffu, ss, off);
    if ((threadIdx.x & 31) == 0) red[threadIdx.x >> 5] = ss;
    __syncthreads();
    if (threadIdx.x < 32) {
        float t = (threadIdx.x < 8) ? red[threadIdx.x] : 0.0f;
        #pragma unroll
        for (int off = 4; off; off >>= 1) t += __shfl_xor_sync(0xffffffffu, t, off);
        if (threadIdx.x == 0) red[0] = t;
    }
    __syncthreads();
    float r = 1.0f / sqrtf(red[0] * (1.0f / DD) + EPS_F);
    float4* q = reinterpret_cast<float4*>(o + (size_t)row * DD);
    float4 w; w.x = v.x * r; w.y = v.y * r; w.z = v.z * r; w.w = v.w * r;
    q[threadIdx.x] = w;
}

// ---------------- fp16 tensor-core GEMM ----------------
// MODE 0: scale + write half C   (q projection -> g_qh)
// MODE 1: split cols -> half K/V (kv projection -> g_kh/g_vh)
// MODE 2: plain float write      (output projection)
#define GAPW 20
#define GBPW 264
#define GASZ (128 * GAPW)
#define GBSZ (16 * GBPW)
#define GEMM_SMEM ((2 * GASZ + 2 * GBSZ) * 4)

template <int MODE>
__global__ void __launch_bounds__(256)
gemm_tc(const float* __restrict__ A, const float* __restrict__ W,
        const float* __restrict__ bias, float* __restrict__ C,
        int M2, int N2, int K2,
        __half* __restrict__ hC, __half* __restrict__ hK, __half* __restrict__ hV) {
    extern __shared__ uint32_t smu[];
    uint32_t* As = smu;
    uint32_t* Bs = smu + 2 * GASZ;

    int tid = threadIdx.x;
    int lane = tid & 31;
    int wid = tid >> 5;
    int gid = lane >> 2, tig = lane & 3;
    int warpm = wid & 1, warpn = wid >> 1;
    int rowBase = blockIdx.y * 128, colBase = blockIdx.x * 256;

    int am = tid >> 3, ak = (tid & 7) << 2;
    int bn = (tid & 63) << 2, bkp = tid >> 6;

    const float* Ap = A + (size_t)rowBase * K2;
    const float* Wp = W + colBase + bn;

    float4 ar[4];
    float4 br0[4], br1[4];
    #pragma unroll
    for (int i = 0; i < 4; ++i)
        ar[i] = *(const float4*)(Ap + (size_t)(am + 32 * i) * K2 + ak);
    #pragma unroll
    for (int i = 0; i < 4; ++i) {
        int kp = bkp + 4 * i;
        br0[i] = *(const float4*)(Wp + (size_t)(2 * kp) * N2);
        br1[i] = *(const float4*)(Wp + (size_t)(2 * kp + 1) * N2);
    }

    #pragma unroll
    for (int i = 0; i < 4; ++i) {
        uint32_t* p = &As[(am + 32 * i) * GAPW + (ak >> 1)];
        p[0] = packh2(ar[i].x, ar[i].y);
        p[1] = packh2(ar[i].z, ar[i].w);
    }
    #pragma unroll
    for (int i = 0; i < 4; ++i) {
        int kp = bkp + 4 * i;
        uint32_t* p = &Bs[kp * GBPW + bn];
        p[0] = packh2(br0[i].x, br1[i].x);
        p[1] = packh2(br0[i].y, br1[i].y);
        p[2] = packh2(br0[i].z, br1[i].z);
        p[3] = packh2(br0[i].w, br1[i].w);
    }
    __syncthreads();

    float acc[4][8][4];
    #pragma unroll
    for (int mt = 0; mt < 4; ++mt)
        #pragma unroll
        for (int nt = 0; nt < 8; ++nt)
            #pragma unroll
            for (int r = 0; r < 4; ++r) acc[mt][nt][r] = 0.0f;

    int nT = K2 >> 5;
    int cur = 0;
    for (int t = 0; t < nT; ++t) {
        if (t + 1 < nT) {
            const float* Ap2 = Ap + (t + 1) * 32;
            #pragma unroll
            for (int i = 0; i < 4; ++i)
                ar[i] = *(const float4*)(Ap2 + (size_t)(am + 32 * i) * K2 + ak);
            const float* Wp2 = Wp + (size_t)(t + 1) * 32 * N2;
            #pragma unroll
            for (int i = 0; i < 4; ++i) {
                int kp = bkp + 4 * i;
                br0[i] = *(const float4*)(Wp2 + (size_t)(2 * kp) * N2);
                br1[i] = *(const float4*)(Wp2 + (size_t)(2 * kp + 1) * N2);
            }
        }
        const uint32_t* Ab = &As[cur * GASZ];
        const uint32_t* Bb = &Bs[cur * GBSZ];
        #pragma unroll
        for (int ks = 0; ks < 2; ++ks) {
            int kw = ks << 3;
            uint32_t af[4][4], bf[8][2];
            #pragma unroll
            for (int mt = 0; mt < 4; ++mt) {
                int m0 = warpm * 64 + mt * 16 + gid;
                af[mt][0] = Ab[m0 * GAPW + kw + tig];
                af[mt][1] = Ab[(m0 + 8) * GAPW + kw + tig];
                af[mt][2] = Ab[m0 * GAPW + kw + tig + 4];
                af[mt][3] = Ab[(m0 + 8) * GAPW + kw + tig + 4];
            }
            #pragma unroll
            for (int nt = 0; nt < 8; ++nt) {
                int n0 = warpn * 64 + nt * 8 + gid;
                bf[nt][0] = Bb[(kw + tig) * GBPW + n0];
                bf[nt][1] = Bb[(kw + tig + 4) * GBPW + n0];
            }
            #pragma unroll
            for (int mt = 0; mt < 4; ++mt)
                #pragma unroll
                for (int nt = 0; nt < 8; ++nt)
                    mma16h(acc[mt][nt], af[mt], bf[nt][0], bf[nt][1]);
        }
        if (t + 1 < nT) {
            int nb = cur ^ 1;
            #pragma unroll
            for (int i = 0; i < 4; ++i) {
                uint32_t* p = &As[nb * GASZ + (am + 32 * i) * GAPW + (ak >> 1)];
                p[0] = packh2(ar[i].x, ar[i].y);
                p[1] = packh2(ar[i].z, ar[i].w);
            }
            #pragma unroll
            for (int i = 0; i < 4; ++i) {
                int kp = bkp + 4 * i;
                uint32_t* p = &Bs[nb * GBSZ + kp * GBPW + bn];
                p[0] = packh2(br0[i].x, br1[i].x);
                p[1] = packh2(br0[i].y, br1[i].y);
                p[2] = packh2(br0[i].z, br1[i].z);
                p[3] = packh2(br0[i].w, br1[i].w);
            }
        }
        __syncthreads();
        cur ^= 1;
    }

    #pragma unroll
    for (int mt = 0; mt < 4; ++mt) {
        int r0 = rowBase + warpm * 64 + mt * 16 + gid;
        #pragma unroll
        for (int nt = 0; nt < 8; ++nt) {
            int col = colBase + warpn * 64 + nt * 8 + tig * 2;
            float2 bb = *(const float2*)(bias + col);
            float2 v0, v1;
            v0.x = acc[mt][nt][0] + bb.x; v0.y = acc[mt][nt][1] + bb.y;
            v1.x = acc[mt][nt][2] + bb.x; v1.y = acc[mt][nt][3] + bb.y;
            if (MODE == 0) {
                uint32_t w0 = packh2(v0.x * SCALE_F, v0.y * SCALE_F);
                uint32_t w1 = packh2(v1.x * SCALE_F, v1.y * SCALE_F);
                ((uint32_t*)hC)[((size_t)r0 * N2 + col) >> 1] = w0;
                ((uint32_t*)hC)[((size_t)(r0 + 8) * N2 + col) >> 1] = w1;
            } else if (MODE == 2) {
                *(float2*)(&C[(size_t)r0 * N2 + col]) = v0;
                *(float2*)(&C[(size_t)(r0 + 8) * N2 + col]) = v1;
            } else {
                uint32_t w0 = packh2(v0.x, v0.y);
                uint32_t w1 = packh2(v1.x, v1.y);
                if (col < DD) {
                    ((uint32_t*)hK)[((size_t)r0 * DD + col) >> 1] = w0;
                    ((uint32_t*)hK)[((size_t)(r0 + 8) * DD + col) >> 1] = w1;
                } else {
                    ((uint32_t*)hV)[((size_t)r0 * DD + col - DD) >> 1] = w0;
                    ((uint32_t*)hV)[((size_t)(r0 + 8) * DD + col - DD) >> 1] = w1;
                }
            }
        }
    }
}

// ---------------- fused attention: fp16 cp.async + ldmatrix + MUFU exp ----
// rows: 72 halves (144B) pitch.  Layout: Qs | Kbuf x2 | Vbuf x2
#define ROWB   144
#define BUFB   (128 * ROWB)      // 18432 bytes per tile buffer
#define ATTN_SMEM (5 * BUFB)     // Q + 2K + 2V = 92160

__global__ void __launch_bounds__(256, 2)
attn_k(const __half* __restrict__ qh, const __half* __restrict__ kh,
       const __half* __restrict__ vh, float* __restrict__ o) {
    extern __shared__ __align__(16) unsigned char smraw[];
    uint32_t s_q = smem_u32(smraw);
    uint32_t s_k = s_q + BUFB;
    uint32_t s_v = s_q + 3 * BUFB;

    int tid = threadIdx.x;
    int lane = tid & 31;
    int wid = tid >> 5;
    int gid = lane >> 2, tig = lane & 3;

    int bh = blockIdx.y;
    int b = bh >> 4;
    int h = bh & 15;
    int n0blk = blockIdx.x * 128;

    const __half* qbase = qh + ((size_t)(b * NN + n0blk)) * DD + h * HD;
    const __half* kbase = kh + (size_t)b * KCC * DD + h * HD;
    const __half* vbase = vh + (size_t)b * KCC * DD + h * HD;

    // ---- Q -> smem (one time) ----
    #pragma unroll
    for (int i = 0; i < 4; ++i) {
        int idx = tid + 256 * i;
        int row = idx >> 3;
        int c = idx & 7;
        uint4 t = *(const uint4*)(qbase + (size_t)row * DD + c * 8);
        *(uint4*)(smraw + row * ROWB + c * 16) = t;
    }
    // ---- V pad columns: dv=64 -> 1.0, dv 65..71 -> 0 (both buffers) ----
    #pragma unroll
    for (int i = 0; i < 4; ++i) {
        int idx = tid + 256 * i;
        int br = idx >> 2;        // 0..255 over both V buffers
        int w  = idx & 3;
        *(uint32_t*)(smraw + 3 * BUFB + br * ROWB + 128 + w * 4) =
            (w == 0) ? 0x00003C00u : 0u;
    }

    // ---- per-lane ldmatrix offsets ----
    int m0 = wid * 16;
    uint32_t qa = s_q + (uint32_t)((m0 + ((lane >> 3) & 1) * 8 + (lane & 7)) * ROWB
                                   + (lane >> 4) * 16);
    uint32_t ka_off = (uint32_t)(((lane & 7) + (lane >> 4) * 8) * ROWB
                                 + ((lane >> 3) & 1) * 16);
    uint32_t va_off = (uint32_t)((((lane >> 3) & 1) * 8 + (lane & 7)) * ROWB
                                 + (lane >> 4) * 16);
    uint32_t vs_off = (uint32_t)((lane & 15) * ROWB + 128);

    // ---- cp.async chunk loader: 4x16B K + 4x16B V per thread ----
    int crow = tid >> 1;
    int cg   = tid & 1;
    const __half* ksrc0 = kbase + (size_t)crow * DD + cg * 32;
    const __half* vsrc0 = vbase + (size_t)crow * DD + cg * 32;
    uint32_t kdst0 = s_k + crow * ROWB + cg * 64;
    uint32_t vdst0 = s_v + crow * ROWB + cg * 64;

    // prologue: chunk 0 -> buffer 0
    {
        const __half* ks = ksrc0;
        const __half* vs = vsrc0;
        #pragma unroll
        for (int j = 0; j < 4; ++j) {
            CPA16(kdst0 + j * 16, ks + j * 8);
            CPA16(vdst0 + j * 16, vs + j * 8);
        }
        CPCOMMIT();
    }

    float oAcc[8][4];
    #pragma unroll
    for (int nt = 0; nt < 8; ++nt)
        #pragma unroll
        for (int r = 0; r < 4; ++r) oAcc[nt][r] = 0.0f;
    float oSum[4] = {0.0f, 0.0f, 0.0f, 0.0f};

    const uint32_t NEG10 = 0xC900C900u, POS10 = 0x49004900u;
    const uint32_t L2E2 = packh2(1.4426950f, 1.4426950f);
    const uint32_t OFF2 = packh2(0.5730496f, 0.5730496f);

    for (int c = 0; c < KCC / 128; ++c) {
        if (c + 1 < KCC / 128) {
            int nb = (c + 1) & 1;
            const __half* ks = ksrc0 + (size_t)(c + 1) * 128 * DD;
            const __half* vs = vsrc0 + (size_t)(c + 1) * 128 * DD;
            #pragma unroll
            for (int j = 0; j < 4; ++j) {
                CPA16(kdst0 + nb * BUFB + j * 16, ks + j * 8);
                CPA16(vdst0 + nb * BUFB + j * 16, vs + j * 8);
            }
            CPCOMMIT();
            CPWAIT(1);
        } else {
            CPWAIT(0);
        }
        __syncthreads();

        uint32_t bo = (c & 1) * BUFB;

        #pragma unroll
        for (int half = 0; half < 2; ++half) {
            // ---- S = Q K^T over 64 keys ----
            float sAcc[8][4];
            #pragma unroll
            for (int nt = 0; nt < 8; ++nt)
                #pragma unroll
                for (int r = 0; r < 4; ++r) sAcc[nt][r] = 0.0f;

            #pragma unroll
            for (int ks = 0; ks < 4; ++ks) {
                uint32_t a0, a1, a2, a3;
                LDSM4(a0, a1, a2, a3, qa + ks * 32);
                uint32_t af[4] = {a0, a1, a2, a3};
                #pragma unroll
                for (int ntp = 0; ntp < 4; ++ntp) {
                    uint32_t b0, b1, b2, b3;
                    LDSM4(b0, b1, b2, b3,
                          s_k + bo + ka_off + (half * 64 + ntp * 16) * ROWB + ks * 32);
                    mma16h(sAcc[2 * ntp], af, b0, b1);
                    mma16h(sAcc[2 * ntp + 1], af, b2, b3);
                }
            }

            // ---- P = exp(clip(s)-10)*2^15 packed fp16 (MUFU ex2) ----
            uint32_t pa[4][4];
            #pragma unroll
            for (int nt = 0; nt < 8; ++nt) {
                uint32_t lo = packh2(sAcc[nt][0], sAcc[nt][1]);
                uint32_t hi = packh2(sAcc[nt][2], sAcc[nt][3]);
                lo = h2ex2(h2fma(h2min(h2max(lo, NEG10), POS10), L2E2, OFF2));
                hi = h2ex2(h2fma(h2min(h2max(hi, NEG10), POS10), L2E2, OFF2));
                int kp = nt >> 1, s = (nt & 1) << 1;
                pa[kp][s + 0] = lo;
                pa[kp][s + 1] = hi;
            }

            // ---- O += P V ; rowsum via ones column ----
            #pragma unroll
            for (int kp = 0; kp < 4; ++kp) {
                uint32_t vrow = s_v + bo + (half * 64 + kp * 16) * ROWB;
                #pragma unroll
                for (int ntp = 0; ntp < 4; ++ntp) {
                    uint32_t b0, b1, b2, b3;
                    LDSM4T(b0, b1, b2, b3, vrow + va_off + ntp * 32);
                    mma16h(oAcc[2 * ntp], pa[kp], b0, b1);
                    mma16h(oAcc[2 * ntp + 1], pa[kp], b2, b3);
                }
                uint32_t c0, c1;
                LDSM2T(c0, c1, vrow + vs_off);
                mma16h(oSum, pa[kp], c0, c1);
            }
        }
        __syncthreads();
    }

    // rowsum lives in tig==0 lane of each quad (ones column = dv 64)
    float rs0 = __shfl_sync(0xffffffffu, oSum[0], lane & ~3);
    float rs1 = __shfl_sync(0xffffffffu, oSum[2], lane & ~3);
    float inv0 = 1.0f / rs0;
    float inv1 = 1.0f / rs1;

    int row0 = n0blk + m0 + gid;
    #pragma unroll
    for (int nt = 0; nt < 8; ++nt) {
        int dv = nt * 8 + 2 * tig;
        float2 w0, w1;
        w0.x = oAcc[nt][0] * inv0; w0.y = oAcc[nt][1] * inv0;
        w1.x = oAcc[nt][2] * inv1; w1.y = oAcc[nt][3] * inv1;
        *(float2*)(&o[((size_t)(b * NN + row0)) * DD + h * HD + dv]) = w0;
        *(float2*)(&o[((size_t)(b * NN + row0 + 8)) * DD + h * HD + dv]) = w1;
    }
}

// ---------------- tail ----------------
__global__ void tail_k(float* __restrict__ dst) {
    dst[0] = 1.0f / (float)KCC;
}

// ---------------- launch ----------------
extern "C" void kernel_launch(void* const* d_in, const int* in_sizes, int n_in,
                              void* d_out, int out_size) {
    const float* x      = (const float*)d_in[0];
    const float* ctx    = (const float*)d_in[1];
    const float* q_w    = (const float*)d_in[2];
    const float* q_b    = (const float*)d_in[3];
    const float* kv_w   = (const float*)d_in[4];
    const float* kv_b   = (const float*)d_in[5];
    const float* proj_w = (const float*)d_in[6];
    const float* proj_b = (const float*)d_in[7];
    float* out = (float*)d_out;

    float *ctxn, *ao;
    __half *qhp, *khp, *vhp;
    cudaGetSymbolAddress((void**)&ctxn, g_ctxn);
    cudaGetSymbolAddress((void**)&qhp,  g_qh);
    cudaGetSymbolAddress((void**)&khp,  g_kh);
    cudaGetSymbolAddress((void**)&vhp,  g_vh);
    cudaGetSymbolAddress((void**)&ao,   g_ao);

    cudaFuncSetAttribute(gemm_tc<0>, cudaFuncAttributeMaxDynamicSharedMemorySize, GEMM_SMEM);
    cudaFuncSetAttribute(gemm_tc<1>, cudaFuncAttributeMaxDynamicSharedMemorySize, GEMM_SMEM);
    cudaFuncSetAttribute(gemm_tc<2>, cudaFuncAttributeMaxDynamicSharedMemorySize, GEMM_SMEM);
    cudaFuncSetAttribute(attn_k,     cudaFuncAttributeMaxDynamicSharedMemorySize, ATTN_SMEM);

    rmsnorm_k<<<BB * KCC, 256>>>(ctx, ctxn);

    dim3 gq(DD / 256, (BB * NN) / 128);
    gemm_tc<0><<<gq, 256, GEMM_SMEM>>>(x, q_w, q_b, nullptr, BB * NN, DD, DD, qhp, nullptr, nullptr);

    dim3 gkv((2 * DD) / 256, (BB * KCC) / 128);
    gemm_tc<1><<<gkv, 256, GEMM_SMEM>>>(ctxn, kv_w, kv_b, nullptr, BB * KCC, 2 * DD, DD, nullptr, khp, vhp);

    dim3 ga(NN / 128, BB * HH);
    attn_k<<<ga, 256, ATTN_SMEM>>>(qhp, khp, vhp, ao);

    dim3 gp(DD / 256, (BB * NN) / 128);
    gemm_tc<2><<<gp, 256, GEMM_SMEM>>>(ao, proj_w, proj_b, out, BB * NN, DD, DD, nullptr, nullptr, nullptr);

    if (out_size > BB * NN * DD) {
        tail_k<<<1, 1>>>(out + (size_t)BB * NN * DD);
    }
}

// round 11
// speedup vs baseline: 2.3458x; 1.0031x over previous
#include <cuda_runtime.h>
#include <cuda_fp16.h>
#include <math.h>
#include <stdint.h>

#define BB   4
#define NN   2048
#define KCC  2048
#define DD   1024
#define HH   16
#define HD   64
#define SCALE_F 0.125f
#define EPS_F   1e-6f

// ---------------- scratch ----------------
__device__ __half g_xh  [BB * NN  * DD];
__device__ __half g_ctxnh[BB * KCC * DD];
__device__ __half g_qwh [DD * DD];
__device__ __half g_kvwh[DD * 2 * DD];
__device__ __half g_pwh [DD * DD];
__device__ __half g_qh  [BB * NN  * DD];
__device__ __half g_kh  [BB * KCC * DD];
__device__ __half g_vh  [BB * KCC * DD];
__device__ __half g_aoh [BB * NN  * DD];

// ---------------- helpers ----------------
__device__ __forceinline__ uint32_t packh2(float a, float b) {
    uint32_t r;
    asm("cvt.rn.f16x2.f32 %0, %2, %1;" : "=r"(r) : "f"(a), "f"(b));
    return r;
}
__device__ __forceinline__ void mma16h(float* c, const uint32_t* a, uint32_t b0, uint32_t b1) {
    asm volatile(
        "mma.sync.aligned.m16n8k16.row.col.f32.f16.f16.f32 "
        "{%0,%1,%2,%3}, {%4,%5,%6,%7}, {%8,%9}, {%0,%1,%2,%3};"
        : "+f"(c[0]), "+f"(c[1]), "+f"(c[2]), "+f"(c[3])
        : "r"(a[0]), "r"(a[1]), "r"(a[2]), "r"(a[3]), "r"(b0), "r"(b1));
}
__device__ __forceinline__ uint32_t smem_u32(const void* p) {
    return (uint32_t)__cvta_generic_to_shared(p);
}
#define LDSM4(r0,r1,r2,r3,addr) \
    asm volatile("ldmatrix.sync.aligned.m8n8.x4.shared.b16 {%0,%1,%2,%3},[%4];" \
        : "=r"(r0),"=r"(r1),"=r"(r2),"=r"(r3) : "r"(addr))
#define LDSM4T(r0,r1,r2,r3,addr) \
    asm volatile("ldmatrix.sync.aligned.m8n8.x4.trans.shared.b16 {%0,%1,%2,%3},[%4];" \
        : "=r"(r0),"=r"(r1),"=r"(r2),"=r"(r3) : "r"(addr))
#define LDSM2T(r0,r1,addr) \
    asm volatile("ldmatrix.sync.aligned.m8n8.x2.trans.shared.b16 {%0,%1},[%2];" \
        : "=r"(r0),"=r"(r1) : "r"(addr))
#define CPA16(dst,src) \
    asm volatile("cp.async.cg.shared.global [%0],[%1],16;" :: "r"(dst),"l"(src))
#define CPCOMMIT() asm volatile("cp.async.commit_group;")
#define CPWAIT(n)  asm volatile("cp.async.wait_group %0;" :: "n"(n))

__device__ __forceinline__ uint32_t h2max(uint32_t a, uint32_t b) {
    uint32_t r; asm("max.f16x2 %0,%1,%2;" : "=r"(r) : "r"(a), "r"(b)); return r;
}
__device__ __forceinline__ uint32_t h2min(uint32_t a, uint32_t b) {
    uint32_t r; asm("min.f16x2 %0,%1,%2;" : "=r"(r) : "r"(a), "r"(b)); return r;
}
__device__ __forceinline__ uint32_t h2fma(uint32_t a, uint32_t b, uint32_t c) {
    uint32_t r; asm("fma.rn.f16x2 %0,%1,%2,%3;" : "=r"(r) : "r"(a), "r"(b), "r"(c)); return r;
}
__device__ __forceinline__ uint32_t h2ex2(uint32_t a) {
    uint32_t r; asm("ex2.approx.f16x2 %0,%1;" : "=r"(r) : "r"(a)); return r;
}

// ---------------- fp32 -> fp16 convert ----------------
__global__ void f2h_k(const float* __restrict__ s, __half* __restrict__ d, int n) {
    int i = (blockIdx.x * blockDim.x + threadIdx.x) * 8;
    if (i < n) {
        float4 a = *(const float4*)(s + i);
        float4 b = *(const float4*)(s + i + 4);
        uint4 w;
        w.x = packh2(a.x, a.y); w.y = packh2(a.z, a.w);
        w.z = packh2(b.x, b.y); w.w = packh2(b.z, b.w);
        *(uint4*)(d + i) = w;
    }
}

// ---------------- rms norm (fp16 out) ----------------
__global__ void rmsnorm_k(const float* __restrict__ ctx, __half* __restrict__ o) {
    int row = blockIdx.x;
    const float4* p = reinterpret_cast<const float4*>(ctx + (size_t)row * DD);
    float4 v = p[threadIdx.x];
    float ss = v.x * v.x + v.y * v.y + v.z * v.z + v.w * v.w;
    __shared__ float red[8];
    #pragma unroll
    for (int off = 16; off; off >>= 1) ss += __shfl_xor_sync(0xffffffffu, ss, off);
    if ((threadIdx.x & 31) == 0) red[threadIdx.x >> 5] = ss;
    __syncthreads();
    if (threadIdx.x < 32) {
        float t = (threadIdx.x < 8) ? red[threadIdx.x] : 0.0f;
        #pragma unroll
        for (int off = 4; off; off >>= 1) t += __shfl_xor_sync(0xffffffffu, t, off);
        if (threadIdx.x == 0) red[0] = t;
    }
    __syncthreads();
    float r = 1.0f / sqrtf(red[0] * (1.0f / DD) + EPS_F);
    uint2 w;
    w.x = packh2(v.x * r, v.y * r);
    w.y = packh2(v.z * r, v.w * r);
    *(uint2*)(o + (size_t)row * DD + threadIdx.x * 4) = w;
}

// ---------------- fp16 GEMM: cp.async + ldmatrix ----------------
// C[M,N2] = A[M,K2] @ W[K2,N2] + bias.  Block 128x256, BK=32, 8 warps @64x64.
// A smem: [128][80B] (32 halves + 8 pad).  W smem: [32][528B] (256 halves + 8 pad).
#define ARB 80
#define BRB 528
#define ABUF (128 * ARB)
#define BBUF (32 * BRB)
#define GEMM_SMEM (2 * ABUF + 2 * BBUF)

template <int MODE>
__global__ void __launch_bounds__(256)
gemm_h(const __half* __restrict__ A, const __half* __restrict__ W,
       const float* __restrict__ bias, float* __restrict__ C,
       int M2, int N2, int K2,
       __half* __restrict__ hC, __half* __restrict__ hK, __half* __restrict__ hV) {
    extern __shared__ __align__(16) unsigned char sm[];
    uint32_t s_a = smem_u32(sm);
    uint32_t s_b = s_a + 2 * ABUF;

    int tid = threadIdx.x;
    int lane = tid & 31;
    int wid = tid >> 5;
    int gid = lane >> 2, tig = lane & 3;
    int warpm = wid & 1, warpn = wid >> 1;
    int rowBase = blockIdx.y * 128, colBase = blockIdx.x * 256;

    const __half* Abase = A + (size_t)rowBase * K2;
    const __half* Wbase = W + colBase;

    // A chunks: c in [0,512): row=c>>2, c16=c&3
    int ar0 = tid >> 2,  ac0 = tid & 3;          // j=0
    int ar1 = (tid + 256) >> 2, ac1 = tid & 3;   // j=1
    // W chunks: c in [0,1024): row=c>>5, c16=c&31
    uint32_t a_off = (uint32_t)((((lane >> 3) & 1) * 8 + (lane & 7)) * ARB + (lane >> 4) * 16);
    uint32_t b_off = (uint32_t)((((lane >> 3) & 1) * 8 + (lane & 7)) * BRB + (lane >> 4) * 16);

    // prologue: tile 0 -> buf 0
    {
        CPA16(s_a + ar0 * ARB + ac0 * 16, Abase + (size_t)ar0 * K2 + ac0 * 8);
        CPA16(s_a + ar1 * ARB + ac1 * 16, Abase + (size_t)ar1 * K2 + ac1 * 8);
        #pragma unroll
        for (int j = 0; j < 4; ++j) {
            int c = tid + 256 * j;
            int row = c >> 5, c16 = c & 31;
            CPA16(s_b + row * BRB + c16 * 16, Wbase + (size_t)row * N2 + c16 * 8);
        }
        CPCOMMIT();
    }

    float acc[4][8][4];
    #pragma unroll
    for (int mt = 0; mt < 4; ++mt)
        #pragma unroll
        for (int nt = 0; nt < 8; ++nt)
            #pragma unroll
            for (int r = 0; r < 4; ++r) acc[mt][nt][r] = 0.0f;

    int nT = K2 >> 5;
    for (int t = 0; t < nT; ++t) {
        if (t + 1 < nT) {
            int nb = (t + 1) & 1;
            const __half* As2 = Abase + (t + 1) * 32;
            const __half* Ws2 = Wbase + (size_t)(t + 1) * 32 * N2;
            CPA16(s_a + nb * ABUF + ar0 * ARB + ac0 * 16, As2 + (size_t)ar0 * K2 + ac0 * 8);
            CPA16(s_a + nb * ABUF + ar1 * ARB + ac1 * 16, As2 + (size_t)ar1 * K2 + ac1 * 8);
            #pragma unroll
            for (int j = 0; j < 4; ++j) {
                int c = tid + 256 * j;
                int row = c >> 5, c16 = c & 31;
                CPA16(s_b + nb * BBUF + row * BRB + c16 * 16, Ws2 + (size_t)row * N2 + c16 * 8);
            }
            CPCOMMIT();
            CPWAIT(1);
        } else {
            CPWAIT(0);
        }
        __syncthreads();

        uint32_t ab = s_a + (t & 1) * ABUF;
        uint32_t bb = s_b + (t & 1) * BBUF;
        #pragma unroll
        for (int ks = 0; ks < 2; ++ks) {
            uint32_t af[4][4];
            #pragma unroll
            for (int mt = 0; mt < 4; ++mt)
                LDSM4(af[mt][0], af[mt][1], af[mt][2], af[mt][3],
                      ab + a_off + (warpm * 64 + mt * 16) * ARB + ks * 32);
            #pragma unroll
            for (int ntp = 0; ntp < 4; ++ntp) {
                uint32_t b0, b1, b2, b3;
                LDSM4T(b0, b1, b2, b3,
                       bb + b_off + (ks * 16) * BRB + warpn * 128 + ntp * 32);
                #pragma unroll
                for (int mt = 0; mt < 4; ++mt) {
                    mma16h(acc[mt][2 * ntp], af[mt], b0, b1);
                    mma16h(acc[mt][2 * ntp + 1], af[mt], b2, b3);
                }
            }
        }
        __syncthreads();
    }

    #pragma unroll
    for (int mt = 0; mt < 4; ++mt) {
        int r0 = rowBase + warpm * 64 + mt * 16 + gid;
        #pragma unroll
        for (int nt = 0; nt < 8; ++nt) {
            int col = colBase + warpn * 64 + nt * 8 + tig * 2;
            float2 bb2 = *(const float2*)(bias + col);
            float2 v0, v1;
            v0.x = acc[mt][nt][0] + bb2.x; v0.y = acc[mt][nt][1] + bb2.y;
            v1.x = acc[mt][nt][2] + bb2.x; v1.y = acc[mt][nt][3] + bb2.y;
            if (MODE == 0) {
                uint32_t w0 = packh2(v0.x * SCALE_F, v0.y * SCALE_F);
                uint32_t w1 = packh2(v1.x * SCALE_F, v1.y * SCALE_F);
                ((uint32_t*)hC)[((size_t)r0 * N2 + col) >> 1] = w0;
                ((uint32_t*)hC)[((size_t)(r0 + 8) * N2 + col) >> 1] = w1;
            } else if (MODE == 2) {
                *(float2*)(&C[(size_t)r0 * N2 + col]) = v0;
                *(float2*)(&C[(size_t)(r0 + 8) * N2 + col]) = v1;
            } else {
                uint32_t w0 = packh2(v0.x, v0.y);
                uint32_t w1 = packh2(v1.x, v1.y);
                if (col < DD) {
                    ((uint32_t*)hK)[((size_t)r0 * DD + col) >> 1] = w0;
                    ((uint32_t*)hK)[((size_t)(r0 + 8) * DD + col) >> 1] = w1;
                } else {
                    ((uint32_t*)hV)[((size_t)r0 * DD + col - DD) >> 1] = w0;
                    ((uint32_t*)hV)[((size_t)(r0 + 8) * DD + col - DD) >> 1] = w1;
                }
            }
        }
    }
}

// ---------------- fused attention (unchanged core; fp16 output) ----------
#define ROWB   144
#define BUFB   (128 * ROWB)
#define ATTN_SMEM (5 * BUFB)

__global__ void __launch_bounds__(256, 2)
attn_k(const __half* __restrict__ qh, const __half* __restrict__ kh,
       const __half* __restrict__ vh, __half* __restrict__ oh) {
    extern __shared__ __align__(16) unsigned char smraw[];
    uint32_t s_q = smem_u32(smraw);
    uint32_t s_k = s_q + BUFB;
    uint32_t s_v = s_q + 3 * BUFB;

    int tid = threadIdx.x;
    int lane = tid & 31;
    int wid = tid >> 5;
    int gid = lane >> 2, tig = lane & 3;

    int bh = blockIdx.y;
    int b = bh >> 4;
    int h = bh & 15;
    int n0blk = blockIdx.x * 128;

    const __half* qbase = qh + ((size_t)(b * NN + n0blk)) * DD + h * HD;
    const __half* kbase = kh + (size_t)b * KCC * DD + h * HD;
    const __half* vbase = vh + (size_t)b * KCC * DD + h * HD;

    #pragma unroll
    for (int i = 0; i < 4; ++i) {
        int idx = tid + 256 * i;
        int row = idx >> 3;
        int c = idx & 7;
        uint4 t = *(const uint4*)(qbase + (size_t)row * DD + c * 8);
        *(uint4*)(smraw + row * ROWB + c * 16) = t;
    }
    #pragma unroll
    for (int i = 0; i < 4; ++i) {
        int idx = tid + 256 * i;
        int br = idx >> 2;
        int w  = idx & 3;
        *(uint32_t*)(smraw + 3 * BUFB + br * ROWB + 128 + w * 4) =
            (w == 0) ? 0x00003C00u : 0u;
    }

    int m0 = wid * 16;
    uint32_t qa = s_q + (uint32_t)((m0 + ((lane >> 3) & 1) * 8 + (lane & 7)) * ROWB
                                   + (lane >> 4) * 16);
    uint32_t ka_off = (uint32_t)(((lane & 7) + (lane >> 4) * 8) * ROWB
                                 + ((lane >> 3) & 1) * 16);
    uint32_t va_off = (uint32_t)((((lane >> 3) & 1) * 8 + (lane & 7)) * ROWB
                                 + (lane >> 4) * 16);
    uint32_t vs_off = (uint32_t)((lane & 15) * ROWB + 128);

    int crow = tid >> 1;
    int cg   = tid & 1;
    const __half* ksrc0 = kbase + (size_t)crow * DD + cg * 32;
    const __half* vsrc0 = vbase + (size_t)crow * DD + cg * 32;
    uint32_t kdst0 = s_k + crow * ROWB + cg * 64;
    uint32_t vdst0 = s_v + crow * ROWB + cg * 64;

    {
        #pragma unroll
        for (int j = 0; j < 4; ++j) {
            CPA16(kdst0 + j * 16, ksrc0 + j * 8);
            CPA16(vdst0 + j * 16, vsrc0 + j * 8);
        }
        CPCOMMIT();
    }

    float oAcc[8][4];
    #pragma unroll
    for (int nt = 0; nt < 8; ++nt)
        #pragma unroll
        for (int r = 0; r < 4; ++r) oAcc[nt][r] = 0.0f;
    float oSum[4] = {0.0f, 0.0f, 0.0f, 0.0f};

    const uint32_t NEG10 = 0xC900C900u, POS10 = 0x49004900u;
    const uint32_t L2E2 = packh2(1.4426950f, 1.4426950f);
    const uint32_t OFF2 = packh2(0.5730496f, 0.5730496f);

    for (int c = 0; c < KCC / 128; ++c) {
        if (c + 1 < KCC / 128) {
            int nb = (c + 1) & 1;
            const __half* ks = ksrc0 + (size_t)(c + 1) * 128 * DD;
            const __half* vs = vsrc0 + (size_t)(c + 1) * 128 * DD;
            #pragma unroll
            for (int j = 0; j < 4; ++j) {
                CPA16(kdst0 + nb * BUFB + j * 16, ks + j * 8);
                CPA16(vdst0 + nb * BUFB + j * 16, vs + j * 8);
            }
            CPCOMMIT();
            CPWAIT(1);
        } else {
            CPWAIT(0);
        }
        __syncthreads();

        uint32_t bo = (c & 1) * BUFB;

        #pragma unroll
        for (int half = 0; half < 2; ++half) {
            float sAcc[8][4];
            #pragma unroll
            for (int nt = 0; nt < 8; ++nt)
                #pragma unroll
                for (int r = 0; r < 4; ++r) sAcc[nt][r] = 0.0f;

            #pragma unroll
            for (int ks = 0; ks < 4; ++ks) {
                uint32_t a0, a1, a2, a3;
                LDSM4(a0, a1, a2, a3, qa + ks * 32);
                uint32_t af[4] = {a0, a1, a2, a3};
                #pragma unroll
                for (int ntp = 0; ntp < 4; ++ntp) {
                    uint32_t b0, b1, b2, b3;
                    LDSM4(b0, b1, b2, b3,
                          s_k + bo + ka_off + (half * 64 + ntp * 16) * ROWB + ks * 32);
                    mma16h(sAcc[2 * ntp], af, b0, b1);
                    mma16h(sAcc[2 * ntp + 1], af, b2, b3);
                }
            }

            uint32_t pa[4][4];
            #pragma unroll
            for (int nt = 0; nt < 8; ++nt) {
                uint32_t lo = packh2(sAcc[nt][0], sAcc[nt][1]);
                uint32_t hi = packh2(sAcc[nt][2], sAcc[nt][3]);
                lo = h2ex2(h2fma(h2min(h2max(lo, NEG10), POS10), L2E2, OFF2));
                hi = h2ex2(h2fma(h2min(h2max(hi, NEG10), POS10), L2E2, OFF2));
                int kp = nt >> 1, s = (nt & 1) << 1;
                pa[kp][s + 0] = lo;
                pa[kp][s + 1] = hi;
            }

            #pragma unroll
            for (int kp = 0; kp < 4; ++kp) {
                uint32_t vrow = s_v + bo + (half * 64 + kp * 16) * ROWB;
                #pragma unroll
                for (int ntp = 0; ntp < 4; ++ntp) {
                    uint32_t b0, b1, b2, b3;
                    LDSM4T(b0, b1, b2, b3, vrow + va_off + ntp * 32);
                    mma16h(oAcc[2 * ntp], pa[kp], b0, b1);
                    mma16h(oAcc[2 * ntp + 1], pa[kp], b2, b3);
                }
                uint32_t c0, c1;
                LDSM2T(c0, c1, vrow + vs_off);
                mma16h(oSum, pa[kp], c0, c1);
            }
        }
        __syncthreads();
    }

    float rs0 = __shfl_sync(0xffffffffu, oSum[0], lane & ~3);
    float rs1 = __shfl_sync(0xffffffffu, oSum[2], lane & ~3);
    float inv0 = 1.0f / rs0;
    float inv1 = 1.0f / rs1;

    int row0 = n0blk + m0 + gid;
    #pragma unroll
    for (int nt = 0; nt < 8; ++nt) {
        int dv = nt * 8 + 2 * tig;
        uint32_t w0 = packh2(oAcc[nt][0] * inv0, oAcc[nt][1] * inv0);
        uint32_t w1 = packh2(oAcc[nt][2] * inv1, oAcc[nt][3] * inv1);
        *(uint32_t*)(&oh[((size_t)(b * NN + row0)) * DD + h * HD + dv]) = w0;
        *(uint32_t*)(&oh[((size_t)(b * NN + row0 + 8)) * DD + h * HD + dv]) = w1;
    }
}

// ---------------- tail ----------------
__global__ void tail_k(float* __restrict__ dst) {
    dst[0] = 1.0f / (float)KCC;
}

// ---------------- launch ----------------
extern "C" void kernel_launch(void* const* d_in, const int* in_sizes, int n_in,
                              void* d_out, int out_size) {
    const float* x      = (const float*)d_in[0];
    const float* ctx    = (const float*)d_in[1];
    const float* q_w    = (const float*)d_in[2];
    const float* q_b    = (const float*)d_in[3];
    const float* kv_w   = (const float*)d_in[4];
    const float* kv_b   = (const float*)d_in[5];
    const float* proj_w = (const float*)d_in[6];
    const float* proj_b = (const float*)d_in[7];
    float* out = (float*)d_out;

    __half *xh, *ctxnh, *qwh, *kvwh, *pwh, *qhp, *khp, *vhp, *aoh;
    cudaGetSymbolAddress((void**)&xh,    g_xh);
    cudaGetSymbolAddress((void**)&ctxnh, g_ctxnh);
    cudaGetSymbolAddress((void**)&qwh,   g_qwh);
    cudaGetSymbolAddress((void**)&kvwh,  g_kvwh);
    cudaGetSymbolAddress((void**)&pwh,   g_pwh);
    cudaGetSymbolAddress((void**)&qhp,   g_qh);
    cudaGetSymbolAddress((void**)&khp,   g_kh);
    cudaGetSymbolAddress((void**)&vhp,   g_vh);
    cudaGetSymbolAddress((void**)&aoh,   g_aoh);

    cudaFuncSetAttribute(gemm_h<0>, cudaFuncAttributeMaxDynamicSharedMemorySize, GEMM_SMEM);
    cudaFuncSetAttribute(gemm_h<1>, cudaFuncAttributeMaxDynamicSharedMemorySize, GEMM_SMEM);
    cudaFuncSetAttribute(gemm_h<2>, cudaFuncAttributeMaxDynamicSharedMemorySize, GEMM_SMEM);
    cudaFuncSetAttribute(attn_k,    cudaFuncAttributeMaxDynamicSharedMemorySize, ATTN_SMEM);

    // one-time fp16 conversions
    f2h_k<<<(BB * NN * DD / 8 + 255) / 256, 256>>>(x, xh, BB * NN * DD);
    f2h_k<<<(DD * DD / 8 + 255) / 256, 256>>>(q_w, qwh, DD * DD);
    f2h_k<<<(DD * 2 * DD / 8 + 255) / 256, 256>>>(kv_w, kvwh, DD * 2 * DD);
    f2h_k<<<(DD * DD / 8 + 255) / 256, 256>>>(proj_w, pwh, DD * DD);

    rmsnorm_k<<<BB * KCC, 256>>>(ctx, ctxnh);

    dim3 gq(DD / 256, (BB * NN) / 128);
    gemm_h<0><<<gq, 256, GEMM_SMEM>>>(xh, qwh, q_b, nullptr, BB * NN, DD, DD, qhp, nullptr, nullptr);

    dim3 gkv((2 * DD) / 256, (BB * KCC) / 128);
    gemm_h<1><<<gkv, 256, GEMM_SMEM>>>(ctxnh, kvwh, kv_b, nullptr, BB * KCC, 2 * DD, DD, nullptr, khp, vhp);

    dim3 ga(NN / 128, BB * HH);
    attn_k<<<ga, 256, ATTN_SMEM>>>(qhp, khp, vhp, aoh);

    dim3 gp(DD / 256, (BB * NN) / 128);
    gemm_h<2><<<gp, 256, GEMM_SMEM>>>(aoh, pwh, proj_b, out, BB * NN, DD, DD, nullptr, nullptr, nullptr);

    if (out_size > BB * NN * DD) {
        tail_k<<<1, 1>>>(out + (size_t)BB * NN * DD);
    }
}

// round 14
// speedup vs baseline: 2.3881x; 1.0180x over previous
#include <cuda_runtime.h>
#include <cuda_fp16.h>
#include <math.h>
#include <stdint.h>

#define BB   4
#define NN   2048
#define KCC  2048
#define DD   1024
#define HH   16
#define HD   64
#define SCALE_F 0.125f
#define EPS_F   1e-6f

// ---------------- scratch ----------------
__device__ __half g_xh  [BB * NN  * DD];
__device__ __half g_ctxnh[BB * KCC * DD];
__device__ __half g_qwh [DD * DD];
__device__ __half g_kvwh[DD * 2 * DD];
__device__ __half g_pwh [DD * DD];
__device__ __half g_qh  [BB * NN  * DD];
__device__ __half g_kh  [BB * KCC * DD];
__device__ __half g_vh  [BB * KCC * DD];
__device__ __half g_aoh [BB * NN  * DD];

// ---------------- helpers ----------------
__device__ __forceinline__ uint32_t packh2(float a, float b) {
    uint32_t r;
    asm("cvt.rn.f16x2.f32 %0, %2, %1;" : "=r"(r) : "f"(a), "f"(b));
    return r;
}
__device__ __forceinline__ void mma16h(float* c, const uint32_t* a, uint32_t b0, uint32_t b1) {
    asm volatile(
        "mma.sync.aligned.m16n8k16.row.col.f32.f16.f16.f32 "
        "{%0,%1,%2,%3}, {%4,%5,%6,%7}, {%8,%9}, {%0,%1,%2,%3};"
        : "+f"(c[0]), "+f"(c[1]), "+f"(c[2]), "+f"(c[3])
        : "r"(a[0]), "r"(a[1]), "r"(a[2]), "r"(a[3]), "r"(b0), "r"(b1));
}
__device__ __forceinline__ uint32_t smem_u32(const void* p) {
    return (uint32_t)__cvta_generic_to_shared(p);
}
#define LDSM4(r0,r1,r2,r3,addr) \
    asm volatile("ldmatrix.sync.aligned.m8n8.x4.shared.b16 {%0,%1,%2,%3},[%4];" \
        : "=r"(r0),"=r"(r1),"=r"(r2),"=r"(r3) : "r"(addr))
#define LDSM4T(r0,r1,r2,r3,addr) \
    asm volatile("ldmatrix.sync.aligned.m8n8.x4.trans.shared.b16 {%0,%1,%2,%3},[%4];" \
        : "=r"(r0),"=r"(r1),"=r"(r2),"=r"(r3) : "r"(addr))
#define LDSM2T(r0,r1,addr) \
    asm volatile("ldmatrix.sync.aligned.m8n8.x2.trans.shared.b16 {%0,%1},[%2];" \
        : "=r"(r0),"=r"(r1) : "r"(addr))
#define CPA16(dst,src) \
    asm volatile("cp.async.cg.shared.global [%0],[%1],16;" :: "r"(dst),"l"(src))
#define CPCOMMIT() asm volatile("cp.async.commit_group;")
#define CPWAIT(n)  asm volatile("cp.async.wait_group %0;" :: "n"(n))

__device__ __forceinline__ uint32_t h2max(uint32_t a, uint32_t b) {
    uint32_t r; asm("max.f16x2 %0,%1,%2;" : "=r"(r) : "r"(a), "r"(b)); return r;
}
__device__ __forceinline__ uint32_t h2min(uint32_t a, uint32_t b) {
    uint32_t r; asm("min.f16x2 %0,%1,%2;" : "=r"(r) : "r"(a), "r"(b)); return r;
}
__device__ __forceinline__ uint32_t h2fma(uint32_t a, uint32_t b, uint32_t c) {
    uint32_t r; asm("fma.rn.f16x2 %0,%1,%2,%3;" : "=r"(r) : "r"(a), "r"(b), "r"(c)); return r;
}
__device__ __forceinline__ uint32_t h2ex2(uint32_t a) {
    uint32_t r; asm("ex2.approx.f16x2 %0,%1;" : "=r"(r) : "r"(a)); return r;
}

// ---------------- fp32 -> fp16 convert ----------------
__global__ void f2h_k(const float* __restrict__ s, __half* __restrict__ d, int n) {
    int i = (blockIdx.x * blockDim.x + threadIdx.x) * 8;
    if (i < n) {
        float4 a = *(const float4*)(s + i);
        float4 b = *(const float4*)(s + i + 4);
        uint4 w;
        w.x = packh2(a.x, a.y); w.y = packh2(a.z, a.w);
        w.z = packh2(b.x, b.y); w.w = packh2(b.z, b.w);
        *(uint4*)(d + i) = w;
    }
}

// ---------------- rms norm (fp16 out) ----------------
__global__ void rmsnorm_k(const float* __restrict__ ctx, __half* __restrict__ o) {
    int row = blockIdx.x;
    const float4* p = reinterpret_cast<const float4*>(ctx + (size_t)row * DD);
    float4 v = p[threadIdx.x];
    float ss = v.x * v.x + v.y * v.y + v.z * v.z + v.w * v.w;
    __shared__ float red[8];
    #pragma unroll
    for (int off = 16; off; off >>= 1) ss += __shfl_xor_sync(0xffffffffu, ss, off);
    if ((threadIdx.x & 31) == 0) red[threadIdx.x >> 5] = ss;
    __syncthreads();
    if (threadIdx.x < 32) {
        float t = (threadIdx.x < 8) ? red[threadIdx.x] : 0.0f;
        #pragma unroll
        for (int off = 4; off; off >>= 1) t += __shfl_xor_sync(0xffffffffu, t, off);
        if (threadIdx.x == 0) red[0] = t;
    }
    __syncthreads();
    float r = 1.0f / sqrtf(red[0] * (1.0f / DD) + EPS_F);
    uint2 w;
    w.x = packh2(v.x * r, v.y * r);
    w.y = packh2(v.z * r, v.w * r);
    *(uint2*)(o + (size_t)row * DD + threadIdx.x * 4) = w;
}

// ---------------- fp16 GEMM: cp.async + ldmatrix (R11, passing) ----------
#define ARB 80
#define BRB 528
#define ABUF (128 * ARB)
#define BBUF (32 * BRB)
#define GEMM_SMEM (2 * ABUF + 2 * BBUF)

template <int MODE>
__global__ void __launch_bounds__(256)
gemm_h(const __half* __restrict__ A, const __half* __restrict__ W,
       const float* __restrict__ bias, float* __restrict__ C,
       int M2, int N2, int K2,
       __half* __restrict__ hC, __half* __restrict__ hK, __half* __restrict__ hV) {
    extern __shared__ __align__(16) unsigned char sm[];
    uint32_t s_a = smem_u32(sm);
    uint32_t s_b = s_a + 2 * ABUF;

    int tid = threadIdx.x;
    int lane = tid & 31;
    int wid = tid >> 5;
    int gid = lane >> 2, tig = lane & 3;
    int warpm = wid & 1, warpn = wid >> 1;
    int rowBase = blockIdx.y * 128, colBase = blockIdx.x * 256;

    const __half* Abase = A + (size_t)rowBase * K2;
    const __half* Wbase = W + colBase;

    int ar0 = tid >> 2,  ac0 = tid & 3;
    int ar1 = (tid + 256) >> 2, ac1 = tid & 3;
    uint32_t a_off = (uint32_t)((((lane >> 3) & 1) * 8 + (lane & 7)) * ARB + (lane >> 4) * 16);
    uint32_t b_off = (uint32_t)((((lane >> 3) & 1) * 8 + (lane & 7)) * BRB + (lane >> 4) * 16);

    {
        CPA16(s_a + ar0 * ARB + ac0 * 16, Abase + (size_t)ar0 * K2 + ac0 * 8);
        CPA16(s_a + ar1 * ARB + ac1 * 16, Abase + (size_t)ar1 * K2 + ac1 * 8);
        #pragma unroll
        for (int j = 0; j < 4; ++j) {
            int c = tid + 256 * j;
            int row = c >> 5, c16 = c & 31;
            CPA16(s_b + row * BRB + c16 * 16, Wbase + (size_t)row * N2 + c16 * 8);
        }
        CPCOMMIT();
    }

    float acc[4][8][4];
    #pragma unroll
    for (int mt = 0; mt < 4; ++mt)
        #pragma unroll
        for (int nt = 0; nt < 8; ++nt)
            #pragma unroll
            for (int r = 0; r < 4; ++r) acc[mt][nt][r] = 0.0f;

    int nT = K2 >> 5;
    for (int t = 0; t < nT; ++t) {
        if (t + 1 < nT) {
            int nb = (t + 1) & 1;
            const __half* As2 = Abase + (t + 1) * 32;
            const __half* Ws2 = Wbase + (size_t)(t + 1) * 32 * N2;
            CPA16(s_a + nb * ABUF + ar0 * ARB + ac0 * 16, As2 + (size_t)ar0 * K2 + ac0 * 8);
            CPA16(s_a + nb * ABUF + ar1 * ARB + ac1 * 16, As2 + (size_t)ar1 * K2 + ac1 * 8);
            #pragma unroll
            for (int j = 0; j < 4; ++j) {
                int c = tid + 256 * j;
                int row = c >> 5, c16 = c & 31;
                CPA16(s_b + nb * BBUF + row * BRB + c16 * 16, Ws2 + (size_t)row * N2 + c16 * 8);
            }
            CPCOMMIT();
            CPWAIT(1);
        } else {
            CPWAIT(0);
        }
        __syncthreads();

        uint32_t ab = s_a + (t & 1) * ABUF;
        uint32_t bb = s_b + (t & 1) * BBUF;
        #pragma unroll
        for (int ks = 0; ks < 2; ++ks) {
            uint32_t af[4][4];
            #pragma unroll
            for (int mt = 0; mt < 4; ++mt)
                LDSM4(af[mt][0], af[mt][1], af[mt][2], af[mt][3],
                      ab + a_off + (warpm * 64 + mt * 16) * ARB + ks * 32);
            #pragma unroll
            for (int ntp = 0; ntp < 4; ++ntp) {
                uint32_t b0, b1, b2, b3;
                LDSM4T(b0, b1, b2, b3,
                       bb + b_off + (ks * 16) * BRB + warpn * 128 + ntp * 32);
                #pragma unroll
                for (int mt = 0; mt < 4; ++mt) {
                    mma16h(acc[mt][2 * ntp], af[mt], b0, b1);
                    mma16h(acc[mt][2 * ntp + 1], af[mt], b2, b3);
                }
            }
        }
        __syncthreads();
    }

    #pragma unroll
    for (int mt = 0; mt < 4; ++mt) {
        int r0 = rowBase + warpm * 64 + mt * 16 + gid;
        #pragma unroll
        for (int nt = 0; nt < 8; ++nt) {
            int col = colBase + warpn * 64 + nt * 8 + tig * 2;
            float2 bb2 = *(const float2*)(bias + col);
            float2 v0, v1;
            v0.x = acc[mt][nt][0] + bb2.x; v0.y = acc[mt][nt][1] + bb2.y;
            v1.x = acc[mt][nt][2] + bb2.x; v1.y = acc[mt][nt][3] + bb2.y;
            if (MODE == 0) {
                uint32_t w0 = packh2(v0.x * SCALE_F, v0.y * SCALE_F);
                uint32_t w1 = packh2(v1.x * SCALE_F, v1.y * SCALE_F);
                ((uint32_t*)hC)[((size_t)r0 * N2 + col) >> 1] = w0;
                ((uint32_t*)hC)[((size_t)(r0 + 8) * N2 + col) >> 1] = w1;
            } else if (MODE == 2) {
                *(float2*)(&C[(size_t)r0 * N2 + col]) = v0;
                *(float2*)(&C[(size_t)(r0 + 8) * N2 + col]) = v1;
            } else {
                uint32_t w0 = packh2(v0.x, v0.y);
                uint32_t w1 = packh2(v1.x, v1.y);
                if (col < DD) {
                    ((uint32_t*)hK)[((size_t)r0 * DD + col) >> 1] = w0;
                    ((uint32_t*)hK)[((size_t)(r0 + 8) * DD + col) >> 1] = w1;
                } else {
                    ((uint32_t*)hV)[((size_t)r0 * DD + col - DD) >> 1] = w0;
                    ((uint32_t*)hV)[((size_t)(r0 + 8) * DD + col - DD) >> 1] = w1;
                }
            }
        }
    }
}

// ---------------- fused attention: interleaved S(h1) with PV(h0) ----------
#define ROWB   144
#define BUFB   (128 * ROWB)
#define ATTN_SMEM (5 * BUFB)

__global__ void __launch_bounds__(256, 2)
attn_k(const __half* __restrict__ qh, const __half* __restrict__ kh,
       const __half* __restrict__ vh, __half* __restrict__ oh) {
    extern __shared__ __align__(16) unsigned char smraw[];
    uint32_t s_q = smem_u32(smraw);
    uint32_t s_k = s_q + BUFB;
    uint32_t s_v = s_q + 3 * BUFB;

    int tid = threadIdx.x;
    int lane = tid & 31;
    int wid = tid >> 5;
    int gid = lane >> 2, tig = lane & 3;

    int bh = blockIdx.y;
    int b = bh >> 4;
    int h = bh & 15;
    int n0blk = blockIdx.x * 128;

    const __half* qbase = qh + ((size_t)(b * NN + n0blk)) * DD + h * HD;
    const __half* kbase = kh + (size_t)b * KCC * DD + h * HD;
    const __half* vbase = vh + (size_t)b * KCC * DD + h * HD;

    #pragma unroll
    for (int i = 0; i < 4; ++i) {
        int idx = tid + 256 * i;
        int row = idx >> 3;
        int c = idx & 7;
        uint4 t = *(const uint4*)(qbase + (size_t)row * DD + c * 8);
        *(uint4*)(smraw + row * ROWB + c * 16) = t;
    }
    #pragma unroll
    for (int i = 0; i < 4; ++i) {
        int idx = tid + 256 * i;
        int br = idx >> 2;
        int w  = idx & 3;
        *(uint32_t*)(smraw + 3 * BUFB + br * ROWB + 128 + w * 4) =
            (w == 0) ? 0x00003C00u : 0u;
    }

    int m0 = wid * 16;
    uint32_t qa = s_q + (uint32_t)((m0 + ((lane >> 3) & 1) * 8 + (lane & 7)) * ROWB
                                   + (lane >> 4) * 16);
    uint32_t ka_off = (uint32_t)(((lane & 7) + (lane >> 4) * 8) * ROWB
                                 + ((lane >> 3) & 1) * 16);
    uint32_t va_off = (uint32_t)((((lane >> 3) & 1) * 8 + (lane & 7)) * ROWB
                                 + (lane >> 4) * 16);
    uint32_t vs_off = (uint32_t)((lane & 15) * ROWB + 128);

    int crow = tid >> 1;
    int cg   = tid & 1;
    const __half* ksrc0 = kbase + (size_t)crow * DD + cg * 32;
    const __half* vsrc0 = vbase + (size_t)crow * DD + cg * 32;
    uint32_t kdst0 = s_k + crow * ROWB + cg * 64;
    uint32_t vdst0 = s_v + crow * ROWB + cg * 64;

    {
        #pragma unroll
        for (int j = 0; j < 4; ++j) {
            CPA16(kdst0 + j * 16, ksrc0 + j * 8);
            CPA16(vdst0 + j * 16, vsrc0 + j * 8);
        }
        CPCOMMIT();
    }

    float oAcc[8][4];
    #pragma unroll
    for (int nt = 0; nt < 8; ++nt)
        #pragma unroll
        for (int r = 0; r < 4; ++r) oAcc[nt][r] = 0.0f;
    float oSum[4] = {0.0f, 0.0f, 0.0f, 0.0f};

    const uint32_t NEG10 = 0xC900C900u, POS10 = 0x49004900u;
    const uint32_t L2E2 = packh2(1.4426950f, 1.4426950f);
    const uint32_t OFF2 = packh2(0.5730496f, 0.5730496f);

    for (int c = 0; c < KCC / 128; ++c) {
        if (c + 1 < KCC / 128) {
            int nb = (c + 1) & 1;
            const __half* ks = ksrc0 + (size_t)(c + 1) * 128 * DD;
            const __half* vs = vsrc0 + (size_t)(c + 1) * 128 * DD;
            #pragma unroll
            for (int j = 0; j < 4; ++j) {
                CPA16(kdst0 + nb * BUFB + j * 16, ks + j * 8);
                CPA16(vdst0 + nb * BUFB + j * 16, vs + j * 8);
            }
            CPCOMMIT();
            CPWAIT(1);
        } else {
            CPWAIT(0);
        }
        __syncthreads();

        uint32_t bo = (c & 1) * BUFB;

        // ---- S half 0 (keys 0..63) ----
        float sAcc[8][4];
        #pragma unroll
        for (int nt = 0; nt < 8; ++nt)
            #pragma unroll
            for (int r = 0; r < 4; ++r) sAcc[nt][r] = 0.0f;

        #pragma unroll
        for (int ks = 0; ks < 4; ++ks) {
            uint32_t a0, a1, a2, a3;
            LDSM4(a0, a1, a2, a3, qa + ks * 32);
            uint32_t af[4] = {a0, a1, a2, a3};
            #pragma unroll
            for (int ntp = 0; ntp < 4; ++ntp) {
                uint32_t b0, b1, b2, b3;
                LDSM4(b0, b1, b2, b3,
                      s_k + bo + ka_off + (ntp * 16) * ROWB + ks * 32);
                mma16h(sAcc[2 * ntp], af, b0, b1);
                mma16h(sAcc[2 * ntp + 1], af, b2, b3);
            }
        }

        // ---- exp half 0 -> pa ----
        uint32_t pa[4][4];
        #pragma unroll
        for (int nt = 0; nt < 8; ++nt) {
            uint32_t lo = packh2(sAcc[nt][0], sAcc[nt][1]);
            uint32_t hi = packh2(sAcc[nt][2], sAcc[nt][3]);
            lo = h2ex2(h2fma(h2min(h2max(lo, NEG10), POS10), L2E2, OFF2));
            hi = h2ex2(h2fma(h2min(h2max(hi, NEG10), POS10), L2E2, OFF2));
            int kp = nt >> 1, s = (nt & 1) << 1;
            pa[kp][s + 0] = lo;
            pa[kp][s + 1] = hi;
        }

        // ---- interleaved: PV half 0 + S half 1 ----
        float sAcc2[8][4];
        #pragma unroll
        for (int nt = 0; nt < 8; ++nt)
            #pragma unroll
            for (int r = 0; r < 4; ++r) sAcc2[nt][r] = 0.0f;

        #pragma unroll
        for (int kp = 0; kp < 4; ++kp) {
            // PV half 0, key group kp
            uint32_t vrow = s_v + bo + (kp * 16) * ROWB;
            #pragma unroll
            for (int ntp = 0; ntp < 4; ++ntp) {
                uint32_t b0, b1, b2, b3;
                LDSM4T(b0, b1, b2, b3, vrow + va_off + ntp * 32);
                mma16h(oAcc[2 * ntp], pa[kp], b0, b1);
                mma16h(oAcc[2 * ntp + 1], pa[kp], b2, b3);
            }
            uint32_t c0, c1;
            LDSM2T(c0, c1, vrow + vs_off);
            mma16h(oSum, pa[kp], c0, c1);

            // S half 1, k-step kp (keys 64..127)
            uint32_t a0, a1, a2, a3;
            LDSM4(a0, a1, a2, a3, qa + kp * 32);
            uint32_t af[4] = {a0, a1, a2, a3};
            #pragma unroll
            for (int ntp = 0; ntp < 4; ++ntp) {
                uint32_t b0, b1, b2, b3;
                LDSM4(b0, b1, b2, b3,
                      s_k + bo + ka_off + ((64 + ntp * 16)) * ROWB + kp * 32);
                mma16h(sAcc2[2 * ntp], af, b0, b1);
                mma16h(sAcc2[2 * ntp + 1], af, b2, b3);
            }
        }

        // ---- exp half 1 -> pa ----
        #pragma unroll
        for (int nt = 0; nt < 8; ++nt) {
            uint32_t lo = packh2(sAcc2[nt][0], sAcc2[nt][1]);
            uint32_t hi = packh2(sAcc2[nt][2], sAcc2[nt][3]);
            lo = h2ex2(h2fma(h2min(h2max(lo, NEG10), POS10), L2E2, OFF2));
            hi = h2ex2(h2fma(h2min(h2max(hi, NEG10), POS10), L2E2, OFF2));
            int kp = nt >> 1, s = (nt & 1) << 1;
            pa[kp][s + 0] = lo;
            pa[kp][s + 1] = hi;
        }

        // ---- PV half 1 ----
        #pragma unroll
        for (int kp = 0; kp < 4; ++kp) {
            uint32_t vrow = s_v + bo + ((64 + kp * 16)) * ROWB;
            #pragma unroll
            for (int ntp = 0; ntp < 4; ++ntp) {
                uint32_t b0, b1, b2, b3;
                LDSM4T(b0, b1, b2, b3, vrow + va_off + ntp * 32);
                mma16h(oAcc[2 * ntp], pa[kp], b0, b1);
                mma16h(oAcc[2 * ntp + 1], pa[kp], b2, b3);
            }
            uint32_t c0, c1;
            LDSM2T(c0, c1, vrow + vs_off);
            mma16h(oSum, pa[kp], c0, c1);
        }

        __syncthreads();
    }

    float rs0 = __shfl_sync(0xffffffffu, oSum[0], lane & ~3);
    float rs1 = __shfl_sync(0xffffffffu, oSum[2], lane & ~3);
    float inv0 = 1.0f / rs0;
    float inv1 = 1.0f / rs1;

    int row0 = n0blk + m0 + gid;
    #pragma unroll
    for (int nt = 0; nt < 8; ++nt) {
        int dv = nt * 8 + 2 * tig;
        uint32_t w0 = packh2(oAcc[nt][0] * inv0, oAcc[nt][1] * inv0);
        uint32_t w1 = packh2(oAcc[nt][2] * inv1, oAcc[nt][3] * inv1);
        *(uint32_t*)(&oh[((size_t)(b * NN + row0)) * DD + h * HD + dv]) = w0;
        *(uint32_t*)(&oh[((size_t)(b * NN + row0 + 8)) * DD + h * HD + dv]) = w1;
    }
}

// ---------------- tail ----------------
__global__ void tail_k(float* __restrict__ dst) {
    dst[0] = 1.0f / (float)KCC;
}

// ---------------- launch ----------------
extern "C" void kernel_launch(void* const* d_in, const int* in_sizes, int n_in,
                              void* d_out, int out_size) {
    const float* x      = (const float*)d_in[0];
    const float* ctx    = (const float*)d_in[1];
    const float* q_w    = (const float*)d_in[2];
    const float* q_b    = (const float*)d_in[3];
    const float* kv_w   = (const float*)d_in[4];
    const float* kv_b   = (const float*)d_in[5];
    const float* proj_w = (const float*)d_in[6];
    const float* proj_b = (const float*)d_in[7];
    float* out = (float*)d_out;

    __half *xh, *ctxnh, *qwh, *kvwh, *pwh, *qhp, *khp, *vhp, *aoh;
    cudaGetSymbolAddress((void**)&xh,    g_xh);
    cudaGetSymbolAddress((void**)&ctxnh, g_ctxnh);
    cudaGetSymbolAddress((void**)&qwh,   g_qwh);
    cudaGetSymbolAddress((void**)&kvwh,  g_kvwh);
    cudaGetSymbolAddress((void**)&pwh,   g_pwh);
    cudaGetSymbolAddress((void**)&qhp,   g_qh);
    cudaGetSymbolAddress((void**)&khp,   g_kh);
    cudaGetSymbolAddress((void**)&vhp,   g_vh);
    cudaGetSymbolAddress((void**)&aoh,   g_aoh);

    cudaFuncSetAttribute(gemm_h<0>, cudaFuncAttributeMaxDynamicSharedMemorySize, GEMM_SMEM);
    cudaFuncSetAttribute(gemm_h<1>, cudaFuncAttributeMaxDynamicSharedMemorySize, GEMM_SMEM);
    cudaFuncSetAttribute(gemm_h<2>, cudaFuncAttributeMaxDynamicSharedMemorySize, GEMM_SMEM);
    cudaFuncSetAttribute(attn_k,    cudaFuncAttributeMaxDynamicSharedMemorySize, ATTN_SMEM);

    f2h_k<<<(BB * NN * DD / 8 + 255) / 256, 256>>>(x, xh, BB * NN * DD);
    f2h_k<<<(DD * DD / 8 + 255) / 256, 256>>>(q_w, qwh, DD * DD);
    f2h_k<<<(DD * 2 * DD / 8 + 255) / 256, 256>>>(kv_w, kvwh, DD * 2 * DD);
    f2h_k<<<(DD * DD / 8 + 255) / 256, 256>>>(proj_w, pwh, DD * DD);

    rmsnorm_k<<<BB * KCC, 256>>>(ctx, ctxnh);

    dim3 gq(DD / 256, (BB * NN) / 128);
    gemm_h<0><<<gq, 256, GEMM_SMEM>>>(xh, qwh, q_b, nullptr, BB * NN, DD, DD, qhp, nullptr, nullptr);

    dim3 gkv((2 * DD) / 256, (BB * KCC) / 128);
    gemm_h<1><<<gkv, 256, GEMM_SMEM>>>(ctxnh, kvwh, kv_b, nullptr, BB * KCC, 2 * DD, DD, nullptr, khp, vhp);

    dim3 ga(NN / 128, BB * HH);
    attn_k<<<ga, 256, ATTN_SMEM>>>(qhp, khp, vhp, aoh);

    dim3 gp(DD / 256, (BB * NN) / 128);
    gemm_h<2><<<gp, 256, GEMM_SMEM>>>(aoh, pwh, proj_b, out, BB * NN, DD, DD, nullptr, nullptr, nullptr);

    if (out_size > BB * NN * DD) {
        tail_k<<<1, 1>>>(out + (size_t)BB * NN * DD);
    }
}

// round 15
// speedup vs baseline: 2.5859x; 1.0828x over previous
#include <cuda_runtime.h>
#include <cuda_fp16.h>
#include <math.h>
#include <stdint.h>

#define BB   4
#define NN   2048
#define KCC  2048
#define DD   1024
#define HH   16
#define HD   64
#define SCALE_F 0.125f
#define EPS_F   1e-6f

// ---------------- scratch ----------------
__device__ __half g_xh  [BB * NN  * DD];
__device__ __half g_ctxnh[BB * KCC * DD];
__device__ __half g_qwh [DD * DD];
__device__ __half g_kvwh[DD * 2 * DD];
__device__ __half g_pwh [DD * DD];
__device__ __half g_qh  [BB * NN  * DD];
__device__ __half g_kh  [BB * KCC * DD];
__device__ __half g_vh  [BB * KCC * DD];
__device__ __half g_aoh [BB * NN  * DD];

// ---------------- helpers ----------------
__device__ __forceinline__ uint32_t packh2(float a, float b) {
    uint32_t r;
    asm("cvt.rn.f16x2.f32 %0, %2, %1;" : "=r"(r) : "f"(a), "f"(b));
    return r;
}
__device__ __forceinline__ void mma16h(float* c, const uint32_t* a, uint32_t b0, uint32_t b1) {
    asm volatile(
        "mma.sync.aligned.m16n8k16.row.col.f32.f16.f16.f32 "
        "{%0,%1,%2,%3}, {%4,%5,%6,%7}, {%8,%9}, {%0,%1,%2,%3};"
        : "+f"(c[0]), "+f"(c[1]), "+f"(c[2]), "+f"(c[3])
        : "r"(a[0]), "r"(a[1]), "r"(a[2]), "r"(a[3]), "r"(b0), "r"(b1));
}
__device__ __forceinline__ uint32_t smem_u32(const void* p) {
    return (uint32_t)__cvta_generic_to_shared(p);
}
#define LDSM4(r0,r1,r2,r3,addr) \
    asm volatile("ldmatrix.sync.aligned.m8n8.x4.shared.b16 {%0,%1,%2,%3},[%4];" \
        : "=r"(r0),"=r"(r1),"=r"(r2),"=r"(r3) : "r"(addr))
#define LDSM4T(r0,r1,r2,r3,addr) \
    asm volatile("ldmatrix.sync.aligned.m8n8.x4.trans.shared.b16 {%0,%1,%2,%3},[%4];" \
        : "=r"(r0),"=r"(r1),"=r"(r2),"=r"(r3) : "r"(addr))
#define LDSM2T(r0,r1,addr) \
    asm volatile("ldmatrix.sync.aligned.m8n8.x2.trans.shared.b16 {%0,%1},[%2];" \
        : "=r"(r0),"=r"(r1) : "r"(addr))
#define CPA16(dst,src) \
    asm volatile("cp.async.cg.shared.global [%0],[%1],16;" :: "r"(dst),"l"(src))
#define CPCOMMIT() asm volatile("cp.async.commit_group;")
#define CPWAIT(n)  asm volatile("cp.async.wait_group %0;" :: "n"(n))

__device__ __forceinline__ uint32_t h2max(uint32_t a, uint32_t b) {
    uint32_t r; asm("max.f16x2 %0,%1,%2;" : "=r"(r) : "r"(a), "r"(b)); return r;
}
__device__ __forceinline__ uint32_t h2min(uint32_t a, uint32_t b) {
    uint32_t r; asm("min.f16x2 %0,%1,%2;" : "=r"(r) : "r"(a), "r"(b)); return r;
}
__device__ __forceinline__ uint32_t h2fma(uint32_t a, uint32_t b, uint32_t c) {
    uint32_t r; asm("fma.rn.f16x2 %0,%1,%2,%3;" : "=r"(r) : "r"(a), "r"(b), "r"(c)); return r;
}
__device__ __forceinline__ uint32_t h2ex2(uint32_t a) {
    uint32_t r; asm("ex2.approx.f16x2 %0,%1;" : "=r"(r) : "r"(a)); return r;
}

// ---------------- fp32 -> fp16 convert ----------------
__global__ void f2h_k(const float* __restrict__ s, __half* __restrict__ d, int n) {
    int i = (blockIdx.x * blockDim.x + threadIdx.x) * 8;
    if (i < n) {
        float4 a = *(const float4*)(s + i);
        float4 b = *(const float4*)(s + i + 4);
        uint4 w;
        w.x = packh2(a.x, a.y); w.y = packh2(a.z, a.w);
        w.z = packh2(b.x, b.y); w.w = packh2(b.z, b.w);
        *(uint4*)(d + i) = w;
    }
}

// ---------------- rms norm (fp16 out) ----------------
__global__ void rmsnorm_k(const float* __restrict__ ctx, __half* __restrict__ o) {
    int row = blockIdx.x;
    const float4* p = reinterpret_cast<const float4*>(ctx + (size_t)row * DD);
    float4 v = p[threadIdx.x];
    float ss = v.x * v.x + v.y * v.y + v.z * v.z + v.w * v.w;
    __shared__ float red[8];
    #pragma unroll
    for (int off = 16; off; off >>= 1) ss += __shfl_xor_sync(0xffffffffu, ss, off);
    if ((threadIdx.x & 31) == 0) red[threadIdx.x >> 5] = ss;
    __syncthreads();
    if (threadIdx.x < 32) {
        float t = (threadIdx.x < 8) ? red[threadIdx.x] : 0.0f;
        #pragma unroll
        for (int off = 4; off; off >>= 1) t += __shfl_xor_sync(0xffffffffu, t, off);
        if (threadIdx.x == 0) red[0] = t;
    }
    __syncthreads();
    float r = 1.0f / sqrtf(red[0] * (1.0f / DD) + EPS_F);
    uint2 w;
    w.x = packh2(v.x * r, v.y * r);
    w.y = packh2(v.z * r, v.w * r);
    *(uint2*)(o + (size_t)row * DD + threadIdx.x * 4) = w;
}

// ---------------- fp16 GEMM: 128x128 tile, 32x64 warp tile, 2 CTA/SM ------
#define ARB 80
#define BRB 272
#define ABUF (128 * ARB)
#define BBUF (32 * BRB)
#define GEMM_SMEM (2 * ABUF + 2 * BBUF)

template <int MODE>
__global__ void __launch_bounds__(256, 2)
gemm_h(const __half* __restrict__ A, const __half* __restrict__ W,
       const float* __restrict__ bias, float* __restrict__ C,
       int M2, int N2, int K2,
       __half* __restrict__ hC, __half* __restrict__ hK, __half* __restrict__ hV) {
    extern __shared__ __align__(16) unsigned char sm[];
    uint32_t s_a = smem_u32(sm);
    uint32_t s_b = s_a + 2 * ABUF;

    int tid = threadIdx.x;
    int lane = tid & 31;
    int wid = tid >> 5;
    int gid = lane >> 2, tig = lane & 3;
    int warpm = wid & 3, warpn = wid >> 2;     // 4 x 2 warps, 32 x 64 tiles
    int rowBase = blockIdx.y * 128, colBase = blockIdx.x * 128;

    const __half* Abase = A + (size_t)rowBase * K2;
    const __half* Wbase = W + colBase;

    // A: 128 rows x 32 halves = 512 16B-chunks; B: 32 rows x 128 halves = 512 chunks
    int ar0 = tid >> 2, ac0 = tid & 3;
    int ar1 = (tid + 256) >> 2, ac1 = tid & 3;
    int br0 = tid >> 4, bc0 = tid & 15;
    int br1 = (tid + 256) >> 4, bc1 = tid & 15;
    uint32_t a_off = (uint32_t)((((lane >> 3) & 1) * 8 + (lane & 7)) * ARB + (lane >> 4) * 16);
    uint32_t b_off = (uint32_t)((((lane >> 3) & 1) * 8 + (lane & 7)) * BRB + (lane >> 4) * 16);

    {
        CPA16(s_a + ar0 * ARB + ac0 * 16, Abase + (size_t)ar0 * K2 + ac0 * 8);
        CPA16(s_a + ar1 * ARB + ac1 * 16, Abase + (size_t)ar1 * K2 + ac1 * 8);
        CPA16(s_b + br0 * BRB + bc0 * 16, Wbase + (size_t)br0 * N2 + bc0 * 8);
        CPA16(s_b + br1 * BRB + bc1 * 16, Wbase + (size_t)br1 * N2 + bc1 * 8);
        CPCOMMIT();
    }

    float acc[2][8][4];
    #pragma unroll
    for (int mt = 0; mt < 2; ++mt)
        #pragma unroll
        for (int nt = 0; nt < 8; ++nt)
            #pragma unroll
            for (int r = 0; r < 4; ++r) acc[mt][nt][r] = 0.0f;

    int nT = K2 >> 5;
    for (int t = 0; t < nT; ++t) {
        if (t + 1 < nT) {
            int nb = (t + 1) & 1;
            const __half* As2 = Abase + (t + 1) * 32;
            const __half* Ws2 = Wbase + (size_t)(t + 1) * 32 * N2;
            CPA16(s_a + nb * ABUF + ar0 * ARB + ac0 * 16, As2 + (size_t)ar0 * K2 + ac0 * 8);
            CPA16(s_a + nb * ABUF + ar1 * ARB + ac1 * 16, As2 + (size_t)ar1 * K2 + ac1 * 8);
            CPA16(s_b + nb * BBUF + br0 * BRB + bc0 * 16, Ws2 + (size_t)br0 * N2 + bc0 * 8);
            CPA16(s_b + nb * BBUF + br1 * BRB + bc1 * 16, Ws2 + (size_t)br1 * N2 + bc1 * 8);
            CPCOMMIT();
            CPWAIT(1);
        } else {
            CPWAIT(0);
        }
        __syncthreads();

        uint32_t ab = s_a + (t & 1) * ABUF;
        uint32_t bb = s_b + (t & 1) * BBUF;
        #pragma unroll
        for (int ks = 0; ks < 2; ++ks) {
            uint32_t af[2][4];
            #pragma unroll
            for (int mt = 0; mt < 2; ++mt)
                LDSM4(af[mt][0], af[mt][1], af[mt][2], af[mt][3],
                      ab + a_off + (warpm * 32 + mt * 16) * ARB + ks * 32);
            #pragma unroll
            for (int ntp = 0; ntp < 4; ++ntp) {
                uint32_t b0, b1, b2, b3;
                LDSM4T(b0, b1, b2, b3,
                       bb + b_off + (ks * 16) * BRB + warpn * 128 + ntp * 32);
                #pragma unroll
                for (int mt = 0; mt < 2; ++mt) {
                    mma16h(acc[mt][2 * ntp], af[mt], b0, b1);
                    mma16h(acc[mt][2 * ntp + 1], af[mt], b2, b3);
                }
            }
        }
        __syncthreads();
    }

    #pragma unroll
    for (int mt = 0; mt < 2; ++mt) {
        int r0 = rowBase + warpm * 32 + mt * 16 + gid;
        #pragma unroll
        for (int nt = 0; nt < 8; ++nt) {
            int col = colBase + warpn * 64 + nt * 8 + tig * 2;
            float2 bb2 = *(const float2*)(bias + col);
            float2 v0, v1;
            v0.x = acc[mt][nt][0] + bb2.x; v0.y = acc[mt][nt][1] + bb2.y;
            v1.x = acc[mt][nt][2] + bb2.x; v1.y = acc[mt][nt][3] + bb2.y;
            if (MODE == 0) {
                uint32_t w0 = packh2(v0.x * SCALE_F, v0.y * SCALE_F);
                uint32_t w1 = packh2(v1.x * SCALE_F, v1.y * SCALE_F);
                ((uint32_t*)hC)[((size_t)r0 * N2 + col) >> 1] = w0;
                ((uint32_t*)hC)[((size_t)(r0 + 8) * N2 + col) >> 1] = w1;
            } else if (MODE == 2) {
                *(float2*)(&C[(size_t)r0 * N2 + col]) = v0;
                *(float2*)(&C[(size_t)(r0 + 8) * N2 + col]) = v1;
            } else {
                uint32_t w0 = packh2(v0.x, v0.y);
                uint32_t w1 = packh2(v1.x, v1.y);
                if (col < DD) {
                    ((uint32_t*)hK)[((size_t)r0 * DD + col) >> 1] = w0;
                    ((uint32_t*)hK)[((size_t)(r0 + 8) * DD + col) >> 1] = w1;
                } else {
                    ((uint32_t*)hV)[((size_t)r0 * DD + col - DD) >> 1] = w0;
                    ((uint32_t*)hV)[((size_t)(r0 + 8) * DD + col - DD) >> 1] = w1;
                }
            }
        }
    }
}

// ---------------- fused attention (R14, passing) --------------------------
#define ROWB   144
#define BUFB   (128 * ROWB)
#define ATTN_SMEM (5 * BUFB)

__global__ void __launch_bounds__(256, 2)
attn_k(const __half* __restrict__ qh, const __half* __restrict__ kh,
       const __half* __restrict__ vh, __half* __restrict__ oh) {
    extern __shared__ __align__(16) unsigned char smraw[];
    uint32_t s_q = smem_u32(smraw);
    uint32_t s_k = s_q + BUFB;
    uint32_t s_v = s_q + 3 * BUFB;

    int tid = threadIdx.x;
    int lane = tid & 31;
    int wid = tid >> 5;
    int gid = lane >> 2, tig = lane & 3;

    int bh = blockIdx.y;
    int b = bh >> 4;
    int h = bh & 15;
    int n0blk = blockIdx.x * 128;

    const __half* qbase = qh + ((size_t)(b * NN + n0blk)) * DD + h * HD;
    const __half* kbase = kh + (size_t)b * KCC * DD + h * HD;
    const __half* vbase = vh + (size_t)b * KCC * DD + h * HD;

    #pragma unroll
    for (int i = 0; i < 4; ++i) {
        int idx = tid + 256 * i;
        int row = idx >> 3;
        int c = idx & 7;
        uint4 t = *(const uint4*)(qbase + (size_t)row * DD + c * 8);
        *(uint4*)(smraw + row * ROWB + c * 16) = t;
    }
    #pragma unroll
    for (int i = 0; i < 4; ++i) {
        int idx = tid + 256 * i;
        int br = idx >> 2;
        int w  = idx & 3;
        *(uint32_t*)(smraw + 3 * BUFB + br * ROWB + 128 + w * 4) =
            (w == 0) ? 0x00003C00u : 0u;
    }

    int m0 = wid * 16;
    uint32_t qa = s_q + (uint32_t)((m0 + ((lane >> 3) & 1) * 8 + (lane & 7)) * ROWB
                                   + (lane >> 4) * 16);
    uint32_t ka_off = (uint32_t)(((lane & 7) + (lane >> 4) * 8) * ROWB
                                 + ((lane >> 3) & 1) * 16);
    uint32_t va_off = (uint32_t)((((lane >> 3) & 1) * 8 + (lane & 7)) * ROWB
                                 + (lane >> 4) * 16);
    uint32_t vs_off = (uint32_t)((lane & 15) * ROWB + 128);

    int crow = tid >> 1;
    int cg   = tid & 1;
    const __half* ksrc0 = kbase + (size_t)crow * DD + cg * 32;
    const __half* vsrc0 = vbase + (size_t)crow * DD + cg * 32;
    uint32_t kdst0 = s_k + crow * ROWB + cg * 64;
    uint32_t vdst0 = s_v + crow * ROWB + cg * 64;

    {
        #pragma unroll
        for (int j = 0; j < 4; ++j) {
            CPA16(kdst0 + j * 16, ksrc0 + j * 8);
            CPA16(vdst0 + j * 16, vsrc0 + j * 8);
        }
        CPCOMMIT();
    }

    float oAcc[8][4];
    #pragma unroll
    for (int nt = 0; nt < 8; ++nt)
        #pragma unroll
        for (int r = 0; r < 4; ++r) oAcc[nt][r] = 0.0f;
    float oSum[4] = {0.0f, 0.0f, 0.0f, 0.0f};

    const uint32_t NEG10 = 0xC900C900u, POS10 = 0x49004900u;
    const uint32_t L2E2 = packh2(1.4426950f, 1.4426950f);
    const uint32_t OFF2 = packh2(0.5730496f, 0.5730496f);

    for (int c = 0; c < KCC / 128; ++c) {
        if (c + 1 < KCC / 128) {
            int nb = (c + 1) & 1;
            const __half* ks = ksrc0 + (size_t)(c + 1) * 128 * DD;
            const __half* vs = vsrc0 + (size_t)(c + 1) * 128 * DD;
            #pragma unroll
            for (int j = 0; j < 4; ++j) {
                CPA16(kdst0 + nb * BUFB + j * 16, ks + j * 8);
                CPA16(vdst0 + nb * BUFB + j * 16, vs + j * 8);
            }
            CPCOMMIT();
            CPWAIT(1);
        } else {
            CPWAIT(0);
        }
        __syncthreads();

        uint32_t bo = (c & 1) * BUFB;

        float sAcc[8][4];
        #pragma unroll
        for (int nt = 0; nt < 8; ++nt)
            #pragma unroll
            for (int r = 0; r < 4; ++r) sAcc[nt][r] = 0.0f;

        #pragma unroll
        for (int ks = 0; ks < 4; ++ks) {
            uint32_t a0, a1, a2, a3;
            LDSM4(a0, a1, a2, a3, qa + ks * 32);
            uint32_t af[4] = {a0, a1, a2, a3};
            #pragma unroll
            for (int ntp = 0; ntp < 4; ++ntp) {
                uint32_t b0, b1, b2, b3;
                LDSM4(b0, b1, b2, b3,
                      s_k + bo + ka_off + (ntp * 16) * ROWB + ks * 32);
                mma16h(sAcc[2 * ntp], af, b0, b1);
                mma16h(sAcc[2 * ntp + 1], af, b2, b3);
            }
        }

        uint32_t pa[4][4];
        #pragma unroll
        for (int nt = 0; nt < 8; ++nt) {
            uint32_t lo = packh2(sAcc[nt][0], sAcc[nt][1]);
            uint32_t hi = packh2(sAcc[nt][2], sAcc[nt][3]);
            lo = h2ex2(h2fma(h2min(h2max(lo, NEG10), POS10), L2E2, OFF2));
            hi = h2ex2(h2fma(h2min(h2max(hi, NEG10), POS10), L2E2, OFF2));
            int kp = nt >> 1, s = (nt & 1) << 1;
            pa[kp][s + 0] = lo;
            pa[kp][s + 1] = hi;
        }

        float sAcc2[8][4];
        #pragma unroll
        for (int nt = 0; nt < 8; ++nt)
            #pragma unroll
            for (int r = 0; r < 4; ++r) sAcc2[nt][r] = 0.0f;

        #pragma unroll
        for (int kp = 0; kp < 4; ++kp) {
            uint32_t vrow = s_v + bo + (kp * 16) * ROWB;
            #pragma unroll
            for (int ntp = 0; ntp < 4; ++ntp) {
                uint32_t b0, b1, b2, b3;
                LDSM4T(b0, b1, b2, b3, vrow + va_off + ntp * 32);
                mma16h(oAcc[2 * ntp], pa[kp], b0, b1);
                mma16h(oAcc[2 * ntp + 1], pa[kp], b2, b3);
            }
            uint32_t c0, c1;
            LDSM2T(c0, c1, vrow + vs_off);
            mma16h(oSum, pa[kp], c0, c1);

            uint32_t a0, a1, a2, a3;
            LDSM4(a0, a1, a2, a3, qa + kp * 32);
            uint32_t af[4] = {a0, a1, a2, a3};
            #pragma unroll
            for (int ntp = 0; ntp < 4; ++ntp) {
                uint32_t b0, b1, b2, b3;
                LDSM4(b0, b1, b2, b3,
                      s_k + bo + ka_off + ((64 + ntp * 16)) * ROWB + kp * 32);
                mma16h(sAcc2[2 * ntp], af, b0, b1);
                mma16h(sAcc2[2 * ntp + 1], af, b2, b3);
            }
        }

        #pragma unroll
        for (int nt = 0; nt < 8; ++nt) {
            uint32_t lo = packh2(sAcc2[nt][0], sAcc2[nt][1]);
            uint32_t hi = packh2(sAcc2[nt][2], sAcc2[nt][3]);
            lo = h2ex2(h2fma(h2min(h2max(lo, NEG10), POS10), L2E2, OFF2));
            hi = h2ex2(h2fma(h2min(h2max(hi, NEG10), POS10), L2E2, OFF2));
            int kp = nt >> 1, s = (nt & 1) << 1;
            pa[kp][s + 0] = lo;
            pa[kp][s + 1] = hi;
        }

        #pragma unroll
        for (int kp = 0; kp < 4; ++kp) {
            uint32_t vrow = s_v + bo + ((64 + kp * 16)) * ROWB;
            #pragma unroll
            for (int ntp = 0; ntp < 4; ++ntp) {
                uint32_t b0, b1, b2, b3;
                LDSM4T(b0, b1, b2, b3, vrow + va_off + ntp * 32);
                mma16h(oAcc[2 * ntp], pa[kp], b0, b1);
                mma16h(oAcc[2 * ntp + 1], pa[kp], b2, b3);
            }
            uint32_t c0, c1;
            LDSM2T(c0, c1, vrow + vs_off);
            mma16h(oSum, pa[kp], c0, c1);
        }

        __syncthreads();
    }

    float rs0 = __shfl_sync(0xffffffffu, oSum[0], lane & ~3);
    float rs1 = __shfl_sync(0xffffffffu, oSum[2], lane & ~3);
    float inv0 = 1.0f / rs0;
    float inv1 = 1.0f / rs1;

    int row0 = n0blk + m0 + gid;
    #pragma unroll
    for (int nt = 0; nt < 8; ++nt) {
        int dv = nt * 8 + 2 * tig;
        uint32_t w0 = packh2(oAcc[nt][0] * inv0, oAcc[nt][1] * inv0);
        uint32_t w1 = packh2(oAcc[nt][2] * inv1, oAcc[nt][3] * inv1);
        *(uint32_t*)(&oh[((size_t)(b * NN + row0)) * DD + h * HD + dv]) = w0;
        *(uint32_t*)(&oh[((size_t)(b * NN + row0 + 8)) * DD + h * HD + dv]) = w1;
    }
}

// ---------------- tail ----------------
__global__ void tail_k(float* __restrict__ dst) {
    dst[0] = 1.0f / (float)KCC;
}

// ---------------- launch ----------------
extern "C" void kernel_launch(void* const* d_in, const int* in_sizes, int n_in,
                              void* d_out, int out_size) {
    const float* x      = (const float*)d_in[0];
    const float* ctx    = (const float*)d_in[1];
    const float* q_w    = (const float*)d_in[2];
    const float* q_b    = (const float*)d_in[3];
    const float* kv_w   = (const float*)d_in[4];
    const float* kv_b   = (const float*)d_in[5];
    const float* proj_w = (const float*)d_in[6];
    const float* proj_b = (const float*)d_in[7];
    float* out = (float*)d_out;

    __half *xh, *ctxnh, *qwh, *kvwh, *pwh, *qhp, *khp, *vhp, *aoh;
    cudaGetSymbolAddress((void**)&xh,    g_xh);
    cudaGetSymbolAddress((void**)&ctxnh, g_ctxnh);
    cudaGetSymbolAddress((void**)&qwh,   g_qwh);
    cudaGetSymbolAddress((void**)&kvwh,  g_kvwh);
    cudaGetSymbolAddress((void**)&pwh,   g_pwh);
    cudaGetSymbolAddress((void**)&qhp,   g_qh);
    cudaGetSymbolAddress((void**)&khp,   g_kh);
    cudaGetSymbolAddress((void**)&vhp,   g_vh);
    cudaGetSymbolAddress((void**)&aoh,   g_aoh);

    cudaFuncSetAttribute(gemm_h<0>, cudaFuncAttributeMaxDynamicSharedMemorySize, GEMM_SMEM);
    cudaFuncSetAttribute(gemm_h<1>, cudaFuncAttributeMaxDynamicSharedMemorySize, GEMM_SMEM);
    cudaFuncSetAttribute(gemm_h<2>, cudaFuncAttributeMaxDynamicSharedMemorySize, GEMM_SMEM);
    cudaFuncSetAttribute(attn_k,    cudaFuncAttributeMaxDynamicSharedMemorySize, ATTN_SMEM);

    f2h_k<<<(BB * NN * DD / 8 + 255) / 256, 256>>>(x, xh, BB * NN * DD);
    f2h_k<<<(DD * DD / 8 + 255) / 256, 256>>>(q_w, qwh, DD * DD);
    f2h_k<<<(DD * 2 * DD / 8 + 255) / 256, 256>>>(kv_w, kvwh, DD * 2 * DD);
    f2h_k<<<(DD * DD / 8 + 255) / 256, 256>>>(proj_w, pwh, DD * DD);

    rmsnorm_k<<<BB * KCC, 256>>>(ctx, ctxnh);

    dim3 gq(DD / 128, (BB * NN) / 128);
    gemm_h<0><<<gq, 256, GEMM_SMEM>>>(xh, qwh, q_b, nullptr, BB * NN, DD, DD, qhp, nullptr, nullptr);

    dim3 gkv((2 * DD) / 128, (BB * KCC) / 128);
    gemm_h<1><<<gkv, 256, GEMM_SMEM>>>(ctxnh, kvwh, kv_b, nullptr, BB * KCC, 2 * DD, DD, nullptr, khp, vhp);

    dim3 ga(NN / 128, BB * HH);
    attn_k<<<ga, 256, ATTN_SMEM>>>(qhp, khp, vhp, aoh);

    dim3 gp(DD / 128, (BB * NN) / 128);
    gemm_h<2><<<gp, 256, GEMM_SMEM>>>(aoh, pwh, proj_b, out, BB * NN, DD, DD, nullptr, nullptr, nullptr);

    if (out_size > BB * NN * DD) {
        tail_k<<<1, 1>>>(out + (size_t)BB * NN * DD);
    }
}

// round 16
// speedup vs baseline: 2.6200x; 1.0132x over previous
#include <cuda_runtime.h>
#include <cuda_fp16.h>
#include <math.h>
#include <stdint.h>

#define BB   4
#define NN   2048
#define KCC  2048
#define DD   1024
#define HH   16
#define HD   64
#define SCALE_F 0.125f
#define EPS_F   1e-6f

// ---------------- scratch ----------------
__device__ __half g_xh  [BB * NN  * DD];
__device__ __half g_ctxnh[BB * KCC * DD];
__device__ __half g_qwh [DD * DD];
__device__ __half g_kvwh[DD * 2 * DD];
__device__ __half g_pwh [DD * DD];
__device__ __half g_qh  [BB * NN  * DD];
__device__ __half g_kh  [BB * KCC * DD];
__device__ __half g_vh  [BB * KCC * DD];
__device__ __half g_aoh [BB * NN  * DD];

// ---------------- helpers ----------------
__device__ __forceinline__ uint32_t packh2(float a, float b) {
    uint32_t r;
    asm("cvt.rn.f16x2.f32 %0, %2, %1;" : "=r"(r) : "f"(a), "f"(b));
    return r;
}
__device__ __forceinline__ void mma16h(float* c, const uint32_t* a, uint32_t b0, uint32_t b1) {
    asm volatile(
        "mma.sync.aligned.m16n8k16.row.col.f32.f16.f16.f32 "
        "{%0,%1,%2,%3}, {%4,%5,%6,%7}, {%8,%9}, {%0,%1,%2,%3};"
        : "+f"(c[0]), "+f"(c[1]), "+f"(c[2]), "+f"(c[3])
        : "r"(a[0]), "r"(a[1]), "r"(a[2]), "r"(a[3]), "r"(b0), "r"(b1));
}
__device__ __forceinline__ uint32_t smem_u32(const void* p) {
    return (uint32_t)__cvta_generic_to_shared(p);
}
#define LDSM4(r0,r1,r2,r3,addr) \
    asm volatile("ldmatrix.sync.aligned.m8n8.x4.shared.b16 {%0,%1,%2,%3},[%4];" \
        : "=r"(r0),"=r"(r1),"=r"(r2),"=r"(r3) : "r"(addr))
#define LDSM4T(r0,r1,r2,r3,addr) \
    asm volatile("ldmatrix.sync.aligned.m8n8.x4.trans.shared.b16 {%0,%1,%2,%3},[%4];" \
        : "=r"(r0),"=r"(r1),"=r"(r2),"=r"(r3) : "r"(addr))
#define LDSM2T(r0,r1,addr) \
    asm volatile("ldmatrix.sync.aligned.m8n8.x2.trans.shared.b16 {%0,%1},[%2];" \
        : "=r"(r0),"=r"(r1) : "r"(addr))
#define CPA16(dst,src) \
    asm volatile("cp.async.cg.shared.global [%0],[%1],16;" :: "r"(dst),"l"(src))
#define CPCOMMIT() asm volatile("cp.async.commit_group;")
#define CPWAIT(n)  asm volatile("cp.async.wait_group %0;" :: "n"(n))

__device__ __forceinline__ uint32_t h2max(uint32_t a, uint32_t b) {
    uint32_t r; asm("max.f16x2 %0,%1,%2;" : "=r"(r) : "r"(a), "r"(b)); return r;
}
__device__ __forceinline__ uint32_t h2min(uint32_t a, uint32_t b) {
    uint32_t r; asm("min.f16x2 %0,%1,%2;" : "=r"(r) : "r"(a), "r"(b)); return r;
}
__device__ __forceinline__ uint32_t h2fma(uint32_t a, uint32_t b, uint32_t c) {
    uint32_t r; asm("fma.rn.f16x2 %0,%1,%2,%3;" : "=r"(r) : "r"(a), "r"(b), "r"(c)); return r;
}
__device__ __forceinline__ uint32_t h2ex2(uint32_t a) {
    uint32_t r; asm("ex2.approx.f16x2 %0,%1;" : "=r"(r) : "r"(a)); return r;
}

// ---------------- fp32 -> fp16 convert ----------------
__global__ void f2h_k(const float* __restrict__ s, __half* __restrict__ d, int n) {
    int i = (blockIdx.x * blockDim.x + threadIdx.x) * 8;
    if (i < n) {
        float4 a = *(const float4*)(s + i);
        float4 b = *(const float4*)(s + i + 4);
        uint4 w;
        w.x = packh2(a.x, a.y); w.y = packh2(a.z, a.w);
        w.z = packh2(b.x, b.y); w.w = packh2(b.z, b.w);
        *(uint4*)(d + i) = w;
    }
}

// ---------------- rms norm (fp16 out) ----------------
__global__ void rmsnorm_k(const float* __restrict__ ctx, __half* __restrict__ o) {
    int row = blockIdx.x;
    const float4* p = reinterpret_cast<const float4*>(ctx + (size_t)row * DD);
    float4 v = p[threadIdx.x];
    float ss = v.x * v.x + v.y * v.y + v.z * v.z + v.w * v.w;
    __shared__ float red[8];
    #pragma unroll
    for (int off = 16; off; off >>= 1) ss += __shfl_xor_sync(0xffffffffu, ss, off);
    if ((threadIdx.x & 31) == 0) red[threadIdx.x >> 5] = ss;
    __syncthreads();
    if (threadIdx.x < 32) {
        float t = (threadIdx.x < 8) ? red[threadIdx.x] : 0.0f;
        #pragma unroll
        for (int off = 4; off; off >>= 1) t += __shfl_xor_sync(0xffffffffu, t, off);
        if (threadIdx.x == 0) red[0] = t;
    }
    __syncthreads();
    float r = 1.0f / sqrtf(red[0] * (1.0f / DD) + EPS_F);
    uint2 w;
    w.x = packh2(v.x * r, v.y * r);
    w.y = packh2(v.z * r, v.w * r);
    *(uint2*)(o + (size_t)row * DD + threadIdx.x * 4) = w;
}

// ---------------- fp16 GEMM: 128x128 tile, 3-stage pipeline, 1 barrier ----
#define ARB 80
#define BRB 272
#define ABUF (128 * ARB)
#define BBUF (32 * BRB)
#define STGB (ABUF + BBUF)
#define GEMM_SMEM (3 * STGB)

template <int MODE>
__global__ void __launch_bounds__(256, 2)
gemm_h(const __half* __restrict__ A, const __half* __restrict__ W,
       const float* __restrict__ bias, float* __restrict__ C,
       int M2, int N2, int K2,
       __half* __restrict__ hC, __half* __restrict__ hK, __half* __restrict__ hV) {
    extern __shared__ __align__(16) unsigned char sm[];
    uint32_t s0 = smem_u32(sm);

    int tid = threadIdx.x;
    int lane = tid & 31;
    int wid = tid >> 5;
    int gid = lane >> 2, tig = lane & 3;
    int warpm = wid & 3, warpn = wid >> 2;     // 4 x 2 warps, 32 x 64 tiles
    int rowBase = blockIdx.y * 128, colBase = blockIdx.x * 128;

    const __half* Abase = A + (size_t)rowBase * K2;
    const __half* Wbase = W + colBase;

    int ar0 = tid >> 2, ac0 = tid & 3;
    int ar1 = (tid + 256) >> 2, ac1 = tid & 3;
    int br0 = tid >> 4, bc0 = tid & 15;
    int br1 = (tid + 256) >> 4, bc1 = tid & 15;
    uint32_t a_off = (uint32_t)((((lane >> 3) & 1) * 8 + (lane & 7)) * ARB + (lane >> 4) * 16);
    uint32_t b_off = (uint32_t)((((lane >> 3) & 1) * 8 + (lane & 7)) * BRB + (lane >> 4) * 16);

    auto load_tile = [&](int t, int buf) {
        uint32_t s_a = s0 + buf * STGB;
        uint32_t s_b = s_a + ABUF;
        const __half* As2 = Abase + t * 32;
        const __half* Ws2 = Wbase + (size_t)t * 32 * N2;
        CPA16(s_a + ar0 * ARB + ac0 * 16, As2 + (size_t)ar0 * K2 + ac0 * 8);
        CPA16(s_a + ar1 * ARB + ac1 * 16, As2 + (size_t)ar1 * K2 + ac1 * 8);
        CPA16(s_b + br0 * BRB + bc0 * 16, Ws2 + (size_t)br0 * N2 + bc0 * 8);
        CPA16(s_b + br1 * BRB + bc1 * 16, Ws2 + (size_t)br1 * N2 + bc1 * 8);
        CPCOMMIT();
    };

    load_tile(0, 0);
    load_tile(1, 1);

    float acc[2][8][4];
    #pragma unroll
    for (int mt = 0; mt < 2; ++mt)
        #pragma unroll
        for (int nt = 0; nt < 8; ++nt)
            #pragma unroll
            for (int r = 0; r < 4; ++r) acc[mt][nt][r] = 0.0f;

    int nT = K2 >> 5;
    int buf = 0;
    for (int t = 0; t < nT; ++t) {
        if (t + 1 < nT) CPWAIT(1); else CPWAIT(0);
        __syncthreads();
        if (t + 2 < nT) load_tile(t + 2, (buf + 2) % 3);

        uint32_t ab = s0 + buf * STGB;
        uint32_t bb = ab + ABUF;
        #pragma unroll
        for (int ks = 0; ks < 2; ++ks) {
            uint32_t af[2][4];
            #pragma unroll
            for (int mt = 0; mt < 2; ++mt)
                LDSM4(af[mt][0], af[mt][1], af[mt][2], af[mt][3],
                      ab + a_off + (warpm * 32 + mt * 16) * ARB + ks * 32);
            #pragma unroll
            for (int ntp = 0; ntp < 4; ++ntp) {
                uint32_t b0, b1, b2, b3;
                LDSM4T(b0, b1, b2, b3,
                       bb + b_off + (ks * 16) * BRB + warpn * 128 + ntp * 32);
                #pragma unroll
                for (int mt = 0; mt < 2; ++mt) {
                    mma16h(acc[mt][2 * ntp], af[mt], b0, b1);
                    mma16h(acc[mt][2 * ntp + 1], af[mt], b2, b3);
                }
            }
        }
        buf = (buf + 1) % 3;
    }

    #pragma unroll
    for (int mt = 0; mt < 2; ++mt) {
        int r0 = rowBase + warpm * 32 + mt * 16 + gid;
        #pragma unroll
        for (int nt = 0; nt < 8; ++nt) {
            int col = colBase + warpn * 64 + nt * 8 + tig * 2;
            float2 bb2 = *(const float2*)(bias + col);
            float2 v0, v1;
            v0.x = acc[mt][nt][0] + bb2.x; v0.y = acc[mt][nt][1] + bb2.y;
            v1.x = acc[mt][nt][2] + bb2.x; v1.y = acc[mt][nt][3] + bb2.y;
            if (MODE == 0) {
                uint32_t w0 = packh2(v0.x * SCALE_F, v0.y * SCALE_F);
                uint32_t w1 = packh2(v1.x * SCALE_F, v1.y * SCALE_F);
                ((uint32_t*)hC)[((size_t)r0 * N2 + col) >> 1] = w0;
                ((uint32_t*)hC)[((size_t)(r0 + 8) * N2 + col) >> 1] = w1;
            } else if (MODE == 2) {
                *(float2*)(&C[(size_t)r0 * N2 + col]) = v0;
                *(float2*)(&C[(size_t)(r0 + 8) * N2 + col]) = v1;
            } else {
                uint32_t w0 = packh2(v0.x, v0.y);
                uint32_t w1 = packh2(v1.x, v1.y);
                if (col < DD) {
                    ((uint32_t*)hK)[((size_t)r0 * DD + col) >> 1] = w0;
                    ((uint32_t*)hK)[((size_t)(r0 + 8) * DD + col) >> 1] = w1;
                } else {
                    ((uint32_t*)hV)[((size_t)r0 * DD + col - DD) >> 1] = w0;
                    ((uint32_t*)hV)[((size_t)(r0 + 8) * DD + col - DD) >> 1] = w1;
                }
            }
        }
    }
}

// ---------------- fused attention (R14/R15, passing) ----------------------
#define ROWB   144
#define BUFB   (128 * ROWB)
#define ATTN_SMEM (5 * BUFB)

__global__ void __launch_bounds__(256, 2)
attn_k(const __half* __restrict__ qh, const __half* __restrict__ kh,
       const __half* __restrict__ vh, __half* __restrict__ oh) {
    extern __shared__ __align__(16) unsigned char smraw[];
    uint32_t s_q = smem_u32(smraw);
    uint32_t s_k = s_q + BUFB;
    uint32_t s_v = s_q + 3 * BUFB;

    int tid = threadIdx.x;
    int lane = tid & 31;
    int wid = tid >> 5;
    int gid = lane >> 2, tig = lane & 3;

    int bh = blockIdx.y;
    int b = bh >> 4;
    int h = bh & 15;
    int n0blk = blockIdx.x * 128;

    const __half* qbase = qh + ((size_t)(b * NN + n0blk)) * DD + h * HD;
    const __half* kbase = kh + (size_t)b * KCC * DD + h * HD;
    const __half* vbase = vh + (size_t)b * KCC * DD + h * HD;

    #pragma unroll
    for (int i = 0; i < 4; ++i) {
        int idx = tid + 256 * i;
        int row = idx >> 3;
        int c = idx & 7;
        uint4 t = *(const uint4*)(qbase + (size_t)row * DD + c * 8);
        *(uint4*)(smraw + row * ROWB + c * 16) = t;
    }
    #pragma unroll
    for (int i = 0; i < 4; ++i) {
        int idx = tid + 256 * i;
        int br = idx >> 2;
        int w  = idx & 3;
        *(uint32_t*)(smraw + 3 * BUFB + br * ROWB + 128 + w * 4) =
            (w == 0) ? 0x00003C00u : 0u;
    }

    int m0 = wid * 16;
    uint32_t qa = s_q + (uint32_t)((m0 + ((lane >> 3) & 1) * 8 + (lane & 7)) * ROWB
                                   + (lane >> 4) * 16);
    uint32_t ka_off = (uint32_t)(((lane & 7) + (lane >> 4) * 8) * ROWB
                                 + ((lane >> 3) & 1) * 16);
    uint32_t va_off = (uint32_t)((((lane >> 3) & 1) * 8 + (lane & 7)) * ROWB
                                 + (lane >> 4) * 16);
    uint32_t vs_off = (uint32_t)((lane & 15) * ROWB + 128);

    int crow = tid >> 1;
    int cg   = tid & 1;
    const __half* ksrc0 = kbase + (size_t)crow * DD + cg * 32;
    const __half* vsrc0 = vbase + (size_t)crow * DD + cg * 32;
    uint32_t kdst0 = s_k + crow * ROWB + cg * 64;
    uint32_t vdst0 = s_v + crow * ROWB + cg * 64;

    {
        #pragma unroll
        for (int j = 0; j < 4; ++j) {
            CPA16(kdst0 + j * 16, ksrc0 + j * 8);
            CPA16(vdst0 + j * 16, vsrc0 + j * 8);
        }
        CPCOMMIT();
    }

    float oAcc[8][4];
    #pragma unroll
    for (int nt = 0; nt < 8; ++nt)
        #pragma unroll
        for (int r = 0; r < 4; ++r) oAcc[nt][r] = 0.0f;
    float oSum[4] = {0.0f, 0.0f, 0.0f, 0.0f};

    const uint32_t NEG10 = 0xC900C900u, POS10 = 0x49004900u;
    const uint32_t L2E2 = packh2(1.4426950f, 1.4426950f);
    const uint32_t OFF2 = packh2(0.5730496f, 0.5730496f);

    for (int c = 0; c < KCC / 128; ++c) {
        if (c + 1 < KCC / 128) {
            int nb = (c + 1) & 1;
            const __half* ks = ksrc0 + (size_t)(c + 1) * 128 * DD;
            const __half* vs = vsrc0 + (size_t)(c + 1) * 128 * DD;
            #pragma unroll
            for (int j = 0; j < 4; ++j) {
                CPA16(kdst0 + nb * BUFB + j * 16, ks + j * 8);
                CPA16(vdst0 + nb * BUFB + j * 16, vs + j * 8);
            }
            CPCOMMIT();
            CPWAIT(1);
        } else {
            CPWAIT(0);
        }
        __syncthreads();

        uint32_t bo = (c & 1) * BUFB;

        float sAcc[8][4];
        #pragma unroll
        for (int nt = 0; nt < 8; ++nt)
            #pragma unroll
            for (int r = 0; r < 4; ++r) sAcc[nt][r] = 0.0f;

        #pragma unroll
        for (int ks = 0; ks < 4; ++ks) {
            uint32_t a0, a1, a2, a3;
            LDSM4(a0, a1, a2, a3, qa + ks * 32);
            uint32_t af[4] = {a0, a1, a2, a3};
            #pragma unroll
            for (int ntp = 0; ntp < 4; ++ntp) {
                uint32_t b0, b1, b2, b3;
                LDSM4(b0, b1, b2, b3,
                      s_k + bo + ka_off + (ntp * 16) * ROWB + ks * 32);
                mma16h(sAcc[2 * ntp], af, b0, b1);
                mma16h(sAcc[2 * ntp + 1], af, b2, b3);
            }
        }

        uint32_t pa[4][4];
        #pragma unroll
        for (int nt = 0; nt < 8; ++nt) {
            uint32_t lo = packh2(sAcc[nt][0], sAcc[nt][1]);
            uint32_t hi = packh2(sAcc[nt][2], sAcc[nt][3]);
            lo = h2ex2(h2fma(h2min(h2max(lo, NEG10), POS10), L2E2, OFF2));
            hi = h2ex2(h2fma(h2min(h2max(hi, NEG10), POS10), L2E2, OFF2));
            int kp = nt >> 1, s = (nt & 1) << 1;
            pa[kp][s + 0] = lo;
            pa[kp][s + 1] = hi;
        }

        float sAcc2[8][4];
        #pragma unroll
        for (int nt = 0; nt < 8; ++nt)
            #pragma unroll
            for (int r = 0; r < 4; ++r) sAcc2[nt][r] = 0.0f;

        #pragma unroll
        for (int kp = 0; kp < 4; ++kp) {
            uint32_t vrow = s_v + bo + (kp * 16) * ROWB;
            #pragma unroll
            for (int ntp = 0; ntp < 4; ++ntp) {
                uint32_t b0, b1, b2, b3;
                LDSM4T(b0, b1, b2, b3, vrow + va_off + ntp * 32);
                mma16h(oAcc[2 * ntp], pa[kp], b0, b1);
                mma16h(oAcc[2 * ntp + 1], pa[kp], b2, b3);
            }
            uint32_t c0, c1;
            LDSM2T(c0, c1, vrow + vs_off);
            mma16h(oSum, pa[kp], c0, c1);

            uint32_t a0, a1, a2, a3;
            LDSM4(a0, a1, a2, a3, qa + kp * 32);
            uint32_t af[4] = {a0, a1, a2, a3};
            #pragma unroll
            for (int ntp = 0; ntp < 4; ++ntp) {
                uint32_t b0, b1, b2, b3;
                LDSM4(b0, b1, b2, b3,
                      s_k + bo + ka_off + ((64 + ntp * 16)) * ROWB + kp * 32);
                mma16h(sAcc2[2 * ntp], af, b0, b1);
                mma16h(sAcc2[2 * ntp + 1], af, b2, b3);
            }
        }

        #pragma unroll
        for (int nt = 0; nt < 8; ++nt) {
            uint32_t lo = packh2(sAcc2[nt][0], sAcc2[nt][1]);
            uint32_t hi = packh2(sAcc2[nt][2], sAcc2[nt][3]);
            lo = h2ex2(h2fma(h2min(h2max(lo, NEG10), POS10), L2E2, OFF2));
            hi = h2ex2(h2fma(h2min(h2max(hi, NEG10), POS10), L2E2, OFF2));
            int kp = nt >> 1, s = (nt & 1) << 1;
            pa[kp][s + 0] = lo;
            pa[kp][s + 1] = hi;
        }

        #pragma unroll
        for (int kp = 0; kp < 4; ++kp) {
            uint32_t vrow = s_v + bo + ((64 + kp * 16)) * ROWB;
            #pragma unroll
            for (int ntp = 0; ntp < 4; ++ntp) {
                uint32_t b0, b1, b2, b3;
                LDSM4T(b0, b1, b2, b3, vrow + va_off + ntp * 32);
                mma16h(oAcc[2 * ntp], pa[kp], b0, b1);
                mma16h(oAcc[2 * ntp + 1], pa[kp], b2, b3);
            }
            uint32_t c0, c1;
            LDSM2T(c0, c1, vrow + vs_off);
            mma16h(oSum, pa[kp], c0, c1);
        }

        __syncthreads();
    }

    float rs0 = __shfl_sync(0xffffffffu, oSum[0], lane & ~3);
    float rs1 = __shfl_sync(0xffffffffu, oSum[2], lane & ~3);
    float inv0 = 1.0f / rs0;
    float inv1 = 1.0f / rs1;

    int row0 = n0blk + m0 + gid;
    #pragma unroll
    for (int nt = 0; nt < 8; ++nt) {
        int dv = nt * 8 + 2 * tig;
        uint32_t w0 = packh2(oAcc[nt][0] * inv0, oAcc[nt][1] * inv0);
        uint32_t w1 = packh2(oAcc[nt][2] * inv1, oAcc[nt][3] * inv1);
        *(uint32_t*)(&oh[((size_t)(b * NN + row0)) * DD + h * HD + dv]) = w0;
        *(uint32_t*)(&oh[((size_t)(b * NN + row0 + 8)) * DD + h * HD + dv]) = w1;
    }
}

// ---------------- tail ----------------
__global__ void tail_k(float* __restrict__ dst) {
    dst[0] = 1.0f / (float)KCC;
}

// ---------------- launch ----------------
extern "C" void kernel_launch(void* const* d_in, const int* in_sizes, int n_in,
                              void* d_out, int out_size) {
    const float* x      = (const float*)d_in[0];
    const float* ctx    = (const float*)d_in[1];
    const float* q_w    = (const float*)d_in[2];
    const float* q_b    = (const float*)d_in[3];
    const float* kv_w   = (const float*)d_in[4];
    const float* kv_b   = (const float*)d_in[5];
    const float* proj_w = (const float*)d_in[6];
    const float* proj_b = (const float*)d_in[7];
    float* out = (float*)d_out;

    __half *xh, *ctxnh, *qwh, *kvwh, *pwh, *qhp, *khp, *vhp, *aoh;
    cudaGetSymbolAddress((void**)&xh,    g_xh);
    cudaGetSymbolAddress((void**)&ctxnh, g_ctxnh);
    cudaGetSymbolAddress((void**)&qwh,   g_qwh);
    cudaGetSymbolAddress((void**)&kvwh,  g_kvwh);
    cudaGetSymbolAddress((void**)&pwh,   g_pwh);
    cudaGetSymbolAddress((void**)&qhp,   g_qh);
    cudaGetSymbolAddress((void**)&khp,   g_kh);
    cudaGetSymbolAddress((void**)&vhp,   g_vh);
    cudaGetSymbolAddress((void**)&aoh,   g_aoh);

    cudaFuncSetAttribute(gemm_h<0>, cudaFuncAttributeMaxDynamicSharedMemorySize, GEMM_SMEM);
    cudaFuncSetAttribute(gemm_h<1>, cudaFuncAttributeMaxDynamicSharedMemorySize, GEMM_SMEM);
    cudaFuncSetAttribute(gemm_h<2>, cudaFuncAttributeMaxDynamicSharedMemorySize, GEMM_SMEM);
    cudaFuncSetAttribute(attn_k,    cudaFuncAttributeMaxDynamicSharedMemorySize, ATTN_SMEM);

    f2h_k<<<(BB * NN * DD / 8 + 255) / 256, 256>>>(x, xh, BB * NN * DD);
    f2h_k<<<(DD * DD / 8 + 255) / 256, 256>>>(q_w, qwh, DD * DD);
    f2h_k<<<(DD * 2 * DD / 8 + 255) / 256, 256>>>(kv_w, kvwh, DD * 2 * DD);
    f2h_k<<<(DD * DD / 8 + 255) / 256, 256>>>(proj_w, pwh, DD * DD);

    rmsnorm_k<<<BB * KCC, 256>>>(ctx, ctxnh);

    dim3 gq(DD / 128, (BB * NN) / 128);
    gemm_h<0><<<gq, 256, GEMM_SMEM>>>(xh, qwh, q_b, nullptr, BB * NN, DD, DD, qhp, nullptr, nullptr);

    dim3 gkv((2 * DD) / 128, (BB * KCC) / 128);
    gemm_h<1><<<gkv, 256, GEMM_SMEM>>>(ctxnh, kvwh, kv_b, nullptr, BB * KCC, 2 * DD, DD, nullptr, khp, vhp);

    dim3 ga(NN / 128, BB * HH);
    attn_k<<<ga, 256, ATTN_SMEM>>>(qhp, khp, vhp, aoh);

    dim3 gp(DD / 128, (BB * NN) / 128);
    gemm_h<2><<<gp, 256, GEMM_SMEM>>>(aoh, pwh, proj_b, out, BB * NN, DD, DD, nullptr, nullptr, nullptr);

    if (out_size > BB * NN * DD) {
        tail_k<<<1, 1>>>(out + (size_t)BB * NN * DD);
    }
}

// round 17
// speedup vs baseline: 2.6835x; 1.0243x over previous
#include <cuda_runtime.h>
#include <cuda_fp16.h>
#include <math.h>
#include <stdint.h>

#define BB   4
#define NN   2048
#define KCC  2048
#define DD   1024
#define HH   16
#define HD   64
#define SCALE_F 0.125f
#define EPS_F   1e-6f

// ---------------- scratch ----------------
__device__ __half g_xh  [BB * NN  * DD];
__device__ __half g_ctxnh[BB * KCC * DD];
__device__ __half g_qwh [DD * DD];
__device__ __half g_kvwh[DD * 2 * DD];
__device__ __half g_pwh [DD * DD];
__device__ __half g_qh  [BB * NN  * DD];
__device__ __half g_kh  [BB * KCC * DD];
__device__ __half g_vh  [BB * KCC * DD];
__device__ __half g_aoh [BB * NN  * DD];

// ---------------- helpers ----------------
__device__ __forceinline__ uint32_t packh2(float a, float b) {
    uint32_t r;
    asm("cvt.rn.f16x2.f32 %0, %2, %1;" : "=r"(r) : "f"(a), "f"(b));
    return r;
}
__device__ __forceinline__ void mma16h(float* c, const uint32_t* a, uint32_t b0, uint32_t b1) {
    asm volatile(
        "mma.sync.aligned.m16n8k16.row.col.f32.f16.f16.f32 "
        "{%0,%1,%2,%3}, {%4,%5,%6,%7}, {%8,%9}, {%0,%1,%2,%3};"
        : "+f"(c[0]), "+f"(c[1]), "+f"(c[2]), "+f"(c[3])
        : "r"(a[0]), "r"(a[1]), "r"(a[2]), "r"(a[3]), "r"(b0), "r"(b1));
}
__device__ __forceinline__ uint32_t smem_u32(const void* p) {
    return (uint32_t)__cvta_generic_to_shared(p);
}
#define LDSM4(r0,r1,r2,r3,addr) \
    asm volatile("ldmatrix.sync.aligned.m8n8.x4.shared.b16 {%0,%1,%2,%3},[%4];" \
        : "=r"(r0),"=r"(r1),"=r"(r2),"=r"(r3) : "r"(addr))
#define LDSM4T(r0,r1,r2,r3,addr) \
    asm volatile("ldmatrix.sync.aligned.m8n8.x4.trans.shared.b16 {%0,%1,%2,%3},[%4];" \
        : "=r"(r0),"=r"(r1),"=r"(r2),"=r"(r3) : "r"(addr))
#define LDSM2T(r0,r1,addr) \
    asm volatile("ldmatrix.sync.aligned.m8n8.x2.trans.shared.b16 {%0,%1},[%2];" \
        : "=r"(r0),"=r"(r1) : "r"(addr))
#define CPA16(dst,src) \
    asm volatile("cp.async.cg.shared.global [%0],[%1],16;" :: "r"(dst),"l"(src))
#define CPCOMMIT() asm volatile("cp.async.commit_group;")
#define CPWAIT(n)  asm volatile("cp.async.wait_group %0;" :: "n"(n))

__device__ __forceinline__ uint32_t h2max(uint32_t a, uint32_t b) {
    uint32_t r; asm("max.f16x2 %0,%1,%2;" : "=r"(r) : "r"(a), "r"(b)); return r;
}
__device__ __forceinline__ uint32_t h2min(uint32_t a, uint32_t b) {
    uint32_t r; asm("min.f16x2 %0,%1,%2;" : "=r"(r) : "r"(a), "r"(b)); return r;
}
__device__ __forceinline__ uint32_t h2fma(uint32_t a, uint32_t b, uint32_t c) {
    uint32_t r; asm("fma.rn.f16x2 %0,%1,%2,%3;" : "=r"(r) : "r"(a), "r"(b), "r"(c)); return r;
}
__device__ __forceinline__ uint32_t h2ex2(uint32_t a) {
    uint32_t r; asm("ex2.approx.f16x2 %0,%1;" : "=r"(r) : "r"(a)); return r;
}

// ---------------- fused fp32 -> fp16 convert (all 4 tensors, 1 launch) ----
#define N_X  (BB * NN * DD)
#define N_QW (DD * DD)
#define N_KVW (DD * 2 * DD)
#define N_PW (DD * DD)
__global__ void f2h_all(const float* __restrict__ x, const float* __restrict__ qw,
                        const float* __restrict__ kvw, const float* __restrict__ pw,
                        __half* __restrict__ xh, __half* __restrict__ qwh,
                        __half* __restrict__ kvwh, __half* __restrict__ pwh) {
    int i = (blockIdx.x * blockDim.x + threadIdx.x) * 8;
    const float* s;
    __half* d;
    int off;
    if (i < N_X) { s = x; d = xh; off = i; }
    else if (i < N_X + N_QW) { s = qw; d = qwh; off = i - N_X; }
    else if (i < N_X + N_QW + N_KVW) { s = kvw; d = kvwh; off = i - N_X - N_QW; }
    else { s = pw; d = pwh; off = i - N_X - N_QW - N_KVW; }
    float4 a = *(const float4*)(s + off);
    float4 b = *(const float4*)(s + off + 4);
    uint4 w;
    w.x = packh2(a.x, a.y); w.y = packh2(a.z, a.w);
    w.z = packh2(b.x, b.y); w.w = packh2(b.z, b.w);
    *(uint4*)(d + off) = w;
}

// ---------------- rms norm (fp16 out) ----------------
__global__ void rmsnorm_k(const float* __restrict__ ctx, __half* __restrict__ o) {
    int row = blockIdx.x;
    const float4* p = reinterpret_cast<const float4*>(ctx + (size_t)row * DD);
    float4 v = p[threadIdx.x];
    float ss = v.x * v.x + v.y * v.y + v.z * v.z + v.w * v.w;
    __shared__ float red[8];
    #pragma unroll
    for (int off = 16; off; off >>= 1) ss += __shfl_xor_sync(0xffffffffu, ss, off);
    if ((threadIdx.x & 31) == 0) red[threadIdx.x >> 5] = ss;
    __syncthreads();
    if (threadIdx.x < 32) {
        float t = (threadIdx.x < 8) ? red[threadIdx.x] : 0.0f;
        #pragma unroll
        for (int off = 4; off; off >>= 1) t += __shfl_xor_sync(0xffffffffu, t, off);
        if (threadIdx.x == 0) red[0] = t;
    }
    __syncthreads();
    float r = 1.0f / sqrtf(red[0] * (1.0f / DD) + EPS_F);
    uint2 w;
    w.x = packh2(v.x * r, v.y * r);
    w.y = packh2(v.z * r, v.w * r);
    *(uint2*)(o + (size_t)row * DD + threadIdx.x * 4) = w;
}

// ---------------- fp16 GEMM: 128x128 tile, BK=64, 3-stage, 1 barrier ------
#define ARB 144
#define BRB 272
#define ABUF (128 * ARB)
#define BBUF (64 * BRB)
#define STGB (ABUF + BBUF)
#define GEMM_SMEM (3 * STGB)

template <int MODE>
__global__ void __launch_bounds__(256, 2)
gemm_h(const __half* __restrict__ A, const __half* __restrict__ W,
       const float* __restrict__ bias, float* __restrict__ C,
       int M2, int N2, int K2,
       __half* __restrict__ hC, __half* __restrict__ hK, __half* __restrict__ hV) {
    extern __shared__ __align__(16) unsigned char sm[];
    uint32_t s0 = smem_u32(sm);

    int tid = threadIdx.x;
    int lane = tid & 31;
    int wid = tid >> 5;
    int gid = lane >> 2, tig = lane & 3;
    int warpm = wid & 3, warpn = wid >> 2;     // 4 x 2 warps, 32 x 64 tiles
    int rowBase = blockIdx.y * 128, colBase = blockIdx.x * 128;

    const __half* Abase = A + (size_t)rowBase * K2;
    const __half* Wbase = W + colBase;

    uint32_t a_off = (uint32_t)((((lane >> 3) & 1) * 8 + (lane & 7)) * ARB + (lane >> 4) * 16);
    uint32_t b_off = (uint32_t)((((lane >> 3) & 1) * 8 + (lane & 7)) * BRB + (lane >> 4) * 16);

    // A: 128 rows x 8 16B-chunks; B: 64 rows x 16 16B-chunks  (1024 each)
    auto load_tile = [&](int t, int buf) {
        uint32_t s_a = s0 + buf * STGB;
        uint32_t s_b = s_a + ABUF;
        const __half* As2 = Abase + t * 64;
        const __half* Ws2 = Wbase + (size_t)t * 64 * N2;
        #pragma unroll
        for (int j = 0; j < 4; ++j) {
            int ca = tid + 256 * j;
            int ar = ca >> 3, ac = ca & 7;
            CPA16(s_a + ar * ARB + ac * 16, As2 + (size_t)ar * K2 + ac * 8);
            int cb = tid + 256 * j;
            int br = cb >> 4, bc = cb & 15;
            CPA16(s_b + br * BRB + bc * 16, Ws2 + (size_t)br * N2 + bc * 8);
        }
        CPCOMMIT();
    };

    load_tile(0, 0);
    load_tile(1, 1);

    float acc[2][8][4];
    #pragma unroll
    for (int mt = 0; mt < 2; ++mt)
        #pragma unroll
        for (int nt = 0; nt < 8; ++nt)
            #pragma unroll
            for (int r = 0; r < 4; ++r) acc[mt][nt][r] = 0.0f;

    int nT = K2 >> 6;
    int buf = 0;
    for (int t = 0; t < nT; ++t) {
        if (t + 1 < nT) CPWAIT(1); else CPWAIT(0);
        __syncthreads();
        if (t + 2 < nT) load_tile(t + 2, (buf + 2) % 3);

        uint32_t ab = s0 + buf * STGB;
        uint32_t bb = ab + ABUF;
        #pragma unroll
        for (int ks = 0; ks < 4; ++ks) {
            uint32_t af[2][4];
            #pragma unroll
            for (int mt = 0; mt < 2; ++mt)
                LDSM4(af[mt][0], af[mt][1], af[mt][2], af[mt][3],
                      ab + a_off + (warpm * 32 + mt * 16) * ARB + ks * 32);
            #pragma unroll
            for (int ntp = 0; ntp < 4; ++ntp) {
                uint32_t b0, b1, b2, b3;
                LDSM4T(b0, b1, b2, b3,
                       bb + b_off + (ks * 16) * BRB + warpn * 128 + ntp * 32);
                #pragma unroll
                for (int mt = 0; mt < 2; ++mt) {
                    mma16h(acc[mt][2 * ntp], af[mt], b0, b1);
                    mma16h(acc[mt][2 * ntp + 1], af[mt], b2, b3);
                }
            }
        }
        buf = (buf + 1) % 3;
    }

    #pragma unroll
    for (int mt = 0; mt < 2; ++mt) {
        int r0 = rowBase + warpm * 32 + mt * 16 + gid;
        #pragma unroll
        for (int nt = 0; nt < 8; ++nt) {
            int col = colBase + warpn * 64 + nt * 8 + tig * 2;
            float2 bb2 = *(const float2*)(bias + col);
            float2 v0, v1;
            v0.x = acc[mt][nt][0] + bb2.x; v0.y = acc[mt][nt][1] + bb2.y;
            v1.x = acc[mt][nt][2] + bb2.x; v1.y = acc[mt][nt][3] + bb2.y;
            if (MODE == 0) {
                uint32_t w0 = packh2(v0.x * SCALE_F, v0.y * SCALE_F);
                uint32_t w1 = packh2(v1.x * SCALE_F, v1.y * SCALE_F);
                ((uint32_t*)hC)[((size_t)r0 * N2 + col) >> 1] = w0;
                ((uint32_t*)hC)[((size_t)(r0 + 8) * N2 + col) >> 1] = w1;
            } else if (MODE == 2) {
                *(float2*)(&C[(size_t)r0 * N2 + col]) = v0;
                *(float2*)(&C[(size_t)(r0 + 8) * N2 + col]) = v1;
            } else {
                uint32_t w0 = packh2(v0.x, v0.y);
                uint32_t w1 = packh2(v1.x, v1.y);
                if (col < DD) {
                    ((uint32_t*)hK)[((size_t)r0 * DD + col) >> 1] = w0;
                    ((uint32_t*)hK)[((size_t)(r0 + 8) * DD + col) >> 1] = w1;
                } else {
                    ((uint32_t*)hV)[((size_t)r0 * DD + col - DD) >> 1] = w0;
                    ((uint32_t*)hV)[((size_t)(r0 + 8) * DD + col - DD) >> 1] = w1;
                }
            }
        }
    }
}

// ---------------- fused attention: Q fragments hoisted to registers -------
#define ROWB   144
#define BUFB   (128 * ROWB)
#define ATTN_SMEM (5 * BUFB)

__global__ void __launch_bounds__(256, 2)
attn_k(const __half* __restrict__ qh, const __half* __restrict__ kh,
       const __half* __restrict__ vh, __half* __restrict__ oh) {
    extern __shared__ __align__(16) unsigned char smraw[];
    uint32_t s_q = smem_u32(smraw);
    uint32_t s_k = s_q + BUFB;
    uint32_t s_v = s_q + 3 * BUFB;

    int tid = threadIdx.x;
    int lane = tid & 31;
    int wid = tid >> 5;
    int gid = lane >> 2, tig = lane & 3;

    int bh = blockIdx.y;
    int b = bh >> 4;
    int h = bh & 15;
    int n0blk = blockIdx.x * 128;

    const __half* qbase = qh + ((size_t)(b * NN + n0blk)) * DD + h * HD;
    const __half* kbase = kh + (size_t)b * KCC * DD + h * HD;
    const __half* vbase = vh + (size_t)b * KCC * DD + h * HD;

    // ---- Q -> smem, V-pad ones column ----
    #pragma unroll
    for (int i = 0; i < 4; ++i) {
        int idx = tid + 256 * i;
        int row = idx >> 3;
        int c = idx & 7;
        uint4 t = *(const uint4*)(qbase + (size_t)row * DD + c * 8);
        *(uint4*)(smraw + row * ROWB + c * 16) = t;
    }
    #pragma unroll
    for (int i = 0; i < 4; ++i) {
        int idx = tid + 256 * i;
        int br = idx >> 2;
        int w  = idx & 3;
        *(uint32_t*)(smraw + 3 * BUFB + br * ROWB + 128 + w * 4) =
            (w == 0) ? 0x00003C00u : 0u;
    }

    int m0 = wid * 16;
    uint32_t qa = s_q + (uint32_t)((m0 + ((lane >> 3) & 1) * 8 + (lane & 7)) * ROWB
                                   + (lane >> 4) * 16);
    uint32_t ka_off = (uint32_t)(((lane & 7) + (lane >> 4) * 8) * ROWB
                                 + ((lane >> 3) & 1) * 16);
    uint32_t va_off = (uint32_t)((((lane >> 3) & 1) * 8 + (lane & 7)) * ROWB
                                 + (lane >> 4) * 16);
    uint32_t vs_off = (uint32_t)((lane & 15) * ROWB + 128);

    int crow = tid >> 1;
    int cg   = tid & 1;
    const __half* ksrc0 = kbase + (size_t)crow * DD + cg * 32;
    const __half* vsrc0 = vbase + (size_t)crow * DD + cg * 32;
    uint32_t kdst0 = s_k + crow * ROWB + cg * 64;
    uint32_t vdst0 = s_v + crow * ROWB + cg * 64;

    // prologue K/V chunk 0
    {
        #pragma unroll
        for (int j = 0; j < 4; ++j) {
            CPA16(kdst0 + j * 16, ksrc0 + j * 8);
            CPA16(vdst0 + j * 16, vsrc0 + j * 8);
        }
        CPCOMMIT();
    }

    // ---- hoist Q A-fragments to registers (loop-invariant) ----
    __syncthreads();
    uint32_t qf[4][4];
    #pragma unroll
    for (int ks = 0; ks < 4; ++ks)
        LDSM4(qf[ks][0], qf[ks][1], qf[ks][2], qf[ks][3], qa + ks * 32);

    float oAcc[8][4];
    #pragma unroll
    for (int nt = 0; nt < 8; ++nt)
        #pragma unroll
        for (int r = 0; r < 4; ++r) oAcc[nt][r] = 0.0f;
    float oSum[4] = {0.0f, 0.0f, 0.0f, 0.0f};

    const uint32_t NEG10 = 0xC900C900u, POS10 = 0x49004900u;
    const uint32_t L2E2 = packh2(1.4426950f, 1.4426950f);
    const uint32_t OFF2 = packh2(0.5730496f, 0.5730496f);

    for (int c = 0; c < KCC / 128; ++c) {
        if (c + 1 < KCC / 128) {
            int nb = (c + 1) & 1;
            const __half* ks = ksrc0 + (size_t)(c + 1) * 128 * DD;
            const __half* vs = vsrc0 + (size_t)(c + 1) * 128 * DD;
            #pragma unroll
            for (int j = 0; j < 4; ++j) {
                CPA16(kdst0 + nb * BUFB + j * 16, ks + j * 8);
                CPA16(vdst0 + nb * BUFB + j * 16, vs + j * 8);
            }
            CPCOMMIT();
            CPWAIT(1);
        } else {
            CPWAIT(0);
        }
        __syncthreads();

        uint32_t bo = (c & 1) * BUFB;

        #pragma unroll
        for (int half = 0; half < 2; ++half) {
            float sAcc[8][4];
            #pragma unroll
            for (int nt = 0; nt < 8; ++nt)
                #pragma unroll
                for (int r = 0; r < 4; ++r) sAcc[nt][r] = 0.0f;

            #pragma unroll
            for (int ks = 0; ks < 4; ++ks) {
                #pragma unroll
                for (int ntp = 0; ntp < 4; ++ntp) {
                    uint32_t b0, b1, b2, b3;
                    LDSM4(b0, b1, b2, b3,
                          s_k + bo + ka_off + (half * 64 + ntp * 16) * ROWB + ks * 32);
                    mma16h(sAcc[2 * ntp], qf[ks], b0, b1);
                    mma16h(sAcc[2 * ntp + 1], qf[ks], b2, b3);
                }
            }

            uint32_t pa[4][4];
            #pragma unroll
            for (int nt = 0; nt < 8; ++nt) {
                uint32_t lo = packh2(sAcc[nt][0], sAcc[nt][1]);
                uint32_t hi = packh2(sAcc[nt][2], sAcc[nt][3]);
                lo = h2ex2(h2fma(h2min(h2max(lo, NEG10), POS10), L2E2, OFF2));
                hi = h2ex2(h2fma(h2min(h2max(hi, NEG10), POS10), L2E2, OFF2));
                int kp = nt >> 1, s = (nt & 1) << 1;
                pa[kp][s + 0] = lo;
                pa[kp][s + 1] = hi;
            }

            #pragma unroll
            for (int kp = 0; kp < 4; ++kp) {
                uint32_t vrow = s_v + bo + (half * 64 + kp * 16) * ROWB;
                #pragma unroll
                for (int ntp = 0; ntp < 4; ++ntp) {
                    uint32_t b0, b1, b2, b3;
                    LDSM4T(b0, b1, b2, b3, vrow + va_off + ntp * 32);
                    mma16h(oAcc[2 * ntp], pa[kp], b0, b1);
                    mma16h(oAcc[2 * ntp + 1], pa[kp], b2, b3);
                }
                uint32_t c0, c1;
                LDSM2T(c0, c1, vrow + vs_off);
                mma16h(oSum, pa[kp], c0, c1);
            }
        }
        __syncthreads();
    }

    float rs0 = __shfl_sync(0xffffffffu, oSum[0], lane & ~3);
    float rs1 = __shfl_sync(0xffffffffu, oSum[2], lane & ~3);
    float inv0 = 1.0f / rs0;
    float inv1 = 1.0f / rs1;

    int row0 = n0blk + m0 + gid;
    #pragma unroll
    for (int nt = 0; nt < 8; ++nt) {
        int dv = nt * 8 + 2 * tig;
        uint32_t w0 = packh2(oAcc[nt][0] * inv0, oAcc[nt][1] * inv0);
        uint32_t w1 = packh2(oAcc[nt][2] * inv1, oAcc[nt][3] * inv1);
        *(uint32_t*)(&oh[((size_t)(b * NN + row0)) * DD + h * HD + dv]) = w0;
        *(uint32_t*)(&oh[((size_t)(b * NN + row0 + 8)) * DD + h * HD + dv]) = w1;
    }
}

// ---------------- tail ----------------
__global__ void tail_k(float* __restrict__ dst) {
    dst[0] = 1.0f / (float)KCC;
}

// ---------------- launch ----------------
extern "C" void kernel_launch(void* const* d_in, const int* in_sizes, int n_in,
                              void* d_out, int out_size) {
    const float* x      = (const float*)d_in[0];
    const float* ctx    = (const float*)d_in[1];
    const float* q_w    = (const float*)d_in[2];
    const float* q_b    = (const float*)d_in[3];
    const float* kv_w   = (const float*)d_in[4];
    const float* kv_b   = (const float*)d_in[5];
    const float* proj_w = (const float*)d_in[6];
    const float* proj_b = (const float*)d_in[7];
    float* out = (float*)d_out;

    __half *xh, *ctxnh, *qwh, *kvwh, *pwh, *qhp, *khp, *vhp, *aoh;
    cudaGetSymbolAddress((void**)&xh,    g_xh);
    cudaGetSymbolAddress((void**)&ctxnh, g_ctxnh);
    cudaGetSymbolAddress((void**)&qwh,   g_qwh);
    cudaGetSymbolAddress((void**)&kvwh,  g_kvwh);
    cudaGetSymbolAddress((void**)&pwh,   g_pwh);
    cudaGetSymbolAddress((void**)&qhp,   g_qh);
    cudaGetSymbolAddress((void**)&khp,   g_kh);
    cudaGetSymbolAddress((void**)&vhp,   g_vh);
    cudaGetSymbolAddress((void**)&aoh,   g_aoh);

    cudaFuncSetAttribute(gemm_h<0>, cudaFuncAttributeMaxDynamicSharedMemorySize, GEMM_SMEM);
    cudaFuncSetAttribute(gemm_h<1>, cudaFuncAttributeMaxDynamicSharedMemorySize, GEMM_SMEM);
    cudaFuncSetAttribute(gemm_h<2>, cudaFuncAttributeMaxDynamicSharedMemorySize, GEMM_SMEM);
    cudaFuncSetAttribute(attn_k,    cudaFuncAttributeMaxDynamicSharedMemorySize, ATTN_SMEM);

    int totalConv = N_X + N_QW + N_KVW + N_PW;
    f2h_all<<<totalConv / 8 / 256, 256>>>(x, q_w, kv_w, proj_w, xh, qwh, kvwh, pwh);

    rmsnorm_k<<<BB * KCC, 256>>>(ctx, ctxnh);

    dim3 gq(DD / 128, (BB * NN) / 128);
    gemm_h<0><<<gq, 256, GEMM_SMEM>>>(xh, qwh, q_b, nullptr, BB * NN, DD, DD, qhp, nullptr, nullptr);

    dim3 gkv((2 * DD) / 128, (BB * KCC) / 128);
    gemm_h<1><<<gkv, 256, GEMM_SMEM>>>(ctxnh, kvwh, kv_b, nullptr, BB * KCC, 2 * DD, DD, nullptr, khp, vhp);

    dim3 ga(NN / 128, BB * HH);
    attn_k<<<ga, 256, ATTN_SMEM>>>(qhp, khp, vhp, aoh);

    dim3 gp(DD / 128, (BB * NN) / 128);
    gemm_h<2><<<gp, 256, GEMM_SMEM>>>(aoh, pwh, proj_b, out, BB * NN, DD, DD, nullptr, nullptr, nullptr);

    if (out_size > BB * NN * DD) {
        tail_k<<<1, 1>>>(out + (size_t)BB * NN * DD);
    }
}